// round 8
// baseline (speedup 1.0000x reference)
#include <cuda_runtime.h>
#include <cuda_bf16.h>
#include <math.h>
#include <cstdint>

// Problem constants
#define Bq   4
#define Tq   1024
#define Dq   1024
#define Hq   16
#define DHq  64
#define Mrows (Bq*Tq)
#define OUT_ELEMS ((size_t)Mrows*Dq)

// ---------------- device scratch (no runtime allocation) -------------------
__device__ float g_k[Mrows*Dq];
__device__ float2 g_ml[Bq*Hq*Tq];

__device__ __nv_bfloat16 g_lnq_h[Mrows*Dq], g_lnq_l[Mrows*Dq];
__device__ __nv_bfloat16 g_lnk_h[Mrows*Dq], g_lnk_l[Mrows*Dq];
__device__ __nv_bfloat16 g_lnv_h[Mrows*Dq], g_lnv_l[Mrows*Dq];
__device__ __nv_bfloat16 g_rp_h [Mrows*Dq], g_rp_l [Mrows*Dq];
__device__ __nv_bfloat16 g_qs_h [Mrows*Dq], g_qs_l [Mrows*Dq];
__device__ __nv_bfloat16 g_kr_h [Mrows*Dq], g_kr_l [Mrows*Dq];
__device__ __nv_bfloat16 g_vs_h [Mrows*Dq], g_vs_l [Mrows*Dq];
__device__ __nv_bfloat16 g_ctx_h[Mrows*Dq], g_ctx_l[Mrows*Dq];
__device__ __nv_bfloat16 g_wq_h[Dq*Dq], g_wq_l[Dq*Dq];
__device__ __nv_bfloat16 g_wk_h[Dq*Dq], g_wk_l[Dq*Dq];
__device__ __nv_bfloat16 g_wv_h[Dq*Dq], g_wv_l[Dq*Dq];
__device__ __nv_bfloat16 g_wr_h[Dq*Dq], g_wr_l[Dq*Dq];
__device__ __nv_bfloat16 g_wo_h[Dq*Dq], g_wo_l[Dq*Dq];

// ------------------------- asm helpers -------------------------------------
__device__ __forceinline__ uint32_t smem_u32(const void* p) {
    uint32_t a;
    asm("{ .reg .u64 t; cvta.to.shared.u64 t, %1; cvt.u32.u64 %0, t; }"
        : "=r"(a) : "l"(p));
    return a;
}
__device__ __forceinline__ void cpa16(uint32_t s, const void* g) {
    asm volatile("cp.async.cg.shared.global [%0], [%1], 16;" :: "r"(s), "l"(g));
}
#define CPA_COMMIT() asm volatile("cp.async.commit_group;" ::: "memory")
#define CPA_WAIT(n)  asm volatile("cp.async.wait_group %0;" :: "n"(n) : "memory")

#define LDSM_X4(r0, r1, r2, r3, addr)                                        \
    asm volatile("ldmatrix.sync.aligned.m8n8.x4.shared.b16 {%0,%1,%2,%3}, [%4];" \
        : "=r"(r0), "=r"(r1), "=r"(r2), "=r"(r3) : "r"(addr))
#define LDSM_T_X4(r0, r1, r2, r3, addr)                                      \
    asm volatile("ldmatrix.sync.aligned.m8n8.x4.trans.shared.b16 {%0,%1,%2,%3}, [%4];" \
        : "=r"(r0), "=r"(r1), "=r"(r2), "=r"(r3) : "r"(addr))
#define MMA16816(c, a, b)                                                    \
    asm volatile("mma.sync.aligned.m16n8k16.row.col.f32.bf16.bf16.f32 "      \
        "{%0,%1,%2,%3}, {%4,%5,%6,%7}, {%8,%9}, {%0,%1,%2,%3};"              \
        : "+f"((c)[0]), "+f"((c)[1]), "+f"((c)[2]), "+f"((c)[3])             \
        : "r"((a)[0]), "r"((a)[1]), "r"((a)[2]), "r"((a)[3]),                \
          "r"((b)[0]), "r"((b)[1]))

__device__ __forceinline__ uint32_t bf2x(float lo, float hi) {
    uint32_t r;
    asm("cvt.rn.bf16x2.f32 %0, %1, %2;" : "=r"(r) : "f"(hi), "f"(lo));
    return r;
}

// ---------------------------------------------------------------------------
// 3x LayerNorm in one launch; outputs bf16 hi/lo split.
// ---------------------------------------------------------------------------
struct LnArgs {
    const float *x[3], *g[3], *b[3];
    __nv_bfloat16 *h[3], *l[3];
};
__global__ __launch_bounds__(256)
void ln3_split_kernel(LnArgs a)
{
    int which = blockIdx.y;
    int row = blockIdx.x;
    int tid = threadIdx.x;
    const float4* xr = reinterpret_cast<const float4*>(a.x[which] + (size_t)row * Dq);
    float4 v = xr[tid];
    float s  = v.x + v.y + v.z + v.w;
    float s2 = v.x*v.x + v.y*v.y + v.z*v.z + v.w*v.w;
    #pragma unroll
    for (int o = 16; o; o >>= 1) {
        s  += __shfl_xor_sync(0xffffffffu, s,  o);
        s2 += __shfl_xor_sync(0xffffffffu, s2, o);
    }
    __shared__ float ws[8], ws2[8], stats[2];
    int w = tid >> 5, lane = tid & 31;
    if (lane == 0) { ws[w] = s; ws2[w] = s2; }
    __syncthreads();
    if (tid == 0) {
        float ts = 0.f, ts2 = 0.f;
        #pragma unroll
        for (int i = 0; i < 8; i++) { ts += ws[i]; ts2 += ws2[i]; }
        float mu  = ts * (1.0f / Dq);
        float var = ts2 * (1.0f / Dq) - mu * mu;
        stats[0] = mu;
        stats[1] = rsqrtf(var + 1e-5f);
    }
    __syncthreads();
    float mu = stats[0], rstd = stats[1];
    float4 g4 = reinterpret_cast<const float4*>(a.g[which])[tid];
    float4 b4 = reinterpret_cast<const float4*>(a.b[which])[tid];
    float o4[4];
    o4[0] = (v.x - mu) * rstd * g4.x + b4.x;
    o4[1] = (v.y - mu) * rstd * g4.y + b4.y;
    o4[2] = (v.z - mu) * rstd * g4.z + b4.z;
    o4[3] = (v.w - mu) * rstd * g4.w + b4.w;
    __nv_bfloat16 h4[4], l4[4];
    #pragma unroll
    for (int i = 0; i < 4; i++) {
        h4[i] = __float2bfloat16_rn(o4[i]);
        l4[i] = __float2bfloat16_rn(o4[i] - __bfloat162float(h4[i]));
    }
    *(ulonglong1*)&a.h[which][(size_t)row * Dq + tid*4] = *(ulonglong1*)h4;
    *(ulonglong1*)&a.l[which][(size_t)row * Dq + tid*4] = *(ulonglong1*)l4;
}

// plain fp32 -> bf16 hi/lo split (rel_pos)
__global__ __launch_bounds__(256)
void fsplit_kernel(const float* __restrict__ x,
                   __nv_bfloat16* __restrict__ hi, __nv_bfloat16* __restrict__ lo)
{
    size_t i = ((size_t)blockIdx.x * 256 + threadIdx.x) * 4;
    float4 v = *(const float4*)&x[i];
    float o4[4] = {v.x, v.y, v.z, v.w};
    __nv_bfloat16 h4[4], l4[4];
    #pragma unroll
    for (int j = 0; j < 4; j++) {
        h4[j] = __float2bfloat16_rn(o4[j]);
        l4[j] = __float2bfloat16_rn(o4[j] - __bfloat162float(h4[j]));
    }
    *(ulonglong1*)&hi[i] = *(ulonglong1*)h4;
    *(ulonglong1*)&lo[i] = *(ulonglong1*)l4;
}

// 5 weights: W [K,N] -> WT [N,K] bf16 hi/lo split, one launch
struct WSplitArgs {
    const float* W[5];
    __nv_bfloat16 *H[5], *L[5];
};
__global__ __launch_bounds__(256)
void wsplit5_kernel(WSplitArgs a)
{
    __shared__ float t[32][33];
    const float* W = a.W[blockIdx.z];
    __nv_bfloat16* hi = a.H[blockIdx.z];
    __nv_bfloat16* lo = a.L[blockIdx.z];
    int tx = threadIdx.x & 31, ty = threadIdx.x >> 5;
    int nb = blockIdx.x * 32, kb = blockIdx.y * 32;
    #pragma unroll
    for (int i = 0; i < 32; i += 8)
        t[ty+i][tx] = W[(size_t)(kb + ty + i) * Dq + nb + tx];
    __syncthreads();
    #pragma unroll
    for (int i = 0; i < 32; i += 8) {
        float v = t[tx][ty+i];
        __nv_bfloat16 h = __float2bfloat16_rn(v);
        size_t off = (size_t)(nb + ty + i) * Dq + kb + tx;
        hi[off] = h;
        lo[off] = __float2bfloat16_rn(v - __bfloat162float(h));
    }
}

// ---------------------------------------------------------------------------
// mma.sync GEMM, 3xBF16 emulated fp32, cp.async double-buffered.
// ---------------------------------------------------------------------------
#define GROW 72
#define GT   (128*GROW)
#define TILEB (GT*2)                  // 18432 B per tile
#define GSM_BYTES (8*TILEB)           // 147456 B (2 buffers x 4 tiles)

__global__ __launch_bounds__(256, 1)
void mma_gemm_kernel(const __nv_bfloat16* __restrict__ Ah, const __nv_bfloat16* __restrict__ Al,
                     const __nv_bfloat16* __restrict__ Bh, const __nv_bfloat16* __restrict__ Bl,
                     const float* __restrict__ bias, const float* __restrict__ add,
                     float alpha, float* __restrict__ C,
                     __nv_bfloat16* __restrict__ Ch, __nv_bfloat16* __restrict__ Cl,
                     int M, int N, int K)
{
    extern __shared__ __nv_bfloat16 gsm[];
    const uint32_t sb = smem_u32(gsm);

    const int tid  = threadIdx.x;
    const int wid  = tid >> 5, lane = tid & 31;
    const int wm   = wid & 3,  wn   = wid >> 2;
    const int bm = blockIdx.y * 128, bn = blockIdx.x * 128;

    const int g_row = (lane & 7) + ((lane >> 3) & 1) * 8;
    const int g_col = ((lane >> 4) & 1) * 8;
    const int lrow0 = tid >> 3, lc16 = tid & 7;

    float acc[2][8][4];
    #pragma unroll
    for (int mt = 0; mt < 2; mt++)
        #pragma unroll
        for (int nf = 0; nf < 8; nf++)
            #pragma unroll
            for (int r = 0; r < 4; r++) acc[mt][nf][r] = 0.f;

    // chunk loader: 4 tiles (Ah, Al, Bh, Bl) into buffer buf
    auto load_chunk = [&](int buf, int k0) {
        uint32_t base = sb + buf * 4 * TILEB;
        #pragma unroll
        for (int i = 0; i < 4; i++) {
            int row = lrow0 + i * 32;
            uint32_t so = (uint32_t)((row * GROW + lc16 * 8) * 2);
            size_t ga = (size_t)(bm + row) * K + k0 + lc16 * 8;
            size_t gb = (size_t)(bn + row) * K + k0 + lc16 * 8;
            cpa16(base + 0*TILEB + so, Ah + ga);
            cpa16(base + 1*TILEB + so, Al + ga);
            cpa16(base + 2*TILEB + so, Bh + gb);
            cpa16(base + 3*TILEB + so, Bl + gb);
        }
        CPA_COMMIT();
    };

    const int nchunks = K / 64;
    load_chunk(0, 0);

    for (int kc = 0; kc < nchunks; kc++) {
        CPA_WAIT(0);
        __syncthreads();
        if (kc + 1 < nchunks) load_chunk((kc + 1) & 1, (kc + 1) * 64);

        uint32_t base = sb + (kc & 1) * 4 * TILEB;
        uint32_t uAh = base, uAl = base + TILEB;
        uint32_t uBh = base + 2*TILEB, uBl = base + 3*TILEB;

        #pragma unroll
        for (int ks = 0; ks < 4; ks++) {
            const int kcol = ks * 16 + g_col;
            uint32_t ah[2][4], al[2][4];
            #pragma unroll
            for (int mt = 0; mt < 2; mt++) {
                uint32_t off = ((wm*32 + mt*16 + g_row) * GROW + kcol) * 2;
                LDSM_X4(ah[mt][0], ah[mt][1], ah[mt][2], ah[mt][3], uAh + off);
                LDSM_X4(al[mt][0], al[mt][1], al[mt][2], al[mt][3], uAl + off);
            }
            uint32_t bh[8][2], bl[8][2];
            #pragma unroll
            for (int np = 0; np < 4; np++) {
                uint32_t off = ((wn*64 + np*16 + g_row) * GROW + kcol) * 2;
                uint32_t r0, r1, r2, r3;
                LDSM_X4(r0, r1, r2, r3, uBh + off);
                bh[2*np][0] = r0;   bh[2*np][1] = r2;
                bh[2*np+1][0] = r1; bh[2*np+1][1] = r3;
                LDSM_X4(r0, r1, r2, r3, uBl + off);
                bl[2*np][0] = r0;   bl[2*np][1] = r2;
                bl[2*np+1][0] = r1; bl[2*np+1][1] = r3;
            }
            #pragma unroll
            for (int mt = 0; mt < 2; mt++)
                #pragma unroll
                for (int nf = 0; nf < 8; nf++) {
                    MMA16816(acc[mt][nf], ah[mt], bh[nf]);
                    MMA16816(acc[mt][nf], ah[mt], bl[nf]);
                    MMA16816(acc[mt][nf], al[mt], bh[nf]);
                }
        }
    }

    const int qrow = lane >> 2, qcol = (lane & 3) * 2;
    #pragma unroll
    for (int mt = 0; mt < 2; mt++) {
        int r0 = bm + wm*32 + mt*16 + qrow;
        #pragma unroll
        for (int nf = 0; nf < 8; nf++) {
            int col = bn + wn*64 + nf*8 + qcol;
            float2 vb = bias ? *(const float2*)&bias[col] : make_float2(0.f, 0.f);
            float2 o0, o1;
            o0.x = alpha * (acc[mt][nf][0] + vb.x);
            o0.y = alpha * (acc[mt][nf][1] + vb.y);
            o1.x = alpha * (acc[mt][nf][2] + vb.x);
            o1.y = alpha * (acc[mt][nf][3] + vb.y);
            size_t off0 = (size_t)r0 * N + col;
            size_t off1 = (size_t)(r0 + 8) * N + col;
            if (add) {
                float2 a0 = *(const float2*)&add[off0];
                float2 a1 = *(const float2*)&add[off1];
                o0.x += a0.x; o0.y += a0.y;
                o1.x += a1.x; o1.y += a1.y;
            }
            if (C) {
                *(float2*)&C[off0] = o0;
                *(float2*)&C[off1] = o1;
            } else {
                float h0 = __bfloat162float(__float2bfloat16_rn(o0.x));
                float h1 = __bfloat162float(__float2bfloat16_rn(o0.y));
                float h2 = __bfloat162float(__float2bfloat16_rn(o1.x));
                float h3 = __bfloat162float(__float2bfloat16_rn(o1.y));
                *(uint32_t*)&Ch[off0] = bf2x(h0, h1);
                *(uint32_t*)&Cl[off0] = bf2x(o0.x - h0, o0.y - h1);
                *(uint32_t*)&Ch[off1] = bf2x(h2, h3);
                *(uint32_t*)&Cl[off1] = bf2x(o1.x - h2, o1.y - h3);
            }
        }
    }
}

// ---------------------------------------------------------------------------
// Attention v5: single-pass flash, cp.async double-buffered K/V.
// ---------------------------------------------------------------------------
#define ATS 72
#define ATILEB (128*ATS*2)            // 18432
// tiles: 0 qh, 1 ql, 2-3 k0(h,l), 4-5 v0(h,l), 6-7 k1(h,l), 8-9 v1(h,l)
#define ATTN_SMEM (10*ATILEB + Tq*4)  // 188416

__device__ __forceinline__ void s_mma(uint32_t uqh, uint32_t uql,
        uint32_t ukh, uint32_t ukl, int wid, int g_row, int g_col,
        float acc[16][4])
{
    #pragma unroll
    for (int nf = 0; nf < 16; nf++) {
        acc[nf][0] = 0.f; acc[nf][1] = 0.f; acc[nf][2] = 0.f; acc[nf][3] = 0.f;
    }
    #pragma unroll
    for (int ks = 0; ks < 4; ks++) {
        uint32_t ah[4], al[4];
        uint32_t aoff = (uint32_t)(((wid*16 + g_row) * ATS + ks*16 + g_col) * 2);
        LDSM_X4(ah[0], ah[1], ah[2], ah[3], uqh + aoff);
        LDSM_X4(al[0], al[1], al[2], al[3], uql + aoff);
        #pragma unroll
        for (int np = 0; np < 8; np++) {
            uint32_t boff = (uint32_t)(((np*16 + g_row) * ATS + ks*16 + g_col) * 2);
            uint32_t r0, r1, r2, r3, s0, s1, s2, s3;
            LDSM_X4(r0, r1, r2, r3, ukh + boff);
            LDSM_X4(s0, s1, s2, s3, ukl + boff);
            uint32_t b0[2] = {r0, r2}, b1[2] = {r1, r3};
            uint32_t c0[2] = {s0, s2}, c1[2] = {s1, s3};
            MMA16816(acc[2*np],   ah, b0);
            MMA16816(acc[2*np],   al, b0);
            MMA16816(acc[2*np],   ah, c0);
            MMA16816(acc[2*np+1], ah, b1);
            MMA16816(acc[2*np+1], al, b1);
            MMA16816(acc[2*np+1], ah, c1);
        }
    }
}

__global__ __launch_bounds__(256, 1)
void attn5_kernel(const __nv_bfloat16* __restrict__ qh_g, const __nv_bfloat16* __restrict__ ql_g,
                  const __nv_bfloat16* __restrict__ kh_g, const __nv_bfloat16* __restrict__ kl_g,
                  const __nv_bfloat16* __restrict__ vh_g, const __nv_bfloat16* __restrict__ vl_g,
                  const int* __restrict__ mask, float* __restrict__ Sraw,
                  float2* __restrict__ ml,
                  __nv_bfloat16* __restrict__ ctx_h, __nv_bfloat16* __restrict__ ctx_l)
{
    extern __shared__ __nv_bfloat16 sm_[];
    const uint32_t sb = smem_u32(sm_);
    int* msk = (int*)(sm_ + 10*128*ATS);

    const int t0 = blockIdx.x * 128, h = blockIdx.y, b = blockIdx.z;
    const int tid = threadIdx.x, wid = tid >> 5, lane = tid & 31;
    const int qrow = lane >> 2, qc2 = (lane & 3) * 2;
    const int g_row = (lane & 7) + ((lane >> 3) & 1) * 8;
    const int g_col = ((lane >> 4) & 1) * 8;
    const int lrow0 = tid >> 3, lc16 = tid & 7;

    const size_t gq  = ((size_t)(b*Tq + t0)) * Dq + h*DHq;
    const size_t gkv = ((size_t)(b*Tq)) * Dq + h*DHq;

    // pair loader into tiles (th, tl) from (gh, gl) at row offset s_row
    auto load_pair = [&](int th, int tl, const __nv_bfloat16* gh,
                         const __nv_bfloat16* gl, size_t gbase) {
        #pragma unroll
        for (int i = 0; i < 4; i++) {
            int row = lrow0 + i*32;
            uint32_t so = (uint32_t)((row*ATS + lc16*8) * 2);
            size_t g = gbase + (size_t)row * Dq + lc16*8;
            cpa16(sb + th*ATILEB + so, gh + g);
            cpa16(sb + tl*ATILEB + so, gl + g);
        }
    };

    // prologue: group1 = q + k0, group2 = v0
    load_pair(0, 1, qh_g, ql_g, gq);
    load_pair(2, 3, kh_g, kl_g, gkv);
    CPA_COMMIT();
    load_pair(4, 5, vh_g, vl_g, gkv);
    CPA_COMMIT();
    for (int s = tid; s < Tq; s += 256) msk[s] = mask[b*Tq + s];

    float m0 = -1e30f, m1 = -1e30f, l0 = 0.f, l1 = 0.f;
    float cacc[8][4];
    #pragma unroll
    for (int nf = 0; nf < 8; nf++) {
        cacc[nf][0] = 0.f; cacc[nf][1] = 0.f; cacc[nf][2] = 0.f; cacc[nf][3] = 0.f;
    }

    const size_t prow0 = ((size_t)((b*Hq + h)*Tq) + t0 + wid*16 + qrow) * Tq;
    const uint32_t uqh = sb, uql = sb + ATILEB;

    for (int st = 0; st < 8; st++) {
        const int kb_ = 2 + (st & 1) * 4;       // k tiles: 2/3 or 6/7
        const int vb_ = 4 + (st & 1) * 4;       // v tiles: 4/5 or 8/9

        CPA_WAIT(1);            // k(st) (+q on st=0) complete; v(st) may be in flight
        __syncthreads();

        if (st < 7) {           // issue next k and v into the other buffer
            const int nk = 2 + ((st+1) & 1) * 4;
            const int nv = 4 + ((st+1) & 1) * 4;
            load_pair(nk, nk+1, kh_g, kl_g, gkv + (size_t)((st+1)*128) * Dq);
            CPA_COMMIT();
            load_pair(nv, nv+1, vh_g, vl_g, gkv + (size_t)((st+1)*128) * Dq);
            CPA_COMMIT();
        }

        float acc[16][4];
        s_mma(uqh, uql, sb + kb_*ATILEB, sb + (kb_+1)*ATILEB, wid, g_row, g_col, acc);

        // ---- online softmax + raw-S store + P fragments (overlaps v load) --
        int s0 = st * 128;
        float cm0 = -1e30f, cm1 = -1e30f;
        #pragma unroll
        for (int nf = 0; nf < 16; nf++) {
            int col = s0 + nf*8 + qc2;
            int k0 = msk[col], k1 = msk[col + 1];
            acc[nf][0] = k0 ? acc[nf][0] : -1e9f;
            acc[nf][1] = k1 ? acc[nf][1] : -1e9f;
            acc[nf][2] = k0 ? acc[nf][2] : -1e9f;
            acc[nf][3] = k1 ? acc[nf][3] : -1e9f;
            cm0 = fmaxf(cm0, fmaxf(acc[nf][0], acc[nf][1]));
            cm1 = fmaxf(cm1, fmaxf(acc[nf][2], acc[nf][3]));
        }
        cm0 = fmaxf(cm0, __shfl_xor_sync(0xffffffffu, cm0, 1));
        cm0 = fmaxf(cm0, __shfl_xor_sync(0xffffffffu, cm0, 2));
        cm1 = fmaxf(cm1, __shfl_xor_sync(0xffffffffu, cm1, 1));
        cm1 = fmaxf(cm1, __shfl_xor_sync(0xffffffffu, cm1, 2));
        float nm0 = fmaxf(m0, cm0), nm1 = fmaxf(m1, cm1);
        float r0 = __expf(m0 - nm0), r1 = __expf(m1 - nm1);
        #pragma unroll
        for (int nf = 0; nf < 8; nf++) {
            cacc[nf][0] *= r0; cacc[nf][1] *= r0;
            cacc[nf][2] *= r1; cacc[nf][3] *= r1;
        }

        float sa0 = 0.f, sa1 = 0.f;
        uint32_t aPh[8][4], aPl[8][4];
        #pragma unroll
        for (int j = 0; j < 8; j++) {
            float p[8];
            #pragma unroll
            for (int u = 0; u < 2; u++) {
                int nf = 2*j + u;
                int col = s0 + nf*8 + qc2;
                *(float2*)&Sraw[prow0 + col]        = make_float2(acc[nf][0], acc[nf][1]);
                *(float2*)&Sraw[prow0 + 8*Tq + col] = make_float2(acc[nf][2], acc[nf][3]);
                float p0 = __expf(acc[nf][0] - nm0);
                float p1 = __expf(acc[nf][1] - nm0);
                float p2 = __expf(acc[nf][2] - nm1);
                float p3 = __expf(acc[nf][3] - nm1);
                sa0 += p0 + p1;  sa1 += p2 + p3;
                p[u*4+0] = p0; p[u*4+1] = p1; p[u*4+2] = p2; p[u*4+3] = p3;
            }
            float h0 = __bfloat162float(__float2bfloat16_rn(p[0]));
            float h1 = __bfloat162float(__float2bfloat16_rn(p[1]));
            float h2 = __bfloat162float(__float2bfloat16_rn(p[2]));
            float h3 = __bfloat162float(__float2bfloat16_rn(p[3]));
            float h4 = __bfloat162float(__float2bfloat16_rn(p[4]));
            float h5 = __bfloat162float(__float2bfloat16_rn(p[5]));
            float h6 = __bfloat162float(__float2bfloat16_rn(p[6]));
            float h7 = __bfloat162float(__float2bfloat16_rn(p[7]));
            aPh[j][0] = bf2x(h0, h1);            aPh[j][1] = bf2x(h2, h3);
            aPh[j][2] = bf2x(h4, h5);            aPh[j][3] = bf2x(h6, h7);
            aPl[j][0] = bf2x(p[0]-h0, p[1]-h1);  aPl[j][1] = bf2x(p[2]-h2, p[3]-h3);
            aPl[j][2] = bf2x(p[4]-h4, p[5]-h5);  aPl[j][3] = bf2x(p[6]-h6, p[7]-h7);
        }
        sa0 += __shfl_xor_sync(0xffffffffu, sa0, 1);
        sa0 += __shfl_xor_sync(0xffffffffu, sa0, 2);
        sa1 += __shfl_xor_sync(0xffffffffu, sa1, 1);
        sa1 += __shfl_xor_sync(0xffffffffu, sa1, 2);
        l0 = l0 * r0 + sa0;  m0 = nm0;
        l1 = l1 * r1 + sa1;  m1 = nm1;

        // wait for v(st): pending after issue = v(st), k(st+1), v(st+1)
        if (st < 7) { CPA_WAIT(2); } else { CPA_WAIT(0); }
        __syncthreads();

        // ctx += P @ V
        uint32_t uvh = sb + vb_*ATILEB, uvl = sb + (vb_+1)*ATILEB;
        #pragma unroll
        for (int ks = 0; ks < 8; ks++) {
            uint32_t bh[8][2], bl[8][2];
            #pragma unroll
            for (int npv = 0; npv < 4; npv++) {
                uint32_t off = (uint32_t)(((ks*16 + g_row) * ATS + npv*16 + g_col) * 2);
                uint32_t r0v, r1v, r2v, r3v;
                LDSM_T_X4(r0v, r1v, r2v, r3v, uvh + off);
                bh[2*npv][0] = r0v;   bh[2*npv][1] = r1v;
                bh[2*npv+1][0] = r2v; bh[2*npv+1][1] = r3v;
                LDSM_T_X4(r0v, r1v, r2v, r3v, uvl + off);
                bl[2*npv][0] = r0v;   bl[2*npv][1] = r1v;
                bl[2*npv+1][0] = r2v; bl[2*npv+1][1] = r3v;
            }
            #pragma unroll
            for (int nf = 0; nf < 8; nf++) {
                MMA16816(cacc[nf], aPh[ks], bh[nf]);
                MMA16816(cacc[nf], aPh[ks], bl[nf]);
                MMA16816(cacc[nf], aPl[ks], bh[nf]);
            }
        }
    }

    const float iL0 = 1.0f / l0, iL1 = 1.0f / l1;

    if ((lane & 3) == 0) {
        size_t pr = (size_t)(b*Hq + h)*Tq + t0 + wid*16 + qrow;
        ml[pr]     = make_float2(m0, iL0);
        ml[pr + 8] = make_float2(m1, iL1);
    }

    {
        int r = t0 + wid*16 + qrow;
        size_t base0 = ((size_t)(b*Tq + r)) * Dq + h*DHq;
        size_t base1 = ((size_t)(b*Tq + r + 8)) * Dq + h*DHq;
        #pragma unroll
        for (int nf = 0; nf < 8; nf++) {
            int col = nf*8 + qc2;
            float f0 = cacc[nf][0] * iL0, f1 = cacc[nf][1] * iL0;
            float f2 = cacc[nf][2] * iL1, f3 = cacc[nf][3] * iL1;
            float h0 = __bfloat162float(__float2bfloat16_rn(f0));
            float h1 = __bfloat162float(__float2bfloat16_rn(f1));
            float h2 = __bfloat162float(__float2bfloat16_rn(f2));
            float h3 = __bfloat162float(__float2bfloat16_rn(f3));
            *(uint32_t*)&ctx_h[base0 + col] = bf2x(h0, h1);
            *(uint32_t*)&ctx_l[base0 + col] = bf2x(f0 - h0, f1 - h1);
            *(uint32_t*)&ctx_h[base1 + col] = bf2x(h2, h3);
            *(uint32_t*)&ctx_l[base1 + col] = bf2x(f2 - h2, f3 - h3);
        }
    }
}

// probs[row][:] = exp(S - M) * iL   (streaming, in place)
__global__ __launch_bounds__(256)
void probs_norm_kernel(float* __restrict__ probs, const float2* __restrict__ ml)
{
    size_t row = blockIdx.x;
    float2 s = ml[row];
    float4* p = (float4*)(probs + row * Tq);
    float4 v = p[threadIdx.x];
    v.x = __expf(v.x - s.x) * s.y;
    v.y = __expf(v.y - s.x) * s.y;
    v.z = __expf(v.z - s.x) * s.y;
    v.w = __expf(v.w - s.x) * s.y;
    p[threadIdx.x] = v;
}

// ---------------------------------------------------------------------------
extern "C" void kernel_launch(void* const* d_in, const int* in_sizes, int n_in,
                              void* d_out, int out_size)
{
    const float* query   = (const float*)d_in[0];
    const float* key     = (const float*)d_in[1];
    const float* value   = (const float*)d_in[2];
    const float* rel_pos = (const float*)d_in[3];
    const int*   kpm     = (const int*)  d_in[4];
    const float* qn_g = (const float*)d_in[5];
    const float* qn_b = (const float*)d_in[6];
    const float* kn_g = (const float*)d_in[7];
    const float* kn_b = (const float*)d_in[8];
    const float* vn_g = (const float*)d_in[9];
    const float* vn_b = (const float*)d_in[10];
    const float* Wq = (const float*)d_in[11];
    const float* bq = (const float*)d_in[12];
    const float* Wk = (const float*)d_in[13];
    const float* bk = (const float*)d_in[14];
    const float* Wv = (const float*)d_in[15];
    const float* bv = (const float*)d_in[16];
    const float* Wr = (const float*)d_in[17];
    const float* Wo = (const float*)d_in[18];
    const float* bo = (const float*)d_in[19];

    float* out   = (float*)d_out;
    float* probs = out + OUT_ELEMS;

    float* p_k;   cudaGetSymbolAddress((void**)&p_k, g_k);
    float2* p_ml; cudaGetSymbolAddress((void**)&p_ml, g_ml);

    __nv_bfloat16 *lnq_h,*lnq_l,*lnk_h,*lnk_l,*lnv_h,*lnv_l,*rp_h,*rp_l;
    __nv_bfloat16 *qs_h,*qs_l,*kr_h,*kr_l,*vs_h,*vs_l,*ctx_h,*ctx_l;
    __nv_bfloat16 *wq_h,*wq_l,*wk_h,*wk_l,*wv_h,*wv_l,*wr_h,*wr_l,*wo_h,*wo_l;
    cudaGetSymbolAddress((void**)&lnq_h, g_lnq_h); cudaGetSymbolAddress((void**)&lnq_l, g_lnq_l);
    cudaGetSymbolAddress((void**)&lnk_h, g_lnk_h); cudaGetSymbolAddress((void**)&lnk_l, g_lnk_l);
    cudaGetSymbolAddress((void**)&lnv_h, g_lnv_h); cudaGetSymbolAddress((void**)&lnv_l, g_lnv_l);
    cudaGetSymbolAddress((void**)&rp_h,  g_rp_h);  cudaGetSymbolAddress((void**)&rp_l,  g_rp_l);
    cudaGetSymbolAddress((void**)&qs_h,  g_qs_h);  cudaGetSymbolAddress((void**)&qs_l,  g_qs_l);
    cudaGetSymbolAddress((void**)&kr_h,  g_kr_h);  cudaGetSymbolAddress((void**)&kr_l,  g_kr_l);
    cudaGetSymbolAddress((void**)&vs_h,  g_vs_h);  cudaGetSymbolAddress((void**)&vs_l,  g_vs_l);
    cudaGetSymbolAddress((void**)&ctx_h, g_ctx_h); cudaGetSymbolAddress((void**)&ctx_l, g_ctx_l);
    cudaGetSymbolAddress((void**)&wq_h, g_wq_h);   cudaGetSymbolAddress((void**)&wq_l, g_wq_l);
    cudaGetSymbolAddress((void**)&wk_h, g_wk_h);   cudaGetSymbolAddress((void**)&wk_l, g_wk_l);
    cudaGetSymbolAddress((void**)&wv_h, g_wv_h);   cudaGetSymbolAddress((void**)&wv_l, g_wv_l);
    cudaGetSymbolAddress((void**)&wr_h, g_wr_h);   cudaGetSymbolAddress((void**)&wr_l, g_wr_l);
    cudaGetSymbolAddress((void**)&wo_h, g_wo_h);   cudaGetSymbolAddress((void**)&wo_l, g_wo_l);

    cudaFuncSetAttribute(mma_gemm_kernel, cudaFuncAttributeMaxDynamicSharedMemorySize, GSM_BYTES);
    cudaFuncSetAttribute(attn5_kernel, cudaFuncAttributeMaxDynamicSharedMemorySize, ATTN_SMEM);

    // 1) weight transpose + split (one launch)
    WSplitArgs wa;
    wa.W[0]=Wq; wa.H[0]=wq_h; wa.L[0]=wq_l;
    wa.W[1]=Wk; wa.H[1]=wk_h; wa.L[1]=wk_l;
    wa.W[2]=Wv; wa.H[2]=wv_h; wa.L[2]=wv_l;
    wa.W[3]=Wr; wa.H[3]=wr_h; wa.L[3]=wr_l;
    wa.W[4]=Wo; wa.H[4]=wo_h; wa.L[4]=wo_l;
    dim3 wgrid(Dq/32, Dq/32, 5);
    wsplit5_kernel<<<wgrid, 256>>>(wa);

    // 2) LayerNorms (one launch) + rel_pos split
    LnArgs la;
    la.x[0]=query; la.g[0]=qn_g; la.b[0]=qn_b; la.h[0]=lnq_h; la.l[0]=lnq_l;
    la.x[1]=key;   la.g[1]=kn_g; la.b[1]=kn_b; la.h[1]=lnk_h; la.l[1]=lnk_l;
    la.x[2]=value; la.g[2]=vn_g; la.b[2]=vn_b; la.h[2]=lnv_h; la.l[2]=lnv_l;
    ln3_split_kernel<<<dim3(Mrows, 3), 256>>>(la);
    fsplit_kernel<<<(Mrows*Dq)/1024, 256>>>(rel_pos, rp_h, rp_l);

    // 3) projection GEMMs
    dim3 ggrid(Dq/128, Mrows/128);
    mma_gemm_kernel<<<ggrid, 256, GSM_BYTES>>>(lnq_h, lnq_l, wq_h, wq_l, bq, nullptr, 0.125f,
                                               nullptr, qs_h, qs_l, Mrows, Dq, Dq);
    mma_gemm_kernel<<<ggrid, 256, GSM_BYTES>>>(lnk_h, lnk_l, wk_h, wk_l, bk, nullptr, 1.0f,
                                               p_k, nullptr, nullptr, Mrows, Dq, Dq);
    mma_gemm_kernel<<<ggrid, 256, GSM_BYTES>>>(lnv_h, lnv_l, wv_h, wv_l, bv, nullptr, 1.0f,
                                               nullptr, vs_h, vs_l, Mrows, Dq, Dq);
    mma_gemm_kernel<<<ggrid, 256, GSM_BYTES>>>(rp_h,  rp_l,  wr_h, wr_l, nullptr, p_k, 0.1f,
                                               nullptr, kr_h, kr_l, Mrows, Dq, Dq);

    // 4) single-pass flash attention -> raw S + (M,1/L) + bf16-split ctx
    dim3 agrid(Tq/128, Hq, Bq);
    attn5_kernel<<<agrid, 256, ATTN_SMEM>>>(qs_h, qs_l, kr_h, kr_l, vs_h, vs_l,
                                            kpm, probs, p_ml, ctx_h, ctx_l);

    // 5) normalize probs in place
    probs_norm_kernel<<<Bq*Hq*Tq, 256>>>(probs, p_ml);

    // 6) out = ctx@Wo + bo
    mma_gemm_kernel<<<ggrid, 256, GSM_BYTES>>>(ctx_h, ctx_l, wo_h, wo_l, bo, nullptr, 1.0f,
                                               out, nullptr, nullptr, Mrows, Dq, Dq);
}

// round 9
// speedup vs baseline: 1.0049x; 1.0049x over previous
#include <cuda_runtime.h>
#include <cuda_bf16.h>
#include <math.h>
#include <cstdint>

// Problem constants
#define Bq   4
#define Tq   1024
#define Dq   1024
#define Hq   16
#define DHq  64
#define Mrows (Bq*Tq)
#define OUT_ELEMS ((size_t)Mrows*Dq)

// ---------------- device scratch (no runtime allocation) -------------------
__device__ float g_k[Mrows*Dq];
__device__ float2 g_ml[Bq*Hq*Tq];

__device__ __nv_bfloat16 g_lnq_h[Mrows*Dq], g_lnq_l[Mrows*Dq];
__device__ __nv_bfloat16 g_lnk_h[Mrows*Dq], g_lnk_l[Mrows*Dq];
__device__ __nv_bfloat16 g_lnv_h[Mrows*Dq], g_lnv_l[Mrows*Dq];
__device__ __nv_bfloat16 g_rp_h [Mrows*Dq], g_rp_l [Mrows*Dq];
__device__ __nv_bfloat16 g_qs_h [Mrows*Dq], g_qs_l [Mrows*Dq];
__device__ __nv_bfloat16 g_kr_h [Mrows*Dq], g_kr_l [Mrows*Dq];
__device__ __nv_bfloat16 g_vs_h [Mrows*Dq], g_vs_l [Mrows*Dq];
__device__ __nv_bfloat16 g_ctx_h[Mrows*Dq], g_ctx_l[Mrows*Dq];
__device__ __nv_bfloat16 g_wq_h[Dq*Dq], g_wq_l[Dq*Dq];
__device__ __nv_bfloat16 g_wk_h[Dq*Dq], g_wk_l[Dq*Dq];
__device__ __nv_bfloat16 g_wv_h[Dq*Dq], g_wv_l[Dq*Dq];
__device__ __nv_bfloat16 g_wr_h[Dq*Dq], g_wr_l[Dq*Dq];
__device__ __nv_bfloat16 g_wo_h[Dq*Dq], g_wo_l[Dq*Dq];

// ------------------------- asm helpers -------------------------------------
__device__ __forceinline__ uint32_t smem_u32(const void* p) {
    uint32_t a;
    asm("{ .reg .u64 t; cvta.to.shared.u64 t, %1; cvt.u32.u64 %0, t; }"
        : "=r"(a) : "l"(p));
    return a;
}
__device__ __forceinline__ void cpa16(uint32_t s, const void* g) {
    asm volatile("cp.async.cg.shared.global [%0], [%1], 16;" :: "r"(s), "l"(g));
}
#define CPA_COMMIT() asm volatile("cp.async.commit_group;" ::: "memory")
#define CPA_WAIT(n)  asm volatile("cp.async.wait_group %0;" :: "n"(n) : "memory")

#define LDSM_X4(r0, r1, r2, r3, addr)                                        \
    asm volatile("ldmatrix.sync.aligned.m8n8.x4.shared.b16 {%0,%1,%2,%3}, [%4];" \
        : "=r"(r0), "=r"(r1), "=r"(r2), "=r"(r3) : "r"(addr))
#define LDSM_T_X4(r0, r1, r2, r3, addr)                                      \
    asm volatile("ldmatrix.sync.aligned.m8n8.x4.trans.shared.b16 {%0,%1,%2,%3}, [%4];" \
        : "=r"(r0), "=r"(r1), "=r"(r2), "=r"(r3) : "r"(addr))
#define MMA16816(c, a, b)                                                    \
    asm volatile("mma.sync.aligned.m16n8k16.row.col.f32.bf16.bf16.f32 "      \
        "{%0,%1,%2,%3}, {%4,%5,%6,%7}, {%8,%9}, {%0,%1,%2,%3};"              \
        : "+f"((c)[0]), "+f"((c)[1]), "+f"((c)[2]), "+f"((c)[3])             \
        : "r"((a)[0]), "r"((a)[1]), "r"((a)[2]), "r"((a)[3]),                \
          "r"((b)[0]), "r"((b)[1]))

__device__ __forceinline__ uint32_t bf2x(float lo, float hi) {
    uint32_t r;
    asm("cvt.rn.bf16x2.f32 %0, %1, %2;" : "=r"(r) : "f"(hi), "f"(lo));
    return r;
}

// ---------------------------------------------------------------------------
// 3x LayerNorm in one launch; outputs bf16 hi/lo split.
// ---------------------------------------------------------------------------
struct LnArgs {
    const float *x[3], *g[3], *b[3];
    __nv_bfloat16 *h[3], *l[3];
};
__global__ __launch_bounds__(256)
void ln3_split_kernel(LnArgs a)
{
    int which = blockIdx.y;
    int row = blockIdx.x;
    int tid = threadIdx.x;
    const float4* xr = reinterpret_cast<const float4*>(a.x[which] + (size_t)row * Dq);
    float4 v = xr[tid];
    float s  = v.x + v.y + v.z + v.w;
    float s2 = v.x*v.x + v.y*v.y + v.z*v.z + v.w*v.w;
    #pragma unroll
    for (int o = 16; o; o >>= 1) {
        s  += __shfl_xor_sync(0xffffffffu, s,  o);
        s2 += __shfl_xor_sync(0xffffffffu, s2, o);
    }
    __shared__ float ws[8], ws2[8], stats[2];
    int w = tid >> 5, lane = tid & 31;
    if (lane == 0) { ws[w] = s; ws2[w] = s2; }
    __syncthreads();
    if (tid == 0) {
        float ts = 0.f, ts2 = 0.f;
        #pragma unroll
        for (int i = 0; i < 8; i++) { ts += ws[i]; ts2 += ws2[i]; }
        float mu  = ts * (1.0f / Dq);
        float var = ts2 * (1.0f / Dq) - mu * mu;
        stats[0] = mu;
        stats[1] = rsqrtf(var + 1e-5f);
    }
    __syncthreads();
    float mu = stats[0], rstd = stats[1];
    float4 g4 = reinterpret_cast<const float4*>(a.g[which])[tid];
    float4 b4 = reinterpret_cast<const float4*>(a.b[which])[tid];
    float o4[4];
    o4[0] = (v.x - mu) * rstd * g4.x + b4.x;
    o4[1] = (v.y - mu) * rstd * g4.y + b4.y;
    o4[2] = (v.z - mu) * rstd * g4.z + b4.z;
    o4[3] = (v.w - mu) * rstd * g4.w + b4.w;
    __nv_bfloat16 h4[4], l4[4];
    #pragma unroll
    for (int i = 0; i < 4; i++) {
        h4[i] = __float2bfloat16_rn(o4[i]);
        l4[i] = __float2bfloat16_rn(o4[i] - __bfloat162float(h4[i]));
    }
    *(ulonglong1*)&a.h[which][(size_t)row * Dq + tid*4] = *(ulonglong1*)h4;
    *(ulonglong1*)&a.l[which][(size_t)row * Dq + tid*4] = *(ulonglong1*)l4;
}

// plain fp32 -> bf16 hi/lo split (rel_pos)
__global__ __launch_bounds__(256)
void fsplit_kernel(const float* __restrict__ x,
                   __nv_bfloat16* __restrict__ hi, __nv_bfloat16* __restrict__ lo)
{
    size_t i = ((size_t)blockIdx.x * 256 + threadIdx.x) * 4;
    float4 v = *(const float4*)&x[i];
    float o4[4] = {v.x, v.y, v.z, v.w};
    __nv_bfloat16 h4[4], l4[4];
    #pragma unroll
    for (int j = 0; j < 4; j++) {
        h4[j] = __float2bfloat16_rn(o4[j]);
        l4[j] = __float2bfloat16_rn(o4[j] - __bfloat162float(h4[j]));
    }
    *(ulonglong1*)&hi[i] = *(ulonglong1*)h4;
    *(ulonglong1*)&lo[i] = *(ulonglong1*)l4;
}

// 5 weights: W [K,N] -> WT [N,K] bf16 hi/lo split, one launch
struct WSplitArgs {
    const float* W[5];
    __nv_bfloat16 *H[5], *L[5];
};
__global__ __launch_bounds__(256)
void wsplit5_kernel(WSplitArgs a)
{
    __shared__ float t[32][33];
    const float* W = a.W[blockIdx.z];
    __nv_bfloat16* hi = a.H[blockIdx.z];
    __nv_bfloat16* lo = a.L[blockIdx.z];
    int tx = threadIdx.x & 31, ty = threadIdx.x >> 5;
    int nb = blockIdx.x * 32, kb = blockIdx.y * 32;
    #pragma unroll
    for (int i = 0; i < 32; i += 8)
        t[ty+i][tx] = W[(size_t)(kb + ty + i) * Dq + nb + tx];
    __syncthreads();
    #pragma unroll
    for (int i = 0; i < 32; i += 8) {
        float v = t[tx][ty+i];
        __nv_bfloat16 h = __float2bfloat16_rn(v);
        size_t off = (size_t)(nb + ty + i) * Dq + kb + tx;
        hi[off] = h;
        lo[off] = __float2bfloat16_rn(v - __bfloat162float(h));
    }
}

// ---------------------------------------------------------------------------
// mma.sync GEMM, 3xBF16 emulated fp32, cp.async double-buffered.
// 512 threads / 16 warps, warp tile 32x32 — feeds 4 warps per SMSP.
// ---------------------------------------------------------------------------
#define GROW 72
#define GT   (128*GROW)
#define TILEB (GT*2)                  // 18432 B per tile
#define GSM_BYTES (8*TILEB)           // 147456 B (2 buffers x 4 tiles)

__global__ __launch_bounds__(512, 1)
void mma_gemm_kernel(const __nv_bfloat16* __restrict__ Ah, const __nv_bfloat16* __restrict__ Al,
                     const __nv_bfloat16* __restrict__ Bh, const __nv_bfloat16* __restrict__ Bl,
                     const float* __restrict__ bias, const float* __restrict__ add,
                     float alpha, float* __restrict__ C,
                     __nv_bfloat16* __restrict__ Ch, __nv_bfloat16* __restrict__ Cl,
                     int M, int N, int K)
{
    extern __shared__ __nv_bfloat16 gsm[];
    const uint32_t sb = smem_u32(gsm);

    const int tid  = threadIdx.x;
    const int wid  = tid >> 5, lane = tid & 31;
    const int wm   = wid & 3,  wn   = wid >> 2;      // 4x4 warp grid, 32x32 tiles
    const int bm = blockIdx.y * 128, bn = blockIdx.x * 128;

    const int g_row = (lane & 7) + ((lane >> 3) & 1) * 8;
    const int g_col = ((lane >> 4) & 1) * 8;
    const int lrow0 = tid >> 3, lc16 = tid & 7;      // rows 0..63

    float acc[2][4][4];
    #pragma unroll
    for (int mt = 0; mt < 2; mt++)
        #pragma unroll
        for (int nf = 0; nf < 4; nf++)
            #pragma unroll
            for (int r = 0; r < 4; r++) acc[mt][nf][r] = 0.f;

    // chunk loader: 4 tiles (Ah, Al, Bh, Bl) into buffer buf
    auto load_chunk = [&](int buf, int k0) {
        uint32_t base = sb + buf * 4 * TILEB;
        #pragma unroll
        for (int i = 0; i < 2; i++) {
            int row = lrow0 + i * 64;
            uint32_t so = (uint32_t)((row * GROW + lc16 * 8) * 2);
            size_t ga = (size_t)(bm + row) * K + k0 + lc16 * 8;
            size_t gb = (size_t)(bn + row) * K + k0 + lc16 * 8;
            cpa16(base + 0*TILEB + so, Ah + ga);
            cpa16(base + 1*TILEB + so, Al + ga);
            cpa16(base + 2*TILEB + so, Bh + gb);
            cpa16(base + 3*TILEB + so, Bl + gb);
        }
        CPA_COMMIT();
    };

    const int nchunks = K / 64;
    load_chunk(0, 0);

    for (int kc = 0; kc < nchunks; kc++) {
        CPA_WAIT(0);
        __syncthreads();
        if (kc + 1 < nchunks) load_chunk((kc + 1) & 1, (kc + 1) * 64);

        uint32_t base = sb + (kc & 1) * 4 * TILEB;
        uint32_t uAh = base, uAl = base + TILEB;
        uint32_t uBh = base + 2*TILEB, uBl = base + 3*TILEB;

        #pragma unroll
        for (int ks = 0; ks < 4; ks++) {
            const int kcol = ks * 16 + g_col;
            uint32_t ah[2][4], al[2][4];
            #pragma unroll
            for (int mt = 0; mt < 2; mt++) {
                uint32_t off = ((wm*32 + mt*16 + g_row) * GROW + kcol) * 2;
                LDSM_X4(ah[mt][0], ah[mt][1], ah[mt][2], ah[mt][3], uAh + off);
                LDSM_X4(al[mt][0], al[mt][1], al[mt][2], al[mt][3], uAl + off);
            }
            uint32_t bh[4][2], bl[4][2];
            #pragma unroll
            for (int np = 0; np < 2; np++) {
                uint32_t off = ((wn*32 + np*16 + g_row) * GROW + kcol) * 2;
                uint32_t r0, r1, r2, r3;
                LDSM_X4(r0, r1, r2, r3, uBh + off);
                bh[2*np][0] = r0;   bh[2*np][1] = r2;
                bh[2*np+1][0] = r1; bh[2*np+1][1] = r3;
                LDSM_X4(r0, r1, r2, r3, uBl + off);
                bl[2*np][0] = r0;   bl[2*np][1] = r2;
                bl[2*np+1][0] = r1; bl[2*np+1][1] = r3;
            }
            #pragma unroll
            for (int mt = 0; mt < 2; mt++)
                #pragma unroll
                for (int nf = 0; nf < 4; nf++) {
                    MMA16816(acc[mt][nf], ah[mt], bh[nf]);
                    MMA16816(acc[mt][nf], ah[mt], bl[nf]);
                    MMA16816(acc[mt][nf], al[mt], bh[nf]);
                }
        }
    }

    const int qrow = lane >> 2, qcol = (lane & 3) * 2;
    #pragma unroll
    for (int mt = 0; mt < 2; mt++) {
        int r0 = bm + wm*32 + mt*16 + qrow;
        #pragma unroll
        for (int nf = 0; nf < 4; nf++) {
            int col = bn + wn*32 + nf*8 + qcol;
            float2 vb = bias ? *(const float2*)&bias[col] : make_float2(0.f, 0.f);
            float2 o0, o1;
            o0.x = alpha * (acc[mt][nf][0] + vb.x);
            o0.y = alpha * (acc[mt][nf][1] + vb.y);
            o1.x = alpha * (acc[mt][nf][2] + vb.x);
            o1.y = alpha * (acc[mt][nf][3] + vb.y);
            size_t off0 = (size_t)r0 * N + col;
            size_t off1 = (size_t)(r0 + 8) * N + col;
            if (add) {
                float2 a0 = *(const float2*)&add[off0];
                float2 a1 = *(const float2*)&add[off1];
                o0.x += a0.x; o0.y += a0.y;
                o1.x += a1.x; o1.y += a1.y;
            }
            if (C) {
                *(float2*)&C[off0] = o0;
                *(float2*)&C[off1] = o1;
            } else {
                float h0 = __bfloat162float(__float2bfloat16_rn(o0.x));
                float h1 = __bfloat162float(__float2bfloat16_rn(o0.y));
                float h2 = __bfloat162float(__float2bfloat16_rn(o1.x));
                float h3 = __bfloat162float(__float2bfloat16_rn(o1.y));
                *(uint32_t*)&Ch[off0] = bf2x(h0, h1);
                *(uint32_t*)&Cl[off0] = bf2x(o0.x - h0, o0.y - h1);
                *(uint32_t*)&Ch[off1] = bf2x(h2, h3);
                *(uint32_t*)&Cl[off1] = bf2x(o1.x - h2, o1.y - h3);
            }
        }
    }
}

// ---------------------------------------------------------------------------
// Attention v5: single-pass flash, cp.async double-buffered K/V (unchanged).
// ---------------------------------------------------------------------------
#define ATS 72
#define ATILEB (128*ATS*2)            // 18432
// tiles: 0 qh, 1 ql, 2-3 k0(h,l), 4-5 v0(h,l), 6-7 k1(h,l), 8-9 v1(h,l)
#define ATTN_SMEM (10*ATILEB + Tq*4)  // 188416

__device__ __forceinline__ void s_mma(uint32_t uqh, uint32_t uql,
        uint32_t ukh, uint32_t ukl, int wid, int g_row, int g_col,
        float acc[16][4])
{
    #pragma unroll
    for (int nf = 0; nf < 16; nf++) {
        acc[nf][0] = 0.f; acc[nf][1] = 0.f; acc[nf][2] = 0.f; acc[nf][3] = 0.f;
    }
    #pragma unroll
    for (int ks = 0; ks < 4; ks++) {
        uint32_t ah[4], al[4];
        uint32_t aoff = (uint32_t)(((wid*16 + g_row) * ATS + ks*16 + g_col) * 2);
        LDSM_X4(ah[0], ah[1], ah[2], ah[3], uqh + aoff);
        LDSM_X4(al[0], al[1], al[2], al[3], uql + aoff);
        #pragma unroll
        for (int np = 0; np < 8; np++) {
            uint32_t boff = (uint32_t)(((np*16 + g_row) * ATS + ks*16 + g_col) * 2);
            uint32_t r0, r1, r2, r3, s0, s1, s2, s3;
            LDSM_X4(r0, r1, r2, r3, ukh + boff);
            LDSM_X4(s0, s1, s2, s3, ukl + boff);
            uint32_t b0[2] = {r0, r2}, b1[2] = {r1, r3};
            uint32_t c0[2] = {s0, s2}, c1[2] = {s1, s3};
            MMA16816(acc[2*np],   ah, b0);
            MMA16816(acc[2*np],   al, b0);
            MMA16816(acc[2*np],   ah, c0);
            MMA16816(acc[2*np+1], ah, b1);
            MMA16816(acc[2*np+1], al, b1);
            MMA16816(acc[2*np+1], ah, c1);
        }
    }
}

__global__ __launch_bounds__(256, 1)
void attn5_kernel(const __nv_bfloat16* __restrict__ qh_g, const __nv_bfloat16* __restrict__ ql_g,
                  const __nv_bfloat16* __restrict__ kh_g, const __nv_bfloat16* __restrict__ kl_g,
                  const __nv_bfloat16* __restrict__ vh_g, const __nv_bfloat16* __restrict__ vl_g,
                  const int* __restrict__ mask, float* __restrict__ Sraw,
                  float2* __restrict__ ml,
                  __nv_bfloat16* __restrict__ ctx_h, __nv_bfloat16* __restrict__ ctx_l)
{
    extern __shared__ __nv_bfloat16 sm_[];
    const uint32_t sb = smem_u32(sm_);
    int* msk = (int*)(sm_ + 10*128*ATS);

    const int t0 = blockIdx.x * 128, h = blockIdx.y, b = blockIdx.z;
    const int tid = threadIdx.x, wid = tid >> 5, lane = tid & 31;
    const int qrow = lane >> 2, qc2 = (lane & 3) * 2;
    const int g_row = (lane & 7) + ((lane >> 3) & 1) * 8;
    const int g_col = ((lane >> 4) & 1) * 8;
    const int lrow0 = tid >> 3, lc16 = tid & 7;

    const size_t gq  = ((size_t)(b*Tq + t0)) * Dq + h*DHq;
    const size_t gkv = ((size_t)(b*Tq)) * Dq + h*DHq;

    auto load_pair = [&](int th, int tl, const __nv_bfloat16* gh,
                         const __nv_bfloat16* gl, size_t gbase) {
        #pragma unroll
        for (int i = 0; i < 4; i++) {
            int row = lrow0 + i*32;
            uint32_t so = (uint32_t)((row*ATS + lc16*8) * 2);
            size_t g = gbase + (size_t)row * Dq + lc16*8;
            cpa16(sb + th*ATILEB + so, gh + g);
            cpa16(sb + tl*ATILEB + so, gl + g);
        }
    };

    load_pair(0, 1, qh_g, ql_g, gq);
    load_pair(2, 3, kh_g, kl_g, gkv);
    CPA_COMMIT();
    load_pair(4, 5, vh_g, vl_g, gkv);
    CPA_COMMIT();
    for (int s = tid; s < Tq; s += 256) msk[s] = mask[b*Tq + s];

    float m0 = -1e30f, m1 = -1e30f, l0 = 0.f, l1 = 0.f;
    float cacc[8][4];
    #pragma unroll
    for (int nf = 0; nf < 8; nf++) {
        cacc[nf][0] = 0.f; cacc[nf][1] = 0.f; cacc[nf][2] = 0.f; cacc[nf][3] = 0.f;
    }

    const size_t prow0 = ((size_t)((b*Hq + h)*Tq) + t0 + wid*16 + qrow) * Tq;
    const uint32_t uqh = sb, uql = sb + ATILEB;

    for (int st = 0; st < 8; st++) {
        const int kb_ = 2 + (st & 1) * 4;
        const int vb_ = 4 + (st & 1) * 4;

        CPA_WAIT(1);
        __syncthreads();

        if (st < 7) {
            const int nk = 2 + ((st+1) & 1) * 4;
            const int nv = 4 + ((st+1) & 1) * 4;
            load_pair(nk, nk+1, kh_g, kl_g, gkv + (size_t)((st+1)*128) * Dq);
            CPA_COMMIT();
            load_pair(nv, nv+1, vh_g, vl_g, gkv + (size_t)((st+1)*128) * Dq);
            CPA_COMMIT();
        }

        float acc[16][4];
        s_mma(uqh, uql, sb + kb_*ATILEB, sb + (kb_+1)*ATILEB, wid, g_row, g_col, acc);

        int s0 = st * 128;
        float cm0 = -1e30f, cm1 = -1e30f;
        #pragma unroll
        for (int nf = 0; nf < 16; nf++) {
            int col = s0 + nf*8 + qc2;
            int k0 = msk[col], k1 = msk[col + 1];
            acc[nf][0] = k0 ? acc[nf][0] : -1e9f;
            acc[nf][1] = k1 ? acc[nf][1] : -1e9f;
            acc[nf][2] = k0 ? acc[nf][2] : -1e9f;
            acc[nf][3] = k1 ? acc[nf][3] : -1e9f;
            cm0 = fmaxf(cm0, fmaxf(acc[nf][0], acc[nf][1]));
            cm1 = fmaxf(cm1, fmaxf(acc[nf][2], acc[nf][3]));
        }
        cm0 = fmaxf(cm0, __shfl_xor_sync(0xffffffffu, cm0, 1));
        cm0 = fmaxf(cm0, __shfl_xor_sync(0xffffffffu, cm0, 2));
        cm1 = fmaxf(cm1, __shfl_xor_sync(0xffffffffu, cm1, 1));
        cm1 = fmaxf(cm1, __shfl_xor_sync(0xffffffffu, cm1, 2));
        float nm0 = fmaxf(m0, cm0), nm1 = fmaxf(m1, cm1);
        float r0 = __expf(m0 - nm0), r1 = __expf(m1 - nm1);
        #pragma unroll
        for (int nf = 0; nf < 8; nf++) {
            cacc[nf][0] *= r0; cacc[nf][1] *= r0;
            cacc[nf][2] *= r1; cacc[nf][3] *= r1;
        }

        float sa0 = 0.f, sa1 = 0.f;
        uint32_t aPh[8][4], aPl[8][4];
        #pragma unroll
        for (int j = 0; j < 8; j++) {
            float p[8];
            #pragma unroll
            for (int u = 0; u < 2; u++) {
                int nf = 2*j + u;
                int col = s0 + nf*8 + qc2;
                *(float2*)&Sraw[prow0 + col]        = make_float2(acc[nf][0], acc[nf][1]);
                *(float2*)&Sraw[prow0 + 8*Tq + col] = make_float2(acc[nf][2], acc[nf][3]);
                float p0 = __expf(acc[nf][0] - nm0);
                float p1 = __expf(acc[nf][1] - nm0);
                float p2 = __expf(acc[nf][2] - nm1);
                float p3 = __expf(acc[nf][3] - nm1);
                sa0 += p0 + p1;  sa1 += p2 + p3;
                p[u*4+0] = p0; p[u*4+1] = p1; p[u*4+2] = p2; p[u*4+3] = p3;
            }
            float h0 = __bfloat162float(__float2bfloat16_rn(p[0]));
            float h1 = __bfloat162float(__float2bfloat16_rn(p[1]));
            float h2 = __bfloat162float(__float2bfloat16_rn(p[2]));
            float h3 = __bfloat162float(__float2bfloat16_rn(p[3]));
            float h4 = __bfloat162float(__float2bfloat16_rn(p[4]));
            float h5 = __bfloat162float(__float2bfloat16_rn(p[5]));
            float h6 = __bfloat162float(__float2bfloat16_rn(p[6]));
            float h7 = __bfloat162float(__float2bfloat16_rn(p[7]));
            aPh[j][0] = bf2x(h0, h1);            aPh[j][1] = bf2x(h2, h3);
            aPh[j][2] = bf2x(h4, h5);            aPh[j][3] = bf2x(h6, h7);
            aPl[j][0] = bf2x(p[0]-h0, p[1]-h1);  aPl[j][1] = bf2x(p[2]-h2, p[3]-h3);
            aPl[j][2] = bf2x(p[4]-h4, p[5]-h5);  aPl[j][3] = bf2x(p[6]-h6, p[7]-h7);
        }
        sa0 += __shfl_xor_sync(0xffffffffu, sa0, 1);
        sa0 += __shfl_xor_sync(0xffffffffu, sa0, 2);
        sa1 += __shfl_xor_sync(0xffffffffu, sa1, 1);
        sa1 += __shfl_xor_sync(0xffffffffu, sa1, 2);
        l0 = l0 * r0 + sa0;  m0 = nm0;
        l1 = l1 * r1 + sa1;  m1 = nm1;

        if (st < 7) { CPA_WAIT(2); } else { CPA_WAIT(0); }
        __syncthreads();

        uint32_t uvh = sb + vb_*ATILEB, uvl = sb + (vb_+1)*ATILEB;
        #pragma unroll
        for (int ks = 0; ks < 8; ks++) {
            uint32_t bh[8][2], bl[8][2];
            #pragma unroll
            for (int npv = 0; npv < 4; npv++) {
                uint32_t off = (uint32_t)(((ks*16 + g_row) * ATS + npv*16 + g_col) * 2);
                uint32_t r0v, r1v, r2v, r3v;
                LDSM_T_X4(r0v, r1v, r2v, r3v, uvh + off);
                bh[2*npv][0] = r0v;   bh[2*npv][1] = r1v;
                bh[2*npv+1][0] = r2v; bh[2*npv+1][1] = r3v;
                LDSM_T_X4(r0v, r1v, r2v, r3v, uvl + off);
                bl[2*npv][0] = r0v;   bl[2*npv][1] = r1v;
                bl[2*npv+1][0] = r2v; bl[2*npv+1][1] = r3v;
            }
            #pragma unroll
            for (int nf = 0; nf < 8; nf++) {
                MMA16816(cacc[nf], aPh[ks], bh[nf]);
                MMA16816(cacc[nf], aPh[ks], bl[nf]);
                MMA16816(cacc[nf], aPl[ks], bh[nf]);
            }
        }
    }

    const float iL0 = 1.0f / l0, iL1 = 1.0f / l1;

    if ((lane & 3) == 0) {
        size_t pr = (size_t)(b*Hq + h)*Tq + t0 + wid*16 + qrow;
        ml[pr]     = make_float2(m0, iL0);
        ml[pr + 8] = make_float2(m1, iL1);
    }

    {
        int r = t0 + wid*16 + qrow;
        size_t base0 = ((size_t)(b*Tq + r)) * Dq + h*DHq;
        size_t base1 = ((size_t)(b*Tq + r + 8)) * Dq + h*DHq;
        #pragma unroll
        for (int nf = 0; nf < 8; nf++) {
            int col = nf*8 + qc2;
            float f0 = cacc[nf][0] * iL0, f1 = cacc[nf][1] * iL0;
            float f2 = cacc[nf][2] * iL1, f3 = cacc[nf][3] * iL1;
            float h0 = __bfloat162float(__float2bfloat16_rn(f0));
            float h1 = __bfloat162float(__float2bfloat16_rn(f1));
            float h2 = __bfloat162float(__float2bfloat16_rn(f2));
            float h3 = __bfloat162float(__float2bfloat16_rn(f3));
            *(uint32_t*)&ctx_h[base0 + col] = bf2x(h0, h1);
            *(uint32_t*)&ctx_l[base0 + col] = bf2x(f0 - h0, f1 - h1);
            *(uint32_t*)&ctx_h[base1 + col] = bf2x(h2, h3);
            *(uint32_t*)&ctx_l[base1 + col] = bf2x(f2 - h2, f3 - h3);
        }
    }
}

// probs[row][:] = exp(S - M) * iL   (streaming, in place)
__global__ __launch_bounds__(256)
void probs_norm_kernel(float* __restrict__ probs, const float2* __restrict__ ml)
{
    size_t row = blockIdx.x;
    float2 s = ml[row];
    float4* p = (float4*)(probs + row * Tq);
    float4 v = p[threadIdx.x];
    v.x = __expf(v.x - s.x) * s.y;
    v.y = __expf(v.y - s.x) * s.y;
    v.z = __expf(v.z - s.x) * s.y;
    v.w = __expf(v.w - s.x) * s.y;
    p[threadIdx.x] = v;
}

// ---------------------------------------------------------------------------
extern "C" void kernel_launch(void* const* d_in, const int* in_sizes, int n_in,
                              void* d_out, int out_size)
{
    const float* query   = (const float*)d_in[0];
    const float* key     = (const float*)d_in[1];
    const float* value   = (const float*)d_in[2];
    const float* rel_pos = (const float*)d_in[3];
    const int*   kpm     = (const int*)  d_in[4];
    const float* qn_g = (const float*)d_in[5];
    const float* qn_b = (const float*)d_in[6];
    const float* kn_g = (const float*)d_in[7];
    const float* kn_b = (const float*)d_in[8];
    const float* vn_g = (const float*)d_in[9];
    const float* vn_b = (const float*)d_in[10];
    const float* Wq = (const float*)d_in[11];
    const float* bq = (const float*)d_in[12];
    const float* Wk = (const float*)d_in[13];
    const float* bk = (const float*)d_in[14];
    const float* Wv = (const float*)d_in[15];
    const float* bv = (const float*)d_in[16];
    const float* Wr = (const float*)d_in[17];
    const float* Wo = (const float*)d_in[18];
    const float* bo = (const float*)d_in[19];

    float* out   = (float*)d_out;
    float* probs = out + OUT_ELEMS;

    float* p_k;   cudaGetSymbolAddress((void**)&p_k, g_k);
    float2* p_ml; cudaGetSymbolAddress((void**)&p_ml, g_ml);

    __nv_bfloat16 *lnq_h,*lnq_l,*lnk_h,*lnk_l,*lnv_h,*lnv_l,*rp_h,*rp_l;
    __nv_bfloat16 *qs_h,*qs_l,*kr_h,*kr_l,*vs_h,*vs_l,*ctx_h,*ctx_l;
    __nv_bfloat16 *wq_h,*wq_l,*wk_h,*wk_l,*wv_h,*wv_l,*wr_h,*wr_l,*wo_h,*wo_l;
    cudaGetSymbolAddress((void**)&lnq_h, g_lnq_h); cudaGetSymbolAddress((void**)&lnq_l, g_lnq_l);
    cudaGetSymbolAddress((void**)&lnk_h, g_lnk_h); cudaGetSymbolAddress((void**)&lnk_l, g_lnk_l);
    cudaGetSymbolAddress((void**)&lnv_h, g_lnv_h); cudaGetSymbolAddress((void**)&lnv_l, g_lnv_l);
    cudaGetSymbolAddress((void**)&rp_h,  g_rp_h);  cudaGetSymbolAddress((void**)&rp_l,  g_rp_l);
    cudaGetSymbolAddress((void**)&qs_h,  g_qs_h);  cudaGetSymbolAddress((void**)&qs_l,  g_qs_l);
    cudaGetSymbolAddress((void**)&kr_h,  g_kr_h);  cudaGetSymbolAddress((void**)&kr_l,  g_kr_l);
    cudaGetSymbolAddress((void**)&vs_h,  g_vs_h);  cudaGetSymbolAddress((void**)&vs_l,  g_vs_l);
    cudaGetSymbolAddress((void**)&ctx_h, g_ctx_h); cudaGetSymbolAddress((void**)&ctx_l, g_ctx_l);
    cudaGetSymbolAddress((void**)&wq_h, g_wq_h);   cudaGetSymbolAddress((void**)&wq_l, g_wq_l);
    cudaGetSymbolAddress((void**)&wk_h, g_wk_h);   cudaGetSymbolAddress((void**)&wk_l, g_wk_l);
    cudaGetSymbolAddress((void**)&wv_h, g_wv_h);   cudaGetSymbolAddress((void**)&wv_l, g_wv_l);
    cudaGetSymbolAddress((void**)&wr_h, g_wr_h);   cudaGetSymbolAddress((void**)&wr_l, g_wr_l);
    cudaGetSymbolAddress((void**)&wo_h, g_wo_h);   cudaGetSymbolAddress((void**)&wo_l, g_wo_l);

    cudaFuncSetAttribute(mma_gemm_kernel, cudaFuncAttributeMaxDynamicSharedMemorySize, GSM_BYTES);
    cudaFuncSetAttribute(attn5_kernel, cudaFuncAttributeMaxDynamicSharedMemorySize, ATTN_SMEM);

    // 1) weight transpose + split (one launch)
    WSplitArgs wa;
    wa.W[0]=Wq; wa.H[0]=wq_h; wa.L[0]=wq_l;
    wa.W[1]=Wk; wa.H[1]=wk_h; wa.L[1]=wk_l;
    wa.W[2]=Wv; wa.H[2]=wv_h; wa.L[2]=wv_l;
    wa.W[3]=Wr; wa.H[3]=wr_h; wa.L[3]=wr_l;
    wa.W[4]=Wo; wa.H[4]=wo_h; wa.L[4]=wo_l;
    dim3 wgrid(Dq/32, Dq/32, 5);
    wsplit5_kernel<<<wgrid, 256>>>(wa);

    // 2) LayerNorms (one launch) + rel_pos split
    LnArgs la;
    la.x[0]=query; la.g[0]=qn_g; la.b[0]=qn_b; la.h[0]=lnq_h; la.l[0]=lnq_l;
    la.x[1]=key;   la.g[1]=kn_g; la.b[1]=kn_b; la.h[1]=lnk_h; la.l[1]=lnk_l;
    la.x[2]=value; la.g[2]=vn_g; la.b[2]=vn_b; la.h[2]=lnv_h; la.l[2]=lnv_l;
    ln3_split_kernel<<<dim3(Mrows, 3), 256>>>(la);
    fsplit_kernel<<<(Mrows*Dq)/1024, 256>>>(rel_pos, rp_h, rp_l);

    // 3) projection GEMMs
    dim3 ggrid(Dq/128, Mrows/128);
    mma_gemm_kernel<<<ggrid, 512, GSM_BYTES>>>(lnq_h, lnq_l, wq_h, wq_l, bq, nullptr, 0.125f,
                                               nullptr, qs_h, qs_l, Mrows, Dq, Dq);
    mma_gemm_kernel<<<ggrid, 512, GSM_BYTES>>>(lnk_h, lnk_l, wk_h, wk_l, bk, nullptr, 1.0f,
                                               p_k, nullptr, nullptr, Mrows, Dq, Dq);
    mma_gemm_kernel<<<ggrid, 512, GSM_BYTES>>>(lnv_h, lnv_l, wv_h, wv_l, bv, nullptr, 1.0f,
                                               nullptr, vs_h, vs_l, Mrows, Dq, Dq);
    mma_gemm_kernel<<<ggrid, 512, GSM_BYTES>>>(rp_h,  rp_l,  wr_h, wr_l, nullptr, p_k, 0.1f,
                                               nullptr, kr_h, kr_l, Mrows, Dq, Dq);

    // 4) single-pass flash attention -> raw S + (M,1/L) + bf16-split ctx
    dim3 agrid(Tq/128, Hq, Bq);
    attn5_kernel<<<agrid, 256, ATTN_SMEM>>>(qs_h, qs_l, kr_h, kr_l, vs_h, vs_l,
                                            kpm, probs, p_ml, ctx_h, ctx_l);

    // 5) normalize probs in place
    probs_norm_kernel<<<Bq*Hq*Tq, 256>>>(probs, p_ml);

    // 6) out = ctx@Wo + bo
    mma_gemm_kernel<<<ggrid, 512, GSM_BYTES>>>(ctx_h, ctx_l, wo_h, wo_l, bo, nullptr, 1.0f,
                                               out, nullptr, nullptr, Mrows, Dq, Dq);
}

// round 10
// speedup vs baseline: 1.0224x; 1.0174x over previous
#include <cuda_runtime.h>
#include <cuda_bf16.h>
#include <math.h>
#include <cstdint>

// Problem constants
#define Bq   4
#define Tq   1024
#define Dq   1024
#define Hq   16
#define DHq  64
#define Mrows (Bq*Tq)
#define OUT_ELEMS ((size_t)Mrows*Dq)

// ---------------- device scratch (no runtime allocation) -------------------
__device__ __nv_bfloat16 g_lnq_h[Mrows*Dq], g_lnq_l[Mrows*Dq];
__device__ __nv_bfloat16 g_lnk_h[Mrows*Dq], g_lnk_l[Mrows*Dq];
__device__ __nv_bfloat16 g_lnv_h[Mrows*Dq], g_lnv_l[Mrows*Dq];
__device__ __nv_bfloat16 g_rp_h [Mrows*Dq], g_rp_l [Mrows*Dq];
__device__ __nv_bfloat16 g_qs_h [Mrows*Dq], g_qs_l [Mrows*Dq];
__device__ __nv_bfloat16 g_kr_h [Mrows*Dq], g_kr_l [Mrows*Dq];
__device__ __nv_bfloat16 g_vs_h [Mrows*Dq], g_vs_l [Mrows*Dq];
__device__ __nv_bfloat16 g_ctx_h[Mrows*Dq], g_ctx_l[Mrows*Dq];
__device__ __nv_bfloat16 g_wq_h[Dq*Dq], g_wq_l[Dq*Dq];
__device__ __nv_bfloat16 g_wk_h[Dq*Dq], g_wk_l[Dq*Dq];
__device__ __nv_bfloat16 g_wv_h[Dq*Dq], g_wv_l[Dq*Dq];
__device__ __nv_bfloat16 g_wr_h[Dq*Dq], g_wr_l[Dq*Dq];
__device__ __nv_bfloat16 g_wo_h[Dq*Dq], g_wo_l[Dq*Dq];

// ------------------------- asm helpers -------------------------------------
__device__ __forceinline__ uint32_t smem_u32(const void* p) {
    uint32_t a;
    asm("{ .reg .u64 t; cvta.to.shared.u64 t, %1; cvt.u32.u64 %0, t; }"
        : "=r"(a) : "l"(p));
    return a;
}
__device__ __forceinline__ void cpa16(uint32_t s, const void* g) {
    asm volatile("cp.async.cg.shared.global [%0], [%1], 16;" :: "r"(s), "l"(g));
}
#define CPA_COMMIT() asm volatile("cp.async.commit_group;" ::: "memory")
#define CPA_WAIT(n)  asm volatile("cp.async.wait_group %0;" :: "n"(n) : "memory")

#define LDSM_X4(r0, r1, r2, r3, addr)                                        \
    asm volatile("ldmatrix.sync.aligned.m8n8.x4.shared.b16 {%0,%1,%2,%3}, [%4];" \
        : "=r"(r0), "=r"(r1), "=r"(r2), "=r"(r3) : "r"(addr))
#define LDSM_T_X4(r0, r1, r2, r3, addr)                                      \
    asm volatile("ldmatrix.sync.aligned.m8n8.x4.trans.shared.b16 {%0,%1,%2,%3}, [%4];" \
        : "=r"(r0), "=r"(r1), "=r"(r2), "=r"(r3) : "r"(addr))
#define MMA16816(c, a, b)                                                    \
    asm volatile("mma.sync.aligned.m16n8k16.row.col.f32.bf16.bf16.f32 "      \
        "{%0,%1,%2,%3}, {%4,%5,%6,%7}, {%8,%9}, {%0,%1,%2,%3};"              \
        : "+f"((c)[0]), "+f"((c)[1]), "+f"((c)[2]), "+f"((c)[3])             \
        : "r"((a)[0]), "r"((a)[1]), "r"((a)[2]), "r"((a)[3]),                \
          "r"((b)[0]), "r"((b)[1]))

__device__ __forceinline__ uint32_t bf2x(float lo, float hi) {
    uint32_t r;
    asm("cvt.rn.bf16x2.f32 %0, %1, %2;" : "=r"(r) : "f"(hi), "f"(lo));
    return r;
}

// ---------------------------------------------------------------------------
// 3x LayerNorm in one launch; outputs bf16 hi/lo split.
// ---------------------------------------------------------------------------
struct LnArgs {
    const float *x[3], *g[3], *b[3];
    __nv_bfloat16 *h[3], *l[3];
};
__global__ __launch_bounds__(256)
void ln3_split_kernel(LnArgs a)
{
    int which = blockIdx.y;
    int row = blockIdx.x;
    int tid = threadIdx.x;
    const float4* xr = reinterpret_cast<const float4*>(a.x[which] + (size_t)row * Dq);
    float4 v = xr[tid];
    float s  = v.x + v.y + v.z + v.w;
    float s2 = v.x*v.x + v.y*v.y + v.z*v.z + v.w*v.w;
    #pragma unroll
    for (int o = 16; o; o >>= 1) {
        s  += __shfl_xor_sync(0xffffffffu, s,  o);
        s2 += __shfl_xor_sync(0xffffffffu, s2, o);
    }
    __shared__ float ws[8], ws2[8], stats[2];
    int w = tid >> 5, lane = tid & 31;
    if (lane == 0) { ws[w] = s; ws2[w] = s2; }
    __syncthreads();
    if (tid == 0) {
        float ts = 0.f, ts2 = 0.f;
        #pragma unroll
        for (int i = 0; i < 8; i++) { ts += ws[i]; ts2 += ws2[i]; }
        float mu  = ts * (1.0f / Dq);
        float var = ts2 * (1.0f / Dq) - mu * mu;
        stats[0] = mu;
        stats[1] = rsqrtf(var + 1e-5f);
    }
    __syncthreads();
    float mu = stats[0], rstd = stats[1];
    float4 g4 = reinterpret_cast<const float4*>(a.g[which])[tid];
    float4 b4 = reinterpret_cast<const float4*>(a.b[which])[tid];
    float o4[4];
    o4[0] = (v.x - mu) * rstd * g4.x + b4.x;
    o4[1] = (v.y - mu) * rstd * g4.y + b4.y;
    o4[2] = (v.z - mu) * rstd * g4.z + b4.z;
    o4[3] = (v.w - mu) * rstd * g4.w + b4.w;
    __nv_bfloat16 h4[4], l4[4];
    #pragma unroll
    for (int i = 0; i < 4; i++) {
        h4[i] = __float2bfloat16_rn(o4[i]);
        l4[i] = __float2bfloat16_rn(o4[i] - __bfloat162float(h4[i]));
    }
    *(ulonglong1*)&a.h[which][(size_t)row * Dq + tid*4] = *(ulonglong1*)h4;
    *(ulonglong1*)&a.l[which][(size_t)row * Dq + tid*4] = *(ulonglong1*)l4;
}

// plain fp32 -> bf16 hi/lo split (rel_pos)
__global__ __launch_bounds__(256)
void fsplit_kernel(const float* __restrict__ x,
                   __nv_bfloat16* __restrict__ hi, __nv_bfloat16* __restrict__ lo)
{
    size_t i = ((size_t)blockIdx.x * 256 + threadIdx.x) * 4;
    float4 v = *(const float4*)&x[i];
    float o4[4] = {v.x, v.y, v.z, v.w};
    __nv_bfloat16 h4[4], l4[4];
    #pragma unroll
    for (int j = 0; j < 4; j++) {
        h4[j] = __float2bfloat16_rn(o4[j]);
        l4[j] = __float2bfloat16_rn(o4[j] - __bfloat162float(h4[j]));
    }
    *(ulonglong1*)&hi[i] = *(ulonglong1*)h4;
    *(ulonglong1*)&lo[i] = *(ulonglong1*)l4;
}

// 5 weights: W [K,N] -> WT [N,K] bf16 hi/lo split (with per-weight scale)
struct WSplitArgs {
    const float* W[5];
    __nv_bfloat16 *H[5], *L[5];
    float scale[5];
};
__global__ __launch_bounds__(256)
void wsplit5_kernel(WSplitArgs a)
{
    __shared__ float t[32][33];
    const float* W = a.W[blockIdx.z];
    __nv_bfloat16* hi = a.H[blockIdx.z];
    __nv_bfloat16* lo = a.L[blockIdx.z];
    float sc = a.scale[blockIdx.z];
    int tx = threadIdx.x & 31, ty = threadIdx.x >> 5;
    int nb = blockIdx.x * 32, kb = blockIdx.y * 32;
    #pragma unroll
    for (int i = 0; i < 32; i += 8)
        t[ty+i][tx] = W[(size_t)(kb + ty + i) * Dq + nb + tx];
    __syncthreads();
    #pragma unroll
    for (int i = 0; i < 32; i += 8) {
        float v = t[tx][ty+i] * sc;
        __nv_bfloat16 h = __float2bfloat16_rn(v);
        size_t off = (size_t)(nb + ty + i) * Dq + kb + tx;
        hi[off] = h;
        lo[off] = __float2bfloat16_rn(v - __bfloat162float(h));
    }
}

// ---------------------------------------------------------------------------
// Shared GEMM tile constants
// ---------------------------------------------------------------------------
#define GROW 72
#define GT   (128*GROW)
#define TILEB (GT*2)                  // 18432 B per tile
#define GSM_BYTES (8*TILEB)           // 147456 B (2 buffers x 4 tiles)

// ---------------------------------------------------------------------------
// Merged projection GEMM: q, v, kr (kr = [lnk|rp] @ [Wk; 0.1Wr], K=2048).
// blockIdx.y: 0-31 -> q tiles, 32-63 -> v tiles, 64-95 -> kr tiles.
// 512 threads, cp.async double-buffered, bf16 split output.
// ---------------------------------------------------------------------------
struct ProjArgs {
    const __nv_bfloat16 *Ah[3], *Al[3];       // primary A (K=1024)
    const __nv_bfloat16 *A2h, *A2l;           // second K-half A (kr only)
    const __nv_bfloat16 *Bh[3], *Bl[3];       // primary B (K=1024)
    const __nv_bfloat16 *B2h, *B2l;           // second K-half B (kr only)
    const float* bias[3];
    float alpha[3];
    __nv_bfloat16 *Ch[3], *Cl[3];
    int nch[3];
};

__global__ __launch_bounds__(512, 1)
void proj_gemm_kernel(ProjArgs a)
{
    extern __shared__ __nv_bfloat16 gsm[];
    const uint32_t sb = smem_u32(gsm);

    const int g  = blockIdx.y >> 5;
    const int bm = (blockIdx.y & 31) * 128, bn = blockIdx.x * 128;

    const int tid  = threadIdx.x;
    const int wid  = tid >> 5, lane = tid & 31;
    const int wm   = wid & 3,  wn   = wid >> 2;
    const int g_row = (lane & 7) + ((lane >> 3) & 1) * 8;
    const int g_col = ((lane >> 4) & 1) * 8;
    const int lrow0 = tid >> 3, lc16 = tid & 7;

    const __nv_bfloat16 *Ah1 = a.Ah[g], *Al1 = a.Al[g];
    const __nv_bfloat16 *Bh1 = a.Bh[g], *Bl1 = a.Bl[g];
    const int nchunks = a.nch[g];

    float acc[2][4][4];
    #pragma unroll
    for (int mt = 0; mt < 2; mt++)
        #pragma unroll
        for (int nf = 0; nf < 4; nf++)
            #pragma unroll
            for (int r = 0; r < 4; r++) acc[mt][nf][r] = 0.f;

    auto load_chunk = [&](int buf, int kc) {
        const __nv_bfloat16 *pAh, *pAl, *pBh, *pBl;
        int k0;
        if (kc < 16) { pAh = Ah1;  pAl = Al1;  pBh = Bh1;  pBl = Bl1;  k0 = kc * 64; }
        else         { pAh = a.A2h; pAl = a.A2l; pBh = a.B2h; pBl = a.B2l; k0 = (kc - 16) * 64; }
        uint32_t base = sb + buf * 4 * TILEB;
        #pragma unroll
        for (int i = 0; i < 2; i++) {
            int row = lrow0 + i * 64;
            uint32_t so = (uint32_t)((row * GROW + lc16 * 8) * 2);
            size_t ga = (size_t)(bm + row) * Dq + k0 + lc16 * 8;
            size_t gb = (size_t)(bn + row) * Dq + k0 + lc16 * 8;
            cpa16(base + 0*TILEB + so, pAh + ga);
            cpa16(base + 1*TILEB + so, pAl + ga);
            cpa16(base + 2*TILEB + so, pBh + gb);
            cpa16(base + 3*TILEB + so, pBl + gb);
        }
        CPA_COMMIT();
    };

    load_chunk(0, 0);

    for (int kc = 0; kc < nchunks; kc++) {
        CPA_WAIT(0);
        __syncthreads();
        if (kc + 1 < nchunks) load_chunk((kc + 1) & 1, kc + 1);

        uint32_t base = sb + (kc & 1) * 4 * TILEB;
        uint32_t uAh = base, uAl = base + TILEB;
        uint32_t uBh = base + 2*TILEB, uBl = base + 3*TILEB;

        #pragma unroll
        for (int ks = 0; ks < 4; ks++) {
            const int kcol = ks * 16 + g_col;
            uint32_t ah[2][4], al[2][4];
            #pragma unroll
            for (int mt = 0; mt < 2; mt++) {
                uint32_t off = ((wm*32 + mt*16 + g_row) * GROW + kcol) * 2;
                LDSM_X4(ah[mt][0], ah[mt][1], ah[mt][2], ah[mt][3], uAh + off);
                LDSM_X4(al[mt][0], al[mt][1], al[mt][2], al[mt][3], uAl + off);
            }
            uint32_t bh[4][2], bl[4][2];
            #pragma unroll
            for (int np = 0; np < 2; np++) {
                uint32_t off = ((wn*32 + np*16 + g_row) * GROW + kcol) * 2;
                uint32_t r0, r1, r2, r3;
                LDSM_X4(r0, r1, r2, r3, uBh + off);
                bh[2*np][0] = r0;   bh[2*np][1] = r2;
                bh[2*np+1][0] = r1; bh[2*np+1][1] = r3;
                LDSM_X4(r0, r1, r2, r3, uBl + off);
                bl[2*np][0] = r0;   bl[2*np][1] = r2;
                bl[2*np+1][0] = r1; bl[2*np+1][1] = r3;
            }
            #pragma unroll
            for (int mt = 0; mt < 2; mt++)
                #pragma unroll
                for (int nf = 0; nf < 4; nf++) {
                    MMA16816(acc[mt][nf], ah[mt], bh[nf]);
                    MMA16816(acc[mt][nf], ah[mt], bl[nf]);
                    MMA16816(acc[mt][nf], al[mt], bh[nf]);
                }
        }
    }

    const float alpha = a.alpha[g];
    const float* bias = a.bias[g];
    __nv_bfloat16 *Ch = a.Ch[g], *Cl = a.Cl[g];
    const int qrow = lane >> 2, qcol = (lane & 3) * 2;
    #pragma unroll
    for (int mt = 0; mt < 2; mt++) {
        int r0 = bm + wm*32 + mt*16 + qrow;
        #pragma unroll
        for (int nf = 0; nf < 4; nf++) {
            int col = bn + wn*32 + nf*8 + qcol;
            float2 vb = *(const float2*)&bias[col];
            float2 o0, o1;
            o0.x = alpha * (acc[mt][nf][0] + vb.x);
            o0.y = alpha * (acc[mt][nf][1] + vb.y);
            o1.x = alpha * (acc[mt][nf][2] + vb.x);
            o1.y = alpha * (acc[mt][nf][3] + vb.y);
            size_t off0 = (size_t)r0 * Dq + col;
            size_t off1 = (size_t)(r0 + 8) * Dq + col;
            float h0 = __bfloat162float(__float2bfloat16_rn(o0.x));
            float h1 = __bfloat162float(__float2bfloat16_rn(o0.y));
            float h2 = __bfloat162float(__float2bfloat16_rn(o1.x));
            float h3 = __bfloat162float(__float2bfloat16_rn(o1.y));
            *(uint32_t*)&Ch[off0] = bf2x(h0, h1);
            *(uint32_t*)&Cl[off0] = bf2x(o0.x - h0, o0.y - h1);
            *(uint32_t*)&Ch[off1] = bf2x(h2, h3);
            *(uint32_t*)&Cl[off1] = bf2x(o1.x - h2, o1.y - h3);
        }
    }
}

// ---------------------------------------------------------------------------
// Output GEMM (out = ctx@Wo + bo), fp32 out. Same engine, single problem.
// ---------------------------------------------------------------------------
__global__ __launch_bounds__(512, 1)
void out_gemm_kernel(const __nv_bfloat16* __restrict__ Ah, const __nv_bfloat16* __restrict__ Al,
                     const __nv_bfloat16* __restrict__ Bh, const __nv_bfloat16* __restrict__ Bl,
                     const float* __restrict__ bias, float* __restrict__ C)
{
    extern __shared__ __nv_bfloat16 gsm[];
    const uint32_t sb = smem_u32(gsm);

    const int tid  = threadIdx.x;
    const int wid  = tid >> 5, lane = tid & 31;
    const int wm   = wid & 3,  wn   = wid >> 2;
    const int bm = blockIdx.y * 128, bn = blockIdx.x * 128;
    const int g_row = (lane & 7) + ((lane >> 3) & 1) * 8;
    const int g_col = ((lane >> 4) & 1) * 8;
    const int lrow0 = tid >> 3, lc16 = tid & 7;

    float acc[2][4][4];
    #pragma unroll
    for (int mt = 0; mt < 2; mt++)
        #pragma unroll
        for (int nf = 0; nf < 4; nf++)
            #pragma unroll
            for (int r = 0; r < 4; r++) acc[mt][nf][r] = 0.f;

    auto load_chunk = [&](int buf, int k0) {
        uint32_t base = sb + buf * 4 * TILEB;
        #pragma unroll
        for (int i = 0; i < 2; i++) {
            int row = lrow0 + i * 64;
            uint32_t so = (uint32_t)((row * GROW + lc16 * 8) * 2);
            size_t ga = (size_t)(bm + row) * Dq + k0 + lc16 * 8;
            size_t gb = (size_t)(bn + row) * Dq + k0 + lc16 * 8;
            cpa16(base + 0*TILEB + so, Ah + ga);
            cpa16(base + 1*TILEB + so, Al + ga);
            cpa16(base + 2*TILEB + so, Bh + gb);
            cpa16(base + 3*TILEB + so, Bl + gb);
        }
        CPA_COMMIT();
    };

    load_chunk(0, 0);
    for (int kc = 0; kc < 16; kc++) {
        CPA_WAIT(0);
        __syncthreads();
        if (kc + 1 < 16) load_chunk((kc + 1) & 1, (kc + 1) * 64);

        uint32_t base = sb + (kc & 1) * 4 * TILEB;
        uint32_t uAh = base, uAl = base + TILEB;
        uint32_t uBh = base + 2*TILEB, uBl = base + 3*TILEB;

        #pragma unroll
        for (int ks = 0; ks < 4; ks++) {
            const int kcol = ks * 16 + g_col;
            uint32_t ah[2][4], al[2][4];
            #pragma unroll
            for (int mt = 0; mt < 2; mt++) {
                uint32_t off = ((wm*32 + mt*16 + g_row) * GROW + kcol) * 2;
                LDSM_X4(ah[mt][0], ah[mt][1], ah[mt][2], ah[mt][3], uAh + off);
                LDSM_X4(al[mt][0], al[mt][1], al[mt][2], al[mt][3], uAl + off);
            }
            uint32_t bh[4][2], bl[4][2];
            #pragma unroll
            for (int np = 0; np < 2; np++) {
                uint32_t off = ((wn*32 + np*16 + g_row) * GROW + kcol) * 2;
                uint32_t r0, r1, r2, r3;
                LDSM_X4(r0, r1, r2, r3, uBh + off);
                bh[2*np][0] = r0;   bh[2*np][1] = r2;
                bh[2*np+1][0] = r1; bh[2*np+1][1] = r3;
                LDSM_X4(r0, r1, r2, r3, uBl + off);
                bl[2*np][0] = r0;   bl[2*np][1] = r2;
                bl[2*np+1][0] = r1; bl[2*np+1][1] = r3;
            }
            #pragma unroll
            for (int mt = 0; mt < 2; mt++)
                #pragma unroll
                for (int nf = 0; nf < 4; nf++) {
                    MMA16816(acc[mt][nf], ah[mt], bh[nf]);
                    MMA16816(acc[mt][nf], ah[mt], bl[nf]);
                    MMA16816(acc[mt][nf], al[mt], bh[nf]);
                }
        }
    }

    const int qrow = lane >> 2, qcol = (lane & 3) * 2;
    #pragma unroll
    for (int mt = 0; mt < 2; mt++) {
        int r0 = bm + wm*32 + mt*16 + qrow;
        #pragma unroll
        for (int nf = 0; nf < 4; nf++) {
            int col = bn + wn*32 + nf*8 + qcol;
            float2 vb = *(const float2*)&bias[col];
            size_t off0 = (size_t)r0 * Dq + col;
            size_t off1 = (size_t)(r0 + 8) * Dq + col;
            *(float2*)&C[off0] = make_float2(acc[mt][nf][0] + vb.x, acc[mt][nf][1] + vb.y);
            *(float2*)&C[off1] = make_float2(acc[mt][nf][2] + vb.x, acc[mt][nf][3] + vb.y);
        }
    }
}

// ---------------------------------------------------------------------------
// Attention v6: single-pass flash, no max subtraction (|s|~6), exp(s) written
// to probs, in-kernel normalization at CTA end (same-thread RAW, L2-resident).
// ---------------------------------------------------------------------------
#define ATS 72
#define ATILEB (128*ATS*2)
#define ATTN_SMEM (10*ATILEB + Tq*4)  // 188416

__device__ __forceinline__ void s_mma(uint32_t uqh, uint32_t uql,
        uint32_t ukh, uint32_t ukl, int wid, int g_row, int g_col,
        float acc[16][4])
{
    #pragma unroll
    for (int nf = 0; nf < 16; nf++) {
        acc[nf][0] = 0.f; acc[nf][1] = 0.f; acc[nf][2] = 0.f; acc[nf][3] = 0.f;
    }
    #pragma unroll
    for (int ks = 0; ks < 4; ks++) {
        uint32_t ah[4], al[4];
        uint32_t aoff = (uint32_t)(((wid*16 + g_row) * ATS + ks*16 + g_col) * 2);
        LDSM_X4(ah[0], ah[1], ah[2], ah[3], uqh + aoff);
        LDSM_X4(al[0], al[1], al[2], al[3], uql + aoff);
        #pragma unroll
        for (int np = 0; np < 8; np++) {
            uint32_t boff = (uint32_t)(((np*16 + g_row) * ATS + ks*16 + g_col) * 2);
            uint32_t r0, r1, r2, r3, s0, s1, s2, s3;
            LDSM_X4(r0, r1, r2, r3, ukh + boff);
            LDSM_X4(s0, s1, s2, s3, ukl + boff);
            uint32_t b0[2] = {r0, r2}, b1[2] = {r1, r3};
            uint32_t c0[2] = {s0, s2}, c1[2] = {s1, s3};
            MMA16816(acc[2*np],   ah, b0);
            MMA16816(acc[2*np],   al, b0);
            MMA16816(acc[2*np],   ah, c0);
            MMA16816(acc[2*np+1], ah, b1);
            MMA16816(acc[2*np+1], al, b1);
            MMA16816(acc[2*np+1], ah, c1);
        }
    }
}

__global__ __launch_bounds__(256, 1)
void attn6_kernel(const __nv_bfloat16* __restrict__ qh_g, const __nv_bfloat16* __restrict__ ql_g,
                  const __nv_bfloat16* __restrict__ kh_g, const __nv_bfloat16* __restrict__ kl_g,
                  const __nv_bfloat16* __restrict__ vh_g, const __nv_bfloat16* __restrict__ vl_g,
                  const int* __restrict__ mask, float* __restrict__ probs,
                  __nv_bfloat16* __restrict__ ctx_h, __nv_bfloat16* __restrict__ ctx_l)
{
    extern __shared__ __nv_bfloat16 sm_[];
    const uint32_t sb = smem_u32(sm_);
    int* msk = (int*)(sm_ + 10*128*ATS);

    const int t0 = blockIdx.x * 128, h = blockIdx.y, b = blockIdx.z;
    const int tid = threadIdx.x, wid = tid >> 5, lane = tid & 31;
    const int qrow = lane >> 2, qc2 = (lane & 3) * 2;
    const int g_row = (lane & 7) + ((lane >> 3) & 1) * 8;
    const int g_col = ((lane >> 4) & 1) * 8;
    const int lrow0 = tid >> 3, lc16 = tid & 7;

    const size_t gq  = ((size_t)(b*Tq + t0)) * Dq + h*DHq;
    const size_t gkv = ((size_t)(b*Tq)) * Dq + h*DHq;

    auto load_pair = [&](int th, int tl, const __nv_bfloat16* gh,
                         const __nv_bfloat16* gl, size_t gbase) {
        #pragma unroll
        for (int i = 0; i < 4; i++) {
            int row = lrow0 + i*32;
            uint32_t so = (uint32_t)((row*ATS + lc16*8) * 2);
            size_t g = gbase + (size_t)row * Dq + lc16*8;
            cpa16(sb + th*ATILEB + so, gh + g);
            cpa16(sb + tl*ATILEB + so, gl + g);
        }
    };

    load_pair(0, 1, qh_g, ql_g, gq);
    load_pair(2, 3, kh_g, kl_g, gkv);
    CPA_COMMIT();
    load_pair(4, 5, vh_g, vl_g, gkv);
    CPA_COMMIT();
    for (int s = tid; s < Tq; s += 256) msk[s] = mask[b*Tq + s];

    float l0 = 0.f, l1 = 0.f;
    float cacc[8][4];
    #pragma unroll
    for (int nf = 0; nf < 8; nf++) {
        cacc[nf][0] = 0.f; cacc[nf][1] = 0.f; cacc[nf][2] = 0.f; cacc[nf][3] = 0.f;
    }

    const size_t prow0 = ((size_t)((b*Hq + h)*Tq) + t0 + wid*16 + qrow) * Tq;
    const uint32_t uqh = sb, uql = sb + ATILEB;

    for (int st = 0; st < 8; st++) {
        const int kb_ = 2 + (st & 1) * 4;
        const int vb_ = 4 + (st & 1) * 4;

        CPA_WAIT(1);
        __syncthreads();

        if (st < 7) {
            const int nk = 2 + ((st+1) & 1) * 4;
            const int nv = 4 + ((st+1) & 1) * 4;
            load_pair(nk, nk+1, kh_g, kl_g, gkv + (size_t)((st+1)*128) * Dq);
            CPA_COMMIT();
            load_pair(nv, nv+1, vh_g, vl_g, gkv + (size_t)((st+1)*128) * Dq);
            CPA_COMMIT();
        }

        float acc[16][4];
        s_mma(uqh, uql, sb + kb_*ATILEB, sb + (kb_+1)*ATILEB, wid, g_row, g_col, acc);

        // ---- exp + store + P fragments (no max subtraction) ----
        int s0 = st * 128;
        float sa0 = 0.f, sa1 = 0.f;
        uint32_t aPh[8][4], aPl[8][4];
        #pragma unroll
        for (int j = 0; j < 8; j++) {
            float p[8];
            #pragma unroll
            for (int u = 0; u < 2; u++) {
                int nf = 2*j + u;
                int col = s0 + nf*8 + qc2;
                int k0 = msk[col], k1 = msk[col + 1];
                float p0 = k0 ? __expf(acc[nf][0]) : 0.f;
                float p1 = k1 ? __expf(acc[nf][1]) : 0.f;
                float p2 = k0 ? __expf(acc[nf][2]) : 0.f;
                float p3 = k1 ? __expf(acc[nf][3]) : 0.f;
                *(float2*)&probs[prow0 + col]        = make_float2(p0, p1);
                *(float2*)&probs[prow0 + 8*Tq + col] = make_float2(p2, p3);
                sa0 += p0 + p1;  sa1 += p2 + p3;
                p[u*4+0] = p0; p[u*4+1] = p1; p[u*4+2] = p2; p[u*4+3] = p3;
            }
            float h0 = __bfloat162float(__float2bfloat16_rn(p[0]));
            float h1 = __bfloat162float(__float2bfloat16_rn(p[1]));
            float h2 = __bfloat162float(__float2bfloat16_rn(p[2]));
            float h3 = __bfloat162float(__float2bfloat16_rn(p[3]));
            float h4 = __bfloat162float(__float2bfloat16_rn(p[4]));
            float h5 = __bfloat162float(__float2bfloat16_rn(p[5]));
            float h6 = __bfloat162float(__float2bfloat16_rn(p[6]));
            float h7 = __bfloat162float(__float2bfloat16_rn(p[7]));
            aPh[j][0] = bf2x(h0, h1);            aPh[j][1] = bf2x(h2, h3);
            aPh[j][2] = bf2x(h4, h5);            aPh[j][3] = bf2x(h6, h7);
            aPl[j][0] = bf2x(p[0]-h0, p[1]-h1);  aPl[j][1] = bf2x(p[2]-h2, p[3]-h3);
            aPl[j][2] = bf2x(p[4]-h4, p[5]-h5);  aPl[j][3] = bf2x(p[6]-h6, p[7]-h7);
        }
        sa0 += __shfl_xor_sync(0xffffffffu, sa0, 1);
        sa0 += __shfl_xor_sync(0xffffffffu, sa0, 2);
        sa1 += __shfl_xor_sync(0xffffffffu, sa1, 1);
        sa1 += __shfl_xor_sync(0xffffffffu, sa1, 2);
        l0 += sa0;
        l1 += sa1;

        if (st < 7) { CPA_WAIT(2); } else { CPA_WAIT(0); }
        __syncthreads();

        uint32_t uvh = sb + vb_*ATILEB, uvl = sb + (vb_+1)*ATILEB;
        #pragma unroll
        for (int ks = 0; ks < 8; ks++) {
            uint32_t bh[8][2], bl[8][2];
            #pragma unroll
            for (int npv = 0; npv < 4; npv++) {
                uint32_t off = (uint32_t)(((ks*16 + g_row) * ATS + npv*16 + g_col) * 2);
                uint32_t r0v, r1v, r2v, r3v;
                LDSM_T_X4(r0v, r1v, r2v, r3v, uvh + off);
                bh[2*npv][0] = r0v;   bh[2*npv][1] = r1v;
                bh[2*npv+1][0] = r2v; bh[2*npv+1][1] = r3v;
                LDSM_T_X4(r0v, r1v, r2v, r3v, uvl + off);
                bl[2*npv][0] = r0v;   bl[2*npv][1] = r1v;
                bl[2*npv+1][0] = r2v; bl[2*npv+1][1] = r3v;
            }
            #pragma unroll
            for (int nf = 0; nf < 8; nf++) {
                MMA16816(cacc[nf], aPh[ks], bh[nf]);
                MMA16816(cacc[nf], aPh[ks], bl[nf]);
                MMA16816(cacc[nf], aPl[ks], bh[nf]);
            }
        }
    }

    const float iL0 = 1.0f / l0, iL1 = 1.0f / l1;

    // in-place probs normalization: each thread rescales exactly what it wrote
    // (same-thread global RAW; rows are CTA-private so L is final here)
    for (int st = 0; st < 8; st++) {
        int s0 = st * 128;
        #pragma unroll
        for (int nf = 0; nf < 16; nf++) {
            int col = s0 + nf*8 + qc2;
            float2 v0 = *(float2*)&probs[prow0 + col];
            float2 v1 = *(float2*)&probs[prow0 + 8*Tq + col];
            v0.x *= iL0; v0.y *= iL0;
            v1.x *= iL1; v1.y *= iL1;
            *(float2*)&probs[prow0 + col]        = v0;
            *(float2*)&probs[prow0 + 8*Tq + col] = v1;
        }
    }

    // write ctx as bf16 hi/lo split
    {
        int r = t0 + wid*16 + qrow;
        size_t base0 = ((size_t)(b*Tq + r)) * Dq + h*DHq;
        size_t base1 = ((size_t)(b*Tq + r + 8)) * Dq + h*DHq;
        #pragma unroll
        for (int nf = 0; nf < 8; nf++) {
            int col = nf*8 + qc2;
            float f0 = cacc[nf][0] * iL0, f1 = cacc[nf][1] * iL0;
            float f2 = cacc[nf][2] * iL1, f3 = cacc[nf][3] * iL1;
            float h0 = __bfloat162float(__float2bfloat16_rn(f0));
            float h1 = __bfloat162float(__float2bfloat16_rn(f1));
            float h2 = __bfloat162float(__float2bfloat16_rn(f2));
            float h3 = __bfloat162float(__float2bfloat16_rn(f3));
            *(uint32_t*)&ctx_h[base0 + col] = bf2x(h0, h1);
            *(uint32_t*)&ctx_l[base0 + col] = bf2x(f0 - h0, f1 - h1);
            *(uint32_t*)&ctx_h[base1 + col] = bf2x(h2, h3);
            *(uint32_t*)&ctx_l[base1 + col] = bf2x(f2 - h2, f3 - h3);
        }
    }
}

// ---------------------------------------------------------------------------
extern "C" void kernel_launch(void* const* d_in, const int* in_sizes, int n_in,
                              void* d_out, int out_size)
{
    const float* query   = (const float*)d_in[0];
    const float* key     = (const float*)d_in[1];
    const float* value   = (const float*)d_in[2];
    const float* rel_pos = (const float*)d_in[3];
    const int*   kpm     = (const int*)  d_in[4];
    const float* qn_g = (const float*)d_in[5];
    const float* qn_b = (const float*)d_in[6];
    const float* kn_g = (const float*)d_in[7];
    const float* kn_b = (const float*)d_in[8];
    const float* vn_g = (const float*)d_in[9];
    const float* vn_b = (const float*)d_in[10];
    const float* Wq = (const float*)d_in[11];
    const float* bq = (const float*)d_in[12];
    const float* Wk = (const float*)d_in[13];
    const float* bk = (const float*)d_in[14];
    const float* Wv = (const float*)d_in[15];
    const float* bv = (const float*)d_in[16];
    const float* Wr = (const float*)d_in[17];
    const float* Wo = (const float*)d_in[18];
    const float* bo = (const float*)d_in[19];

    float* out   = (float*)d_out;
    float* probs = out + OUT_ELEMS;

    __nv_bfloat16 *lnq_h,*lnq_l,*lnk_h,*lnk_l,*lnv_h,*lnv_l,*rp_h,*rp_l;
    __nv_bfloat16 *qs_h,*qs_l,*kr_h,*kr_l,*vs_h,*vs_l,*ctx_h,*ctx_l;
    __nv_bfloat16 *wq_h,*wq_l,*wk_h,*wk_l,*wv_h,*wv_l,*wr_h,*wr_l,*wo_h,*wo_l;
    cudaGetSymbolAddress((void**)&lnq_h, g_lnq_h); cudaGetSymbolAddress((void**)&lnq_l, g_lnq_l);
    cudaGetSymbolAddress((void**)&lnk_h, g_lnk_h); cudaGetSymbolAddress((void**)&lnk_l, g_lnk_l);
    cudaGetSymbolAddress((void**)&lnv_h, g_lnv_h); cudaGetSymbolAddress((void**)&lnv_l, g_lnv_l);
    cudaGetSymbolAddress((void**)&rp_h,  g_rp_h);  cudaGetSymbolAddress((void**)&rp_l,  g_rp_l);
    cudaGetSymbolAddress((void**)&qs_h,  g_qs_h);  cudaGetSymbolAddress((void**)&qs_l,  g_qs_l);
    cudaGetSymbolAddress((void**)&kr_h,  g_kr_h);  cudaGetSymbolAddress((void**)&kr_l,  g_kr_l);
    cudaGetSymbolAddress((void**)&vs_h,  g_vs_h);  cudaGetSymbolAddress((void**)&vs_l,  g_vs_l);
    cudaGetSymbolAddress((void**)&ctx_h, g_ctx_h); cudaGetSymbolAddress((void**)&ctx_l, g_ctx_l);
    cudaGetSymbolAddress((void**)&wq_h, g_wq_h);   cudaGetSymbolAddress((void**)&wq_l, g_wq_l);
    cudaGetSymbolAddress((void**)&wk_h, g_wk_h);   cudaGetSymbolAddress((void**)&wk_l, g_wk_l);
    cudaGetSymbolAddress((void**)&wv_h, g_wv_h);   cudaGetSymbolAddress((void**)&wv_l, g_wv_l);
    cudaGetSymbolAddress((void**)&wr_h, g_wr_h);   cudaGetSymbolAddress((void**)&wr_l, g_wr_l);
    cudaGetSymbolAddress((void**)&wo_h, g_wo_h);   cudaGetSymbolAddress((void**)&wo_l, g_wo_l);

    cudaFuncSetAttribute(proj_gemm_kernel, cudaFuncAttributeMaxDynamicSharedMemorySize, GSM_BYTES);
    cudaFuncSetAttribute(out_gemm_kernel, cudaFuncAttributeMaxDynamicSharedMemorySize, GSM_BYTES);
    cudaFuncSetAttribute(attn6_kernel, cudaFuncAttributeMaxDynamicSharedMemorySize, ATTN_SMEM);

    // 1) weight transpose + split (0.1 folded into Wr)
    WSplitArgs wa;
    wa.W[0]=Wq; wa.H[0]=wq_h; wa.L[0]=wq_l; wa.scale[0]=1.f;
    wa.W[1]=Wk; wa.H[1]=wk_h; wa.L[1]=wk_l; wa.scale[1]=1.f;
    wa.W[2]=Wv; wa.H[2]=wv_h; wa.L[2]=wv_l; wa.scale[2]=1.f;
    wa.W[3]=Wr; wa.H[3]=wr_h; wa.L[3]=wr_l; wa.scale[3]=0.1f;
    wa.W[4]=Wo; wa.H[4]=wo_h; wa.L[4]=wo_l; wa.scale[4]=1.f;
    dim3 wgrid(Dq/32, Dq/32, 5);
    wsplit5_kernel<<<wgrid, 256>>>(wa);

    // 2) LayerNorms (one launch) + rel_pos split
    LnArgs la;
    la.x[0]=query; la.g[0]=qn_g; la.b[0]=qn_b; la.h[0]=lnq_h; la.l[0]=lnq_l;
    la.x[1]=key;   la.g[1]=kn_g; la.b[1]=kn_b; la.h[1]=lnk_h; la.l[1]=lnk_l;
    la.x[2]=value; la.g[2]=vn_g; la.b[2]=vn_b; la.h[2]=lnv_h; la.l[2]=lnv_l;
    ln3_split_kernel<<<dim3(Mrows, 3), 256>>>(la);
    fsplit_kernel<<<(Mrows*Dq)/1024, 256>>>(rel_pos, rp_h, rp_l);

    // 3) merged projection GEMM: q, v, kr=[lnk|rp]@[Wk;0.1Wr]
    ProjArgs pa;
    pa.Ah[0]=lnq_h; pa.Al[0]=lnq_l; pa.Bh[0]=wq_h; pa.Bl[0]=wq_l;
    pa.bias[0]=bq;  pa.alpha[0]=0.125f; pa.Ch[0]=qs_h; pa.Cl[0]=qs_l; pa.nch[0]=16;
    pa.Ah[1]=lnv_h; pa.Al[1]=lnv_l; pa.Bh[1]=wv_h; pa.Bl[1]=wv_l;
    pa.bias[1]=bv;  pa.alpha[1]=1.f;    pa.Ch[1]=vs_h; pa.Cl[1]=vs_l; pa.nch[1]=16;
    pa.Ah[2]=lnk_h; pa.Al[2]=lnk_l; pa.Bh[2]=wk_h; pa.Bl[2]=wk_l;
    pa.A2h=rp_h; pa.A2l=rp_l; pa.B2h=wr_h; pa.B2l=wr_l;
    pa.bias[2]=bk;  pa.alpha[2]=1.f;    pa.Ch[2]=kr_h; pa.Cl[2]=kr_l; pa.nch[2]=32;
    proj_gemm_kernel<<<dim3(Dq/128, 96), 512, GSM_BYTES>>>(pa);

    // 4) single-pass flash attention -> normalized probs + bf16-split ctx
    dim3 agrid(Tq/128, Hq, Bq);
    attn6_kernel<<<agrid, 256, ATTN_SMEM>>>(qs_h, qs_l, kr_h, kr_l, vs_h, vs_l,
                                            kpm, probs, ctx_h, ctx_l);

    // 5) out = ctx@Wo + bo
    out_gemm_kernel<<<dim3(Dq/128, Mrows/128), 512, GSM_BYTES>>>(
        ctx_h, ctx_l, wo_h, wo_l, bo, out);
}

// round 11
// speedup vs baseline: 1.0700x; 1.0465x over previous
#include <cuda_runtime.h>
#include <cuda_bf16.h>
#include <cuda_fp16.h>
#include <math.h>
#include <cstdint>

// Problem constants
#define Bq   4
#define Tq   1024
#define Dq   1024
#define Hq   16
#define DHq  64
#define Mrows (Bq*Tq)
#define OUT_ELEMS ((size_t)Mrows*Dq)

// ---------------- device scratch (no runtime allocation) -------------------
__device__ __nv_bfloat16 g_lnq_h[Mrows*Dq], g_lnq_l[Mrows*Dq];
__device__ __nv_bfloat16 g_lnk_h[Mrows*Dq], g_lnk_l[Mrows*Dq];
__device__ __nv_bfloat16 g_lnv_h[Mrows*Dq], g_lnv_l[Mrows*Dq];
__device__ __nv_bfloat16 g_rp_h [Mrows*Dq], g_rp_l [Mrows*Dq];
__device__ __nv_bfloat16 g_qs_h [Mrows*Dq], g_qs_l [Mrows*Dq];
__device__ __nv_bfloat16 g_kr_h [Mrows*Dq], g_kr_l [Mrows*Dq];
__device__ __half        g_v16  [Mrows*Dq];
__device__ __nv_bfloat16 g_ctx_h[Mrows*Dq], g_ctx_l[Mrows*Dq];
__device__ __nv_bfloat16 g_wq_h[Dq*Dq], g_wq_l[Dq*Dq];
__device__ __nv_bfloat16 g_wk_h[Dq*Dq], g_wk_l[Dq*Dq];
__device__ __nv_bfloat16 g_wv_h[Dq*Dq], g_wv_l[Dq*Dq];
__device__ __nv_bfloat16 g_wr_h[Dq*Dq], g_wr_l[Dq*Dq];
__device__ __nv_bfloat16 g_wo_h[Dq*Dq], g_wo_l[Dq*Dq];

// ------------------------- asm helpers -------------------------------------
__device__ __forceinline__ uint32_t smem_u32(const void* p) {
    uint32_t a;
    asm("{ .reg .u64 t; cvta.to.shared.u64 t, %1; cvt.u32.u64 %0, t; }"
        : "=r"(a) : "l"(p));
    return a;
}
__device__ __forceinline__ void cpa16(uint32_t s, const void* g) {
    asm volatile("cp.async.cg.shared.global [%0], [%1], 16;" :: "r"(s), "l"(g));
}
#define CPA_COMMIT() asm volatile("cp.async.commit_group;" ::: "memory")
#define CPA_WAIT(n)  asm volatile("cp.async.wait_group %0;" :: "n"(n) : "memory")

#define LDSM_X4(r0, r1, r2, r3, addr)                                        \
    asm volatile("ldmatrix.sync.aligned.m8n8.x4.shared.b16 {%0,%1,%2,%3}, [%4];" \
        : "=r"(r0), "=r"(r1), "=r"(r2), "=r"(r3) : "r"(addr))
#define LDSM_T_X4(r0, r1, r2, r3, addr)                                      \
    asm volatile("ldmatrix.sync.aligned.m8n8.x4.trans.shared.b16 {%0,%1,%2,%3}, [%4];" \
        : "=r"(r0), "=r"(r1), "=r"(r2), "=r"(r3) : "r"(addr))
#define MMA16816(c, a, b)                                                    \
    asm volatile("mma.sync.aligned.m16n8k16.row.col.f32.bf16.bf16.f32 "      \
        "{%0,%1,%2,%3}, {%4,%5,%6,%7}, {%8,%9}, {%0,%1,%2,%3};"              \
        : "+f"((c)[0]), "+f"((c)[1]), "+f"((c)[2]), "+f"((c)[3])             \
        : "r"((a)[0]), "r"((a)[1]), "r"((a)[2]), "r"((a)[3]),                \
          "r"((b)[0]), "r"((b)[1]))
#define MMA16816F16(c, a, b)                                                 \
    asm volatile("mma.sync.aligned.m16n8k16.row.col.f32.f16.f16.f32 "        \
        "{%0,%1,%2,%3}, {%4,%5,%6,%7}, {%8,%9}, {%0,%1,%2,%3};"              \
        : "+f"((c)[0]), "+f"((c)[1]), "+f"((c)[2]), "+f"((c)[3])             \
        : "r"((a)[0]), "r"((a)[1]), "r"((a)[2]), "r"((a)[3]),                \
          "r"((b)[0]), "r"((b)[1]))

__device__ __forceinline__ uint32_t bf2x(float lo, float hi) {
    uint32_t r;
    asm("cvt.rn.bf16x2.f32 %0, %1, %2;" : "=r"(r) : "f"(hi), "f"(lo));
    return r;
}
__device__ __forceinline__ uint32_t h2x(float lo, float hi) {
    __half2 h = __floats2half2_rn(lo, hi);   // lo -> .x (low half)
    return *(uint32_t*)&h;
}

// ---------------------------------------------------------------------------
// 3x LayerNorm in one launch; outputs bf16 hi/lo split.
// ---------------------------------------------------------------------------
struct LnArgs {
    const float *x[3], *g[3], *b[3];
    __nv_bfloat16 *h[3], *l[3];
};
__global__ __launch_bounds__(256)
void ln3_split_kernel(LnArgs a)
{
    int which = blockIdx.y;
    int row = blockIdx.x;
    int tid = threadIdx.x;
    const float4* xr = reinterpret_cast<const float4*>(a.x[which] + (size_t)row * Dq);
    float4 v = xr[tid];
    float s  = v.x + v.y + v.z + v.w;
    float s2 = v.x*v.x + v.y*v.y + v.z*v.z + v.w*v.w;
    #pragma unroll
    for (int o = 16; o; o >>= 1) {
        s  += __shfl_xor_sync(0xffffffffu, s,  o);
        s2 += __shfl_xor_sync(0xffffffffu, s2, o);
    }
    __shared__ float ws[8], ws2[8], stats[2];
    int w = tid >> 5, lane = tid & 31;
    if (lane == 0) { ws[w] = s; ws2[w] = s2; }
    __syncthreads();
    if (tid == 0) {
        float ts = 0.f, ts2 = 0.f;
        #pragma unroll
        for (int i = 0; i < 8; i++) { ts += ws[i]; ts2 += ws2[i]; }
        float mu  = ts * (1.0f / Dq);
        float var = ts2 * (1.0f / Dq) - mu * mu;
        stats[0] = mu;
        stats[1] = rsqrtf(var + 1e-5f);
    }
    __syncthreads();
    float mu = stats[0], rstd = stats[1];
    float4 g4 = reinterpret_cast<const float4*>(a.g[which])[tid];
    float4 b4 = reinterpret_cast<const float4*>(a.b[which])[tid];
    float o4[4];
    o4[0] = (v.x - mu) * rstd * g4.x + b4.x;
    o4[1] = (v.y - mu) * rstd * g4.y + b4.y;
    o4[2] = (v.z - mu) * rstd * g4.z + b4.z;
    o4[3] = (v.w - mu) * rstd * g4.w + b4.w;
    __nv_bfloat16 h4[4], l4[4];
    #pragma unroll
    for (int i = 0; i < 4; i++) {
        h4[i] = __float2bfloat16_rn(o4[i]);
        l4[i] = __float2bfloat16_rn(o4[i] - __bfloat162float(h4[i]));
    }
    *(ulonglong1*)&a.h[which][(size_t)row * Dq + tid*4] = *(ulonglong1*)h4;
    *(ulonglong1*)&a.l[which][(size_t)row * Dq + tid*4] = *(ulonglong1*)l4;
}

// plain fp32 -> bf16 hi/lo split (rel_pos)
__global__ __launch_bounds__(256)
void fsplit_kernel(const float* __restrict__ x,
                   __nv_bfloat16* __restrict__ hi, __nv_bfloat16* __restrict__ lo)
{
    size_t i = ((size_t)blockIdx.x * 256 + threadIdx.x) * 4;
    float4 v = *(const float4*)&x[i];
    float o4[4] = {v.x, v.y, v.z, v.w};
    __nv_bfloat16 h4[4], l4[4];
    #pragma unroll
    for (int j = 0; j < 4; j++) {
        h4[j] = __float2bfloat16_rn(o4[j]);
        l4[j] = __float2bfloat16_rn(o4[j] - __bfloat162float(h4[j]));
    }
    *(ulonglong1*)&hi[i] = *(ulonglong1*)h4;
    *(ulonglong1*)&lo[i] = *(ulonglong1*)l4;
}

// 5 weights: W [K,N] -> WT [N,K] bf16 hi/lo split (with per-weight scale)
struct WSplitArgs {
    const float* W[5];
    __nv_bfloat16 *H[5], *L[5];
    float scale[5];
};
__global__ __launch_bounds__(256)
void wsplit5_kernel(WSplitArgs a)
{
    __shared__ float t[32][33];
    const float* W = a.W[blockIdx.z];
    __nv_bfloat16* hi = a.H[blockIdx.z];
    __nv_bfloat16* lo = a.L[blockIdx.z];
    float sc = a.scale[blockIdx.z];
    int tx = threadIdx.x & 31, ty = threadIdx.x >> 5;
    int nb = blockIdx.x * 32, kb = blockIdx.y * 32;
    #pragma unroll
    for (int i = 0; i < 32; i += 8)
        t[ty+i][tx] = W[(size_t)(kb + ty + i) * Dq + nb + tx];
    __syncthreads();
    #pragma unroll
    for (int i = 0; i < 32; i += 8) {
        float v = t[tx][ty+i] * sc;
        __nv_bfloat16 h = __float2bfloat16_rn(v);
        size_t off = (size_t)(nb + ty + i) * Dq + kb + tx;
        hi[off] = h;
        lo[off] = __float2bfloat16_rn(v - __bfloat162float(h));
    }
}

// ---------------------------------------------------------------------------
// Shared GEMM tile constants
// ---------------------------------------------------------------------------
#define GROW 72
#define GT   (128*GROW)
#define TILEB (GT*2)                  // 18432 B per tile
#define GSM_BYTES (8*TILEB)           // 147456 B

// ---------------------------------------------------------------------------
// Merged projection GEMM: q, v, kr (kr = [lnk|rp] @ [Wk; 0.1Wr], K=2048).
// blockIdx.y: 0-31 -> q, 32-63 -> v (fp16 out), 64-95 -> kr.
// ---------------------------------------------------------------------------
struct ProjArgs {
    const __nv_bfloat16 *Ah[3], *Al[3];
    const __nv_bfloat16 *A2h, *A2l;
    const __nv_bfloat16 *Bh[3], *Bl[3];
    const __nv_bfloat16 *B2h, *B2l;
    const float* bias[3];
    float alpha[3];
    __nv_bfloat16 *Ch[3], *Cl[3];     // for f16out, Ch is (half*) in disguise
    int nch[3];
    int f16out[3];
};

__global__ __launch_bounds__(512, 1)
void proj_gemm_kernel(ProjArgs a)
{
    extern __shared__ __nv_bfloat16 gsm[];
    const uint32_t sb = smem_u32(gsm);

    const int g  = blockIdx.y >> 5;
    const int bm = (blockIdx.y & 31) * 128, bn = blockIdx.x * 128;

    const int tid  = threadIdx.x;
    const int wid  = tid >> 5, lane = tid & 31;
    const int wm   = wid & 3,  wn   = wid >> 2;
    const int g_row = (lane & 7) + ((lane >> 3) & 1) * 8;
    const int g_col = ((lane >> 4) & 1) * 8;
    const int lrow0 = tid >> 3, lc16 = tid & 7;

    const __nv_bfloat16 *Ah1 = a.Ah[g], *Al1 = a.Al[g];
    const __nv_bfloat16 *Bh1 = a.Bh[g], *Bl1 = a.Bl[g];
    const int nchunks = a.nch[g];

    float acc[2][4][4];
    #pragma unroll
    for (int mt = 0; mt < 2; mt++)
        #pragma unroll
        for (int nf = 0; nf < 4; nf++)
            #pragma unroll
            for (int r = 0; r < 4; r++) acc[mt][nf][r] = 0.f;

    auto load_chunk = [&](int buf, int kc) {
        const __nv_bfloat16 *pAh, *pAl, *pBh, *pBl;
        int k0;
        if (kc < 16) { pAh = Ah1;  pAl = Al1;  pBh = Bh1;  pBl = Bl1;  k0 = kc * 64; }
        else         { pAh = a.A2h; pAl = a.A2l; pBh = a.B2h; pBl = a.B2l; k0 = (kc - 16) * 64; }
        uint32_t base = sb + buf * 4 * TILEB;
        #pragma unroll
        for (int i = 0; i < 2; i++) {
            int row = lrow0 + i * 64;
            uint32_t so = (uint32_t)((row * GROW + lc16 * 8) * 2);
            size_t ga = (size_t)(bm + row) * Dq + k0 + lc16 * 8;
            size_t gb = (size_t)(bn + row) * Dq + k0 + lc16 * 8;
            cpa16(base + 0*TILEB + so, pAh + ga);
            cpa16(base + 1*TILEB + so, pAl + ga);
            cpa16(base + 2*TILEB + so, pBh + gb);
            cpa16(base + 3*TILEB + so, pBl + gb);
        }
        CPA_COMMIT();
    };

    load_chunk(0, 0);

    for (int kc = 0; kc < nchunks; kc++) {
        CPA_WAIT(0);
        __syncthreads();
        if (kc + 1 < nchunks) load_chunk((kc + 1) & 1, kc + 1);

        uint32_t base = sb + (kc & 1) * 4 * TILEB;
        uint32_t uAh = base, uAl = base + TILEB;
        uint32_t uBh = base + 2*TILEB, uBl = base + 3*TILEB;

        #pragma unroll
        for (int ks = 0; ks < 4; ks++) {
            const int kcol = ks * 16 + g_col;
            uint32_t ah[2][4], al[2][4];
            #pragma unroll
            for (int mt = 0; mt < 2; mt++) {
                uint32_t off = ((wm*32 + mt*16 + g_row) * GROW + kcol) * 2;
                LDSM_X4(ah[mt][0], ah[mt][1], ah[mt][2], ah[mt][3], uAh + off);
                LDSM_X4(al[mt][0], al[mt][1], al[mt][2], al[mt][3], uAl + off);
            }
            uint32_t bh[4][2], bl[4][2];
            #pragma unroll
            for (int np = 0; np < 2; np++) {
                uint32_t off = ((wn*32 + np*16 + g_row) * GROW + kcol) * 2;
                uint32_t r0, r1, r2, r3;
                LDSM_X4(r0, r1, r2, r3, uBh + off);
                bh[2*np][0] = r0;   bh[2*np][1] = r2;
                bh[2*np+1][0] = r1; bh[2*np+1][1] = r3;
                LDSM_X4(r0, r1, r2, r3, uBl + off);
                bl[2*np][0] = r0;   bl[2*np][1] = r2;
                bl[2*np+1][0] = r1; bl[2*np+1][1] = r3;
            }
            #pragma unroll
            for (int mt = 0; mt < 2; mt++)
                #pragma unroll
                for (int nf = 0; nf < 4; nf++) {
                    MMA16816(acc[mt][nf], ah[mt], bh[nf]);
                    MMA16816(acc[mt][nf], ah[mt], bl[nf]);
                    MMA16816(acc[mt][nf], al[mt], bh[nf]);
                }
        }
    }

    const float alpha = a.alpha[g];
    const float* bias = a.bias[g];
    __nv_bfloat16 *Ch = a.Ch[g], *Cl = a.Cl[g];
    const int f16o = a.f16out[g];
    const int qrow = lane >> 2, qcol = (lane & 3) * 2;
    #pragma unroll
    for (int mt = 0; mt < 2; mt++) {
        int r0 = bm + wm*32 + mt*16 + qrow;
        #pragma unroll
        for (int nf = 0; nf < 4; nf++) {
            int col = bn + wn*32 + nf*8 + qcol;
            float2 vb = *(const float2*)&bias[col];
            float2 o0, o1;
            o0.x = alpha * (acc[mt][nf][0] + vb.x);
            o0.y = alpha * (acc[mt][nf][1] + vb.y);
            o1.x = alpha * (acc[mt][nf][2] + vb.x);
            o1.y = alpha * (acc[mt][nf][3] + vb.y);
            size_t off0 = (size_t)r0 * Dq + col;
            size_t off1 = (size_t)(r0 + 8) * Dq + col;
            if (f16o) {
                __half* C16 = (__half*)Ch;
                *(uint32_t*)&C16[off0] = h2x(o0.x, o0.y);
                *(uint32_t*)&C16[off1] = h2x(o1.x, o1.y);
            } else {
                float h0 = __bfloat162float(__float2bfloat16_rn(o0.x));
                float h1 = __bfloat162float(__float2bfloat16_rn(o0.y));
                float h2 = __bfloat162float(__float2bfloat16_rn(o1.x));
                float h3 = __bfloat162float(__float2bfloat16_rn(o1.y));
                *(uint32_t*)&Ch[off0] = bf2x(h0, h1);
                *(uint32_t*)&Cl[off0] = bf2x(o0.x - h0, o0.y - h1);
                *(uint32_t*)&Ch[off1] = bf2x(h2, h3);
                *(uint32_t*)&Cl[off1] = bf2x(o1.x - h2, o1.y - h3);
            }
        }
    }
}

// ---------------------------------------------------------------------------
// Output GEMM (out = ctx@Wo + bo), fp32 out.
// ---------------------------------------------------------------------------
__global__ __launch_bounds__(512, 1)
void out_gemm_kernel(const __nv_bfloat16* __restrict__ Ah, const __nv_bfloat16* __restrict__ Al,
                     const __nv_bfloat16* __restrict__ Bh, const __nv_bfloat16* __restrict__ Bl,
                     const float* __restrict__ bias, float* __restrict__ C)
{
    extern __shared__ __nv_bfloat16 gsm[];
    const uint32_t sb = smem_u32(gsm);

    const int tid  = threadIdx.x;
    const int wid  = tid >> 5, lane = tid & 31;
    const int wm   = wid & 3,  wn   = wid >> 2;
    const int bm = blockIdx.y * 128, bn = blockIdx.x * 128;
    const int g_row = (lane & 7) + ((lane >> 3) & 1) * 8;
    const int g_col = ((lane >> 4) & 1) * 8;
    const int lrow0 = tid >> 3, lc16 = tid & 7;

    float acc[2][4][4];
    #pragma unroll
    for (int mt = 0; mt < 2; mt++)
        #pragma unroll
        for (int nf = 0; nf < 4; nf++)
            #pragma unroll
            for (int r = 0; r < 4; r++) acc[mt][nf][r] = 0.f;

    auto load_chunk = [&](int buf, int k0) {
        uint32_t base = sb + buf * 4 * TILEB;
        #pragma unroll
        for (int i = 0; i < 2; i++) {
            int row = lrow0 + i * 64;
            uint32_t so = (uint32_t)((row * GROW + lc16 * 8) * 2);
            size_t ga = (size_t)(bm + row) * Dq + k0 + lc16 * 8;
            size_t gb = (size_t)(bn + row) * Dq + k0 + lc16 * 8;
            cpa16(base + 0*TILEB + so, Ah + ga);
            cpa16(base + 1*TILEB + so, Al + ga);
            cpa16(base + 2*TILEB + so, Bh + gb);
            cpa16(base + 3*TILEB + so, Bl + gb);
        }
        CPA_COMMIT();
    };

    load_chunk(0, 0);
    for (int kc = 0; kc < 16; kc++) {
        CPA_WAIT(0);
        __syncthreads();
        if (kc + 1 < 16) load_chunk((kc + 1) & 1, (kc + 1) * 64);

        uint32_t base = sb + (kc & 1) * 4 * TILEB;
        uint32_t uAh = base, uAl = base + TILEB;
        uint32_t uBh = base + 2*TILEB, uBl = base + 3*TILEB;

        #pragma unroll
        for (int ks = 0; ks < 4; ks++) {
            const int kcol = ks * 16 + g_col;
            uint32_t ah[2][4], al[2][4];
            #pragma unroll
            for (int mt = 0; mt < 2; mt++) {
                uint32_t off = ((wm*32 + mt*16 + g_row) * GROW + kcol) * 2;
                LDSM_X4(ah[mt][0], ah[mt][1], ah[mt][2], ah[mt][3], uAh + off);
                LDSM_X4(al[mt][0], al[mt][1], al[mt][2], al[mt][3], uAl + off);
            }
            uint32_t bh[4][2], bl[4][2];
            #pragma unroll
            for (int np = 0; np < 2; np++) {
                uint32_t off = ((wn*32 + np*16 + g_row) * GROW + kcol) * 2;
                uint32_t r0, r1, r2, r3;
                LDSM_X4(r0, r1, r2, r3, uBh + off);
                bh[2*np][0] = r0;   bh[2*np][1] = r2;
                bh[2*np+1][0] = r1; bh[2*np+1][1] = r3;
                LDSM_X4(r0, r1, r2, r3, uBl + off);
                bl[2*np][0] = r0;   bl[2*np][1] = r2;
                bl[2*np+1][0] = r1; bl[2*np+1][1] = r3;
            }
            #pragma unroll
            for (int mt = 0; mt < 2; mt++)
                #pragma unroll
                for (int nf = 0; nf < 4; nf++) {
                    MMA16816(acc[mt][nf], ah[mt], bh[nf]);
                    MMA16816(acc[mt][nf], ah[mt], bl[nf]);
                    MMA16816(acc[mt][nf], al[mt], bh[nf]);
                }
        }
    }

    const int qrow = lane >> 2, qcol = (lane & 3) * 2;
    #pragma unroll
    for (int mt = 0; mt < 2; mt++) {
        int r0 = bm + wm*32 + mt*16 + qrow;
        #pragma unroll
        for (int nf = 0; nf < 4; nf++) {
            int col = bn + wn*32 + nf*8 + qcol;
            float2 vb = *(const float2*)&bias[col];
            size_t off0 = (size_t)r0 * Dq + col;
            size_t off1 = (size_t)(r0 + 8) * Dq + col;
            *(float2*)&C[off0] = make_float2(acc[mt][nf][0] + vb.x, acc[mt][nf][1] + vb.y);
            *(float2*)&C[off1] = make_float2(acc[mt][nf][2] + vb.x, acc[mt][nf][3] + vb.y);
        }
    }
}

// ---------------------------------------------------------------------------
// Attention v7: single-pass flash, online max, fp16 PV (1-term), raw S to
// probs during loop, final in-place exp(S-M)*iL pass.
// smem tiles: 0 qh, 1 ql, 2-3 k0(h,l), 4 v0(f16), 5-6 k1(h,l), 7 v1(f16)
// ---------------------------------------------------------------------------
#define ATS 72
#define ATILEB (128*ATS*2)
#define ATTN_SMEM (8*ATILEB + Tq*4)   // 151552

__device__ __forceinline__ void s_mma(uint32_t uqh, uint32_t uql,
        uint32_t ukh, uint32_t ukl, int wid, int g_row, int g_col,
        float acc[16][4])
{
    #pragma unroll
    for (int nf = 0; nf < 16; nf++) {
        acc[nf][0] = 0.f; acc[nf][1] = 0.f; acc[nf][2] = 0.f; acc[nf][3] = 0.f;
    }
    #pragma unroll
    for (int ks = 0; ks < 4; ks++) {
        uint32_t ah[4], al[4];
        uint32_t aoff = (uint32_t)(((wid*16 + g_row) * ATS + ks*16 + g_col) * 2);
        LDSM_X4(ah[0], ah[1], ah[2], ah[3], uqh + aoff);
        LDSM_X4(al[0], al[1], al[2], al[3], uql + aoff);
        #pragma unroll
        for (int np = 0; np < 8; np++) {
            uint32_t boff = (uint32_t)(((np*16 + g_row) * ATS + ks*16 + g_col) * 2);
            uint32_t r0, r1, r2, r3, s0, s1, s2, s3;
            LDSM_X4(r0, r1, r2, r3, ukh + boff);
            LDSM_X4(s0, s1, s2, s3, ukl + boff);
            uint32_t b0[2] = {r0, r2}, b1[2] = {r1, r3};
            uint32_t c0[2] = {s0, s2}, c1[2] = {s1, s3};
            MMA16816(acc[2*np],   ah, b0);
            MMA16816(acc[2*np],   al, b0);
            MMA16816(acc[2*np],   ah, c0);
            MMA16816(acc[2*np+1], ah, b1);
            MMA16816(acc[2*np+1], al, b1);
            MMA16816(acc[2*np+1], ah, c1);
        }
    }
}

__global__ __launch_bounds__(256, 1)
void attn7_kernel(const __nv_bfloat16* __restrict__ qh_g, const __nv_bfloat16* __restrict__ ql_g,
                  const __nv_bfloat16* __restrict__ kh_g, const __nv_bfloat16* __restrict__ kl_g,
                  const __half* __restrict__ v16_g,
                  const int* __restrict__ mask, float* __restrict__ probs,
                  __nv_bfloat16* __restrict__ ctx_h, __nv_bfloat16* __restrict__ ctx_l)
{
    extern __shared__ __nv_bfloat16 sm_[];
    const uint32_t sb = smem_u32(sm_);
    int* msk = (int*)(sm_ + 8*128*ATS);

    const int t0 = blockIdx.x * 128, h = blockIdx.y, b = blockIdx.z;
    const int tid = threadIdx.x, wid = tid >> 5, lane = tid & 31;
    const int qrow = lane >> 2, qc2 = (lane & 3) * 2;
    const int g_row = (lane & 7) + ((lane >> 3) & 1) * 8;
    const int g_col = ((lane >> 4) & 1) * 8;
    const int lrow0 = tid >> 3, lc16 = tid & 7;

    const size_t gq  = ((size_t)(b*Tq + t0)) * Dq + h*DHq;
    const size_t gkv = ((size_t)(b*Tq)) * Dq + h*DHq;

    auto load_pair = [&](int th, int tl, const __nv_bfloat16* gh,
                         const __nv_bfloat16* gl, size_t gbase) {
        #pragma unroll
        for (int i = 0; i < 4; i++) {
            int row = lrow0 + i*32;
            uint32_t so = (uint32_t)((row*ATS + lc16*8) * 2);
            size_t g = gbase + (size_t)row * Dq + lc16*8;
            cpa16(sb + th*ATILEB + so, gh + g);
            cpa16(sb + tl*ATILEB + so, gl + g);
        }
    };
    auto load_v = [&](int tv, size_t gbase) {
        #pragma unroll
        for (int i = 0; i < 4; i++) {
            int row = lrow0 + i*32;
            uint32_t so = (uint32_t)((row*ATS + lc16*8) * 2);
            size_t g = gbase + (size_t)row * Dq + lc16*8;
            cpa16(sb + tv*ATILEB + so, v16_g + g);
        }
    };

    // prologue: group1 = q + k0, group2 = v0
    load_pair(0, 1, qh_g, ql_g, gq);
    load_pair(2, 3, kh_g, kl_g, gkv);
    CPA_COMMIT();
    load_v(4, gkv);
    CPA_COMMIT();
    for (int s = tid; s < Tq; s += 256) msk[s] = mask[b*Tq + s];

    float m0 = -1e30f, m1 = -1e30f, l0 = 0.f, l1 = 0.f;
    float cacc[8][4];
    #pragma unroll
    for (int nf = 0; nf < 8; nf++) {
        cacc[nf][0] = 0.f; cacc[nf][1] = 0.f; cacc[nf][2] = 0.f; cacc[nf][3] = 0.f;
    }

    const size_t prow0 = ((size_t)((b*Hq + h)*Tq) + t0 + wid*16 + qrow) * Tq;
    const uint32_t uqh = sb, uql = sb + ATILEB;

    for (int st = 0; st < 8; st++) {
        const int kb_ = 2 + (st & 1) * 3;   // 2-3 or 5-6
        const int vb_ = 4 + (st & 1) * 3;   // 4 or 7

        CPA_WAIT(1);        // k(st) ready; v(st) may be in flight
        __syncthreads();

        if (st < 7) {
            const int nk = 2 + ((st+1) & 1) * 3;
            const int nv = 4 + ((st+1) & 1) * 3;
            load_pair(nk, nk+1, kh_g, kl_g, gkv + (size_t)((st+1)*128) * Dq);
            CPA_COMMIT();
            load_v(nv, gkv + (size_t)((st+1)*128) * Dq);
            CPA_COMMIT();
        }

        float acc[16][4];
        s_mma(uqh, uql, sb + kb_*ATILEB, sb + (kb_+1)*ATILEB, wid, g_row, g_col, acc);

        // ---- mask + raw-S store + online max + fp16 P fragments ----
        int s0 = st * 128;
        float cm0 = -1e30f, cm1 = -1e30f;
        #pragma unroll
        for (int nf = 0; nf < 16; nf++) {
            int col = s0 + nf*8 + qc2;
            int k0 = msk[col], k1 = msk[col + 1];
            acc[nf][0] = k0 ? acc[nf][0] : -1e9f;
            acc[nf][1] = k1 ? acc[nf][1] : -1e9f;
            acc[nf][2] = k0 ? acc[nf][2] : -1e9f;
            acc[nf][3] = k1 ? acc[nf][3] : -1e9f;
            *(float2*)&probs[prow0 + col]        = make_float2(acc[nf][0], acc[nf][1]);
            *(float2*)&probs[prow0 + 8*Tq + col] = make_float2(acc[nf][2], acc[nf][3]);
            cm0 = fmaxf(cm0, fmaxf(acc[nf][0], acc[nf][1]));
            cm1 = fmaxf(cm1, fmaxf(acc[nf][2], acc[nf][3]));
        }
        cm0 = fmaxf(cm0, __shfl_xor_sync(0xffffffffu, cm0, 1));
        cm0 = fmaxf(cm0, __shfl_xor_sync(0xffffffffu, cm0, 2));
        cm1 = fmaxf(cm1, __shfl_xor_sync(0xffffffffu, cm1, 1));
        cm1 = fmaxf(cm1, __shfl_xor_sync(0xffffffffu, cm1, 2));
        float nm0 = fmaxf(m0, cm0), nm1 = fmaxf(m1, cm1);
        float r0 = __expf(m0 - nm0), r1 = __expf(m1 - nm1);
        #pragma unroll
        for (int nf = 0; nf < 8; nf++) {
            cacc[nf][0] *= r0; cacc[nf][1] *= r0;
            cacc[nf][2] *= r1; cacc[nf][3] *= r1;
        }

        float sa0 = 0.f, sa1 = 0.f;
        uint32_t aP[8][4];
        #pragma unroll
        for (int j = 0; j < 8; j++) {
            float p[8];
            #pragma unroll
            for (int u = 0; u < 2; u++) {
                int nf = 2*j + u;
                float p0 = __expf(acc[nf][0] - nm0);
                float p1 = __expf(acc[nf][1] - nm0);
                float p2 = __expf(acc[nf][2] - nm1);
                float p3 = __expf(acc[nf][3] - nm1);
                sa0 += p0 + p1;  sa1 += p2 + p3;
                p[u*4+0] = p0; p[u*4+1] = p1; p[u*4+2] = p2; p[u*4+3] = p3;
            }
            aP[j][0] = h2x(p[0], p[1]);
            aP[j][1] = h2x(p[2], p[3]);
            aP[j][2] = h2x(p[4], p[5]);
            aP[j][3] = h2x(p[6], p[7]);
        }
        sa0 += __shfl_xor_sync(0xffffffffu, sa0, 1);
        sa0 += __shfl_xor_sync(0xffffffffu, sa0, 2);
        sa1 += __shfl_xor_sync(0xffffffffu, sa1, 1);
        sa1 += __shfl_xor_sync(0xffffffffu, sa1, 2);
        l0 = l0 * r0 + sa0;  m0 = nm0;
        l1 = l1 * r1 + sa1;  m1 = nm1;

        if (st < 7) { CPA_WAIT(2); } else { CPA_WAIT(0); }
        __syncthreads();

        // ctx += P @ V (fp16 single-term)
        uint32_t uv = sb + vb_*ATILEB;
        #pragma unroll
        for (int ks = 0; ks < 8; ks++) {
            uint32_t bv[8][2];
            #pragma unroll
            for (int npv = 0; npv < 4; npv++) {
                uint32_t off = (uint32_t)(((ks*16 + g_row) * ATS + npv*16 + g_col) * 2);
                uint32_t r0v, r1v, r2v, r3v;
                LDSM_T_X4(r0v, r1v, r2v, r3v, uv + off);
                bv[2*npv][0] = r0v;   bv[2*npv][1] = r1v;
                bv[2*npv+1][0] = r2v; bv[2*npv+1][1] = r3v;
            }
            #pragma unroll
            for (int nf = 0; nf < 8; nf++)
                MMA16816F16(cacc[nf], aP[ks], bv[nf]);
        }
    }

    const float iL0 = 1.0f / l0, iL1 = 1.0f / l1;

    // in-place probs: p = exp(S - M) * iL (each thread re-reads its own writes)
    for (int st = 0; st < 8; st++) {
        int s0 = st * 128;
        #pragma unroll
        for (int nf = 0; nf < 16; nf++) {
            int col = s0 + nf*8 + qc2;
            float2 v0 = *(float2*)&probs[prow0 + col];
            float2 v1 = *(float2*)&probs[prow0 + 8*Tq + col];
            v0.x = __expf(v0.x - m0) * iL0;
            v0.y = __expf(v0.y - m0) * iL0;
            v1.x = __expf(v1.x - m1) * iL1;
            v1.y = __expf(v1.y - m1) * iL1;
            *(float2*)&probs[prow0 + col]        = v0;
            *(float2*)&probs[prow0 + 8*Tq + col] = v1;
        }
    }

    // write ctx as bf16 hi/lo split
    {
        int r = t0 + wid*16 + qrow;
        size_t base0 = ((size_t)(b*Tq + r)) * Dq + h*DHq;
        size_t base1 = ((size_t)(b*Tq + r + 8)) * Dq + h*DHq;
        #pragma unroll
        for (int nf = 0; nf < 8; nf++) {
            int col = nf*8 + qc2;
            float f0 = cacc[nf][0] * iL0, f1 = cacc[nf][1] * iL0;
            float f2 = cacc[nf][2] * iL1, f3 = cacc[nf][3] * iL1;
            float h0 = __bfloat162float(__float2bfloat16_rn(f0));
            float h1 = __bfloat162float(__float2bfloat16_rn(f1));
            float h2 = __bfloat162float(__float2bfloat16_rn(f2));
            float h3 = __bfloat162float(__float2bfloat16_rn(f3));
            *(uint32_t*)&ctx_h[base0 + col] = bf2x(h0, h1);
            *(uint32_t*)&ctx_l[base0 + col] = bf2x(f0 - h0, f1 - h1);
            *(uint32_t*)&ctx_h[base1 + col] = bf2x(h2, h3);
            *(uint32_t*)&ctx_l[base1 + col] = bf2x(f2 - h2, f3 - h3);
        }
    }
}

// ---------------------------------------------------------------------------
extern "C" void kernel_launch(void* const* d_in, const int* in_sizes, int n_in,
                              void* d_out, int out_size)
{
    const float* query   = (const float*)d_in[0];
    const float* key     = (const float*)d_in[1];
    const float* value   = (const float*)d_in[2];
    const float* rel_pos = (const float*)d_in[3];
    const int*   kpm     = (const int*)  d_in[4];
    const float* qn_g = (const float*)d_in[5];
    const float* qn_b = (const float*)d_in[6];
    const float* kn_g = (const float*)d_in[7];
    const float* kn_b = (const float*)d_in[8];
    const float* vn_g = (const float*)d_in[9];
    const float* vn_b = (const float*)d_in[10];
    const float* Wq = (const float*)d_in[11];
    const float* bq = (const float*)d_in[12];
    const float* Wk = (const float*)d_in[13];
    const float* bk = (const float*)d_in[14];
    const float* Wv = (const float*)d_in[15];
    const float* bv = (const float*)d_in[16];
    const float* Wr = (const float*)d_in[17];
    const float* Wo = (const float*)d_in[18];
    const float* bo = (const float*)d_in[19];

    float* out   = (float*)d_out;
    float* probs = out + OUT_ELEMS;

    __nv_bfloat16 *lnq_h,*lnq_l,*lnk_h,*lnk_l,*lnv_h,*lnv_l,*rp_h,*rp_l;
    __nv_bfloat16 *qs_h,*qs_l,*kr_h,*kr_l,*ctx_h,*ctx_l;
    __half *v16;
    __nv_bfloat16 *wq_h,*wq_l,*wk_h,*wk_l,*wv_h,*wv_l,*wr_h,*wr_l,*wo_h,*wo_l;
    cudaGetSymbolAddress((void**)&lnq_h, g_lnq_h); cudaGetSymbolAddress((void**)&lnq_l, g_lnq_l);
    cudaGetSymbolAddress((void**)&lnk_h, g_lnk_h); cudaGetSymbolAddress((void**)&lnk_l, g_lnk_l);
    cudaGetSymbolAddress((void**)&lnv_h, g_lnv_h); cudaGetSymbolAddress((void**)&lnv_l, g_lnv_l);
    cudaGetSymbolAddress((void**)&rp_h,  g_rp_h);  cudaGetSymbolAddress((void**)&rp_l,  g_rp_l);
    cudaGetSymbolAddress((void**)&qs_h,  g_qs_h);  cudaGetSymbolAddress((void**)&qs_l,  g_qs_l);
    cudaGetSymbolAddress((void**)&kr_h,  g_kr_h);  cudaGetSymbolAddress((void**)&kr_l,  g_kr_l);
    cudaGetSymbolAddress((void**)&v16,   g_v16);
    cudaGetSymbolAddress((void**)&ctx_h, g_ctx_h); cudaGetSymbolAddress((void**)&ctx_l, g_ctx_l);
    cudaGetSymbolAddress((void**)&wq_h, g_wq_h);   cudaGetSymbolAddress((void**)&wq_l, g_wq_l);
    cudaGetSymbolAddress((void**)&wk_h, g_wk_h);   cudaGetSymbolAddress((void**)&wk_l, g_wk_l);
    cudaGetSymbolAddress((void**)&wv_h, g_wv_h);   cudaGetSymbolAddress((void**)&wv_l, g_wv_l);
    cudaGetSymbolAddress((void**)&wr_h, g_wr_h);   cudaGetSymbolAddress((void**)&wr_l, g_wr_l);
    cudaGetSymbolAddress((void**)&wo_h, g_wo_h);   cudaGetSymbolAddress((void**)&wo_l, g_wo_l);

    cudaFuncSetAttribute(proj_gemm_kernel, cudaFuncAttributeMaxDynamicSharedMemorySize, GSM_BYTES);
    cudaFuncSetAttribute(out_gemm_kernel, cudaFuncAttributeMaxDynamicSharedMemorySize, GSM_BYTES);
    cudaFuncSetAttribute(attn7_kernel, cudaFuncAttributeMaxDynamicSharedMemorySize, ATTN_SMEM);

    // 1) weight transpose + split (0.1 folded into Wr)
    WSplitArgs wa;
    wa.W[0]=Wq; wa.H[0]=wq_h; wa.L[0]=wq_l; wa.scale[0]=1.f;
    wa.W[1]=Wk; wa.H[1]=wk_h; wa.L[1]=wk_l; wa.scale[1]=1.f;
    wa.W[2]=Wv; wa.H[2]=wv_h; wa.L[2]=wv_l; wa.scale[2]=1.f;
    wa.W[3]=Wr; wa.H[3]=wr_h; wa.L[3]=wr_l; wa.scale[3]=0.1f;
    wa.W[4]=Wo; wa.H[4]=wo_h; wa.L[4]=wo_l; wa.scale[4]=1.f;
    dim3 wgrid(Dq/32, Dq/32, 5);
    wsplit5_kernel<<<wgrid, 256>>>(wa);

    // 2) LayerNorms (one launch) + rel_pos split
    LnArgs la;
    la.x[0]=query; la.g[0]=qn_g; la.b[0]=qn_b; la.h[0]=lnq_h; la.l[0]=lnq_l;
    la.x[1]=key;   la.g[1]=kn_g; la.b[1]=kn_b; la.h[1]=lnk_h; la.l[1]=lnk_l;
    la.x[2]=value; la.g[2]=vn_g; la.b[2]=vn_b; la.h[2]=lnv_h; la.l[2]=lnv_l;
    ln3_split_kernel<<<dim3(Mrows, 3), 256>>>(la);
    fsplit_kernel<<<(Mrows*Dq)/1024, 256>>>(rel_pos, rp_h, rp_l);

    // 3) merged projection GEMM: q, v (fp16 out), kr=[lnk|rp]@[Wk;0.1Wr]
    ProjArgs pa;
    pa.Ah[0]=lnq_h; pa.Al[0]=lnq_l; pa.Bh[0]=wq_h; pa.Bl[0]=wq_l;
    pa.bias[0]=bq;  pa.alpha[0]=0.125f; pa.Ch[0]=qs_h; pa.Cl[0]=qs_l;
    pa.nch[0]=16;   pa.f16out[0]=0;
    pa.Ah[1]=lnv_h; pa.Al[1]=lnv_l; pa.Bh[1]=wv_h; pa.Bl[1]=wv_l;
    pa.bias[1]=bv;  pa.alpha[1]=1.f;    pa.Ch[1]=(__nv_bfloat16*)v16; pa.Cl[1]=nullptr;
    pa.nch[1]=16;   pa.f16out[1]=1;
    pa.Ah[2]=lnk_h; pa.Al[2]=lnk_l; pa.Bh[2]=wk_h; pa.Bl[2]=wk_l;
    pa.A2h=rp_h; pa.A2l=rp_l; pa.B2h=wr_h; pa.B2l=wr_l;
    pa.bias[2]=bk;  pa.alpha[2]=1.f;    pa.Ch[2]=kr_h; pa.Cl[2]=kr_l;
    pa.nch[2]=32;   pa.f16out[2]=0;
    proj_gemm_kernel<<<dim3(Dq/128, 96), 512, GSM_BYTES>>>(pa);

    // 4) single-pass flash attention (fp16 PV) -> normalized probs + bf16 ctx
    dim3 agrid(Tq/128, Hq, Bq);
    attn7_kernel<<<agrid, 256, ATTN_SMEM>>>(qs_h, qs_l, kr_h, kr_l, v16,
                                            kpm, probs, ctx_h, ctx_l);

    // 5) out = ctx@Wo + bo
    out_gemm_kernel<<<dim3(Dq/128, Mrows/128), 512, GSM_BYTES>>>(
        ctx_h, ctx_l, wo_h, wo_l, bo, out);
}

// round 12
// speedup vs baseline: 1.3072x; 1.2217x over previous
#include <cuda_runtime.h>
#include <cuda_bf16.h>
#include <cuda_fp16.h>
#include <math.h>
#include <cstdint>

// Problem constants
#define Bq   4
#define Tq   1024
#define Dq   1024
#define Hq   16
#define DHq  64
#define Mrows (Bq*Tq)
#define OUT_ELEMS ((size_t)Mrows*Dq)

// ---------------- device scratch (no runtime allocation) -------------------
__device__ __nv_bfloat16 g_lnq_h[Mrows*Dq], g_lnq_l[Mrows*Dq];
__device__ __nv_bfloat16 g_lnk_h[Mrows*Dq], g_lnk_l[Mrows*Dq];
__device__ __half        g_lnv16[Mrows*Dq];
__device__ __nv_bfloat16 g_rp_h [Mrows*Dq], g_rp_l [Mrows*Dq];
__device__ __nv_bfloat16 g_qs_h [Mrows*Dq], g_qs_l [Mrows*Dq];
__device__ __nv_bfloat16 g_kr_h [Mrows*Dq], g_kr_l [Mrows*Dq];
__device__ __half        g_v16  [Mrows*Dq];
__device__ __half        g_ctx16[Mrows*Dq];
__device__ __nv_bfloat16 g_wq_h[Dq*Dq], g_wq_l[Dq*Dq];
__device__ __nv_bfloat16 g_wk_h[Dq*Dq], g_wk_l[Dq*Dq];
__device__ __half        g_wv16[Dq*Dq];
__device__ __nv_bfloat16 g_wr_h[Dq*Dq], g_wr_l[Dq*Dq];
__device__ __half        g_wo16[Dq*Dq];

// ------------------------- asm helpers -------------------------------------
__device__ __forceinline__ uint32_t smem_u32(const void* p) {
    uint32_t a;
    asm("{ .reg .u64 t; cvta.to.shared.u64 t, %1; cvt.u32.u64 %0, t; }"
        : "=r"(a) : "l"(p));
    return a;
}
__device__ __forceinline__ void cpa16(uint32_t s, const void* g) {
    asm volatile("cp.async.cg.shared.global [%0], [%1], 16;" :: "r"(s), "l"(g));
}
#define CPA_COMMIT() asm volatile("cp.async.commit_group;" ::: "memory")
#define CPA_WAIT(n)  asm volatile("cp.async.wait_group %0;" :: "n"(n) : "memory")

#define LDSM_X4(r0, r1, r2, r3, addr)                                        \
    asm volatile("ldmatrix.sync.aligned.m8n8.x4.shared.b16 {%0,%1,%2,%3}, [%4];" \
        : "=r"(r0), "=r"(r1), "=r"(r2), "=r"(r3) : "r"(addr))
#define LDSM_T_X4(r0, r1, r2, r3, addr)                                      \
    asm volatile("ldmatrix.sync.aligned.m8n8.x4.trans.shared.b16 {%0,%1,%2,%3}, [%4];" \
        : "=r"(r0), "=r"(r1), "=r"(r2), "=r"(r3) : "r"(addr))
#define MMA16816(c, a, b)                                                    \
    asm volatile("mma.sync.aligned.m16n8k16.row.col.f32.bf16.bf16.f32 "      \
        "{%0,%1,%2,%3}, {%4,%5,%6,%7}, {%8,%9}, {%0,%1,%2,%3};"              \
        : "+f"((c)[0]), "+f"((c)[1]), "+f"((c)[2]), "+f"((c)[3])             \
        : "r"((a)[0]), "r"((a)[1]), "r"((a)[2]), "r"((a)[3]),                \
          "r"((b)[0]), "r"((b)[1]))
#define MMA16816F16(c, a, b)                                                 \
    asm volatile("mma.sync.aligned.m16n8k16.row.col.f32.f16.f16.f32 "        \
        "{%0,%1,%2,%3}, {%4,%5,%6,%7}, {%8,%9}, {%0,%1,%2,%3};"              \
        : "+f"((c)[0]), "+f"((c)[1]), "+f"((c)[2]), "+f"((c)[3])             \
        : "r"((a)[0]), "r"((a)[1]), "r"((a)[2]), "r"((a)[3]),                \
          "r"((b)[0]), "r"((b)[1]))

__device__ __forceinline__ uint32_t bf2x(float lo, float hi) {
    uint32_t r;
    asm("cvt.rn.bf16x2.f32 %0, %1, %2;" : "=r"(r) : "f"(hi), "f"(lo));
    return r;
}
__device__ __forceinline__ uint32_t h2x(float lo, float hi) {
    __half2 h = __floats2half2_rn(lo, hi);
    return *(uint32_t*)&h;
}

// ---------------------------------------------------------------------------
// 3x LayerNorm in one launch; q/k -> bf16 hi/lo, v -> fp16 single.
// ---------------------------------------------------------------------------
struct LnArgs {
    const float *x[3], *g[3], *b[3];
    __nv_bfloat16 *h[3], *l[3];
    int f16[3];
};
__global__ __launch_bounds__(256)
void ln3_split_kernel(LnArgs a)
{
    int which = blockIdx.y;
    int row = blockIdx.x;
    int tid = threadIdx.x;
    const float4* xr = reinterpret_cast<const float4*>(a.x[which] + (size_t)row * Dq);
    float4 v = xr[tid];
    float s  = v.x + v.y + v.z + v.w;
    float s2 = v.x*v.x + v.y*v.y + v.z*v.z + v.w*v.w;
    #pragma unroll
    for (int o = 16; o; o >>= 1) {
        s  += __shfl_xor_sync(0xffffffffu, s,  o);
        s2 += __shfl_xor_sync(0xffffffffu, s2, o);
    }
    __shared__ float ws[8], ws2[8], stats[2];
    int w = tid >> 5, lane = tid & 31;
    if (lane == 0) { ws[w] = s; ws2[w] = s2; }
    __syncthreads();
    if (tid == 0) {
        float ts = 0.f, ts2 = 0.f;
        #pragma unroll
        for (int i = 0; i < 8; i++) { ts += ws[i]; ts2 += ws2[i]; }
        float mu  = ts * (1.0f / Dq);
        float var = ts2 * (1.0f / Dq) - mu * mu;
        stats[0] = mu;
        stats[1] = rsqrtf(var + 1e-5f);
    }
    __syncthreads();
    float mu = stats[0], rstd = stats[1];
    float4 g4 = reinterpret_cast<const float4*>(a.g[which])[tid];
    float4 b4 = reinterpret_cast<const float4*>(a.b[which])[tid];
    float o4[4];
    o4[0] = (v.x - mu) * rstd * g4.x + b4.x;
    o4[1] = (v.y - mu) * rstd * g4.y + b4.y;
    o4[2] = (v.z - mu) * rstd * g4.z + b4.z;
    o4[3] = (v.w - mu) * rstd * g4.w + b4.w;
    if (a.f16[which]) {
        __half* dst = (__half*)a.h[which];
        uint32_t p0 = h2x(o4[0], o4[1]);
        uint32_t p1 = h2x(o4[2], o4[3]);
        *(uint2*)&dst[(size_t)row * Dq + tid*4] = make_uint2(p0, p1);
    } else {
        __nv_bfloat16 h4[4], l4[4];
        #pragma unroll
        for (int i = 0; i < 4; i++) {
            h4[i] = __float2bfloat16_rn(o4[i]);
            l4[i] = __float2bfloat16_rn(o4[i] - __bfloat162float(h4[i]));
        }
        *(ulonglong1*)&a.h[which][(size_t)row * Dq + tid*4] = *(ulonglong1*)h4;
        *(ulonglong1*)&a.l[which][(size_t)row * Dq + tid*4] = *(ulonglong1*)l4;
    }
}

// plain fp32 -> bf16 hi/lo split (rel_pos)
__global__ __launch_bounds__(256)
void fsplit_kernel(const float* __restrict__ x,
                   __nv_bfloat16* __restrict__ hi, __nv_bfloat16* __restrict__ lo)
{
    size_t i = ((size_t)blockIdx.x * 256 + threadIdx.x) * 4;
    float4 v = *(const float4*)&x[i];
    float o4[4] = {v.x, v.y, v.z, v.w};
    __nv_bfloat16 h4[4], l4[4];
    #pragma unroll
    for (int j = 0; j < 4; j++) {
        h4[j] = __float2bfloat16_rn(o4[j]);
        l4[j] = __float2bfloat16_rn(o4[j] - __bfloat162float(h4[j]));
    }
    *(ulonglong1*)&hi[i] = *(ulonglong1*)h4;
    *(ulonglong1*)&lo[i] = *(ulonglong1*)l4;
}

// 5 weights: W [K,N] -> WT [N,K]; wq/wk/wr bf16 hi/lo; wv/wo fp16 single
struct WSplitArgs {
    const float* W[5];
    __nv_bfloat16 *H[5], *L[5];
    float scale[5];
    int f16[5];
};
__global__ __launch_bounds__(256)
void wsplit5_kernel(WSplitArgs a)
{
    __shared__ float t[32][33];
    int z = blockIdx.z;
    const float* W = a.W[z];
    int tx = threadIdx.x & 31, ty = threadIdx.x >> 5;
    int nb = blockIdx.x * 32, kb = blockIdx.y * 32;
    #pragma unroll
    for (int i = 0; i < 32; i += 8)
        t[ty+i][tx] = W[(size_t)(kb + ty + i) * Dq + nb + tx];
    __syncthreads();
    float sc = a.scale[z];
    #pragma unroll
    for (int i = 0; i < 32; i += 8) {
        float v = t[tx][ty+i] * sc;
        size_t off = (size_t)(nb + ty + i) * Dq + kb + tx;
        if (a.f16[z]) {
            ((__half*)a.H[z])[off] = __float2half_rn(v);
        } else {
            __nv_bfloat16 h = __float2bfloat16_rn(v);
            a.H[z][off] = h;
            a.L[z][off] = __float2bfloat16_rn(v - __bfloat162float(h));
        }
    }
}

// ---------------------------------------------------------------------------
// Shared GEMM tile constants
// ---------------------------------------------------------------------------
#define GROW 72
#define GT   (128*GROW)
#define TILEB (GT*2)                  // 18432 B per tile
#define GSM_BYTES (8*TILEB)           // 3-term: 2 buf x 4 tiles
#define G16_BYTES (4*TILEB)           // fp16:   2 buf x 2 tiles

// ---------------------------------------------------------------------------
// Merged 3-term projection GEMM: q (16 chunks), kr=[lnk|rp]@[Wk;0.1Wr] (32).
// blockIdx.y: 0-31 -> q, 32-63 -> kr.
// ---------------------------------------------------------------------------
struct ProjArgs {
    const __nv_bfloat16 *Ah[2], *Al[2];
    const __nv_bfloat16 *A2h, *A2l;
    const __nv_bfloat16 *Bh[2], *Bl[2];
    const __nv_bfloat16 *B2h, *B2l;
    const float* bias[2];
    float alpha[2];
    __nv_bfloat16 *Ch[2], *Cl[2];
    int nch[2];
};

__global__ __launch_bounds__(512, 1)
void proj_gemm_kernel(ProjArgs a)
{
    extern __shared__ __nv_bfloat16 gsm[];
    const uint32_t sb = smem_u32(gsm);

    const int g  = blockIdx.y >> 5;
    const int bm = (blockIdx.y & 31) * 128, bn = blockIdx.x * 128;

    const int tid  = threadIdx.x;
    const int wid  = tid >> 5, lane = tid & 31;
    const int wm   = wid & 3,  wn   = wid >> 2;
    const int g_row = (lane & 7) + ((lane >> 3) & 1) * 8;
    const int g_col = ((lane >> 4) & 1) * 8;
    const int lrow0 = tid >> 3, lc16 = tid & 7;

    const __nv_bfloat16 *Ah1 = a.Ah[g], *Al1 = a.Al[g];
    const __nv_bfloat16 *Bh1 = a.Bh[g], *Bl1 = a.Bl[g];
    const int nchunks = a.nch[g];

    float acc[2][4][4];
    #pragma unroll
    for (int mt = 0; mt < 2; mt++)
        #pragma unroll
        for (int nf = 0; nf < 4; nf++)
            #pragma unroll
            for (int r = 0; r < 4; r++) acc[mt][nf][r] = 0.f;

    auto load_chunk = [&](int buf, int kc) {
        const __nv_bfloat16 *pAh, *pAl, *pBh, *pBl;
        int k0;
        if (kc < 16) { pAh = Ah1;  pAl = Al1;  pBh = Bh1;  pBl = Bl1;  k0 = kc * 64; }
        else         { pAh = a.A2h; pAl = a.A2l; pBh = a.B2h; pBl = a.B2l; k0 = (kc - 16) * 64; }
        uint32_t base = sb + buf * 4 * TILEB;
        #pragma unroll
        for (int i = 0; i < 2; i++) {
            int row = lrow0 + i * 64;
            uint32_t so = (uint32_t)((row * GROW + lc16 * 8) * 2);
            size_t ga = (size_t)(bm + row) * Dq + k0 + lc16 * 8;
            size_t gb = (size_t)(bn + row) * Dq + k0 + lc16 * 8;
            cpa16(base + 0*TILEB + so, pAh + ga);
            cpa16(base + 1*TILEB + so, pAl + ga);
            cpa16(base + 2*TILEB + so, pBh + gb);
            cpa16(base + 3*TILEB + so, pBl + gb);
        }
        CPA_COMMIT();
    };

    load_chunk(0, 0);

    for (int kc = 0; kc < nchunks; kc++) {
        CPA_WAIT(0);
        __syncthreads();
        if (kc + 1 < nchunks) load_chunk((kc + 1) & 1, kc + 1);

        uint32_t base = sb + (kc & 1) * 4 * TILEB;
        uint32_t uAh = base, uAl = base + TILEB;
        uint32_t uBh = base + 2*TILEB, uBl = base + 3*TILEB;

        #pragma unroll
        for (int ks = 0; ks < 4; ks++) {
            const int kcol = ks * 16 + g_col;
            uint32_t ah[2][4], al[2][4];
            #pragma unroll
            for (int mt = 0; mt < 2; mt++) {
                uint32_t off = ((wm*32 + mt*16 + g_row) * GROW + kcol) * 2;
                LDSM_X4(ah[mt][0], ah[mt][1], ah[mt][2], ah[mt][3], uAh + off);
                LDSM_X4(al[mt][0], al[mt][1], al[mt][2], al[mt][3], uAl + off);
            }
            uint32_t bh[4][2], bl[4][2];
            #pragma unroll
            for (int np = 0; np < 2; np++) {
                uint32_t off = ((wn*32 + np*16 + g_row) * GROW + kcol) * 2;
                uint32_t r0, r1, r2, r3;
                LDSM_X4(r0, r1, r2, r3, uBh + off);
                bh[2*np][0] = r0;   bh[2*np][1] = r2;
                bh[2*np+1][0] = r1; bh[2*np+1][1] = r3;
                LDSM_X4(r0, r1, r2, r3, uBl + off);
                bl[2*np][0] = r0;   bl[2*np][1] = r2;
                bl[2*np+1][0] = r1; bl[2*np+1][1] = r3;
            }
            #pragma unroll
            for (int mt = 0; mt < 2; mt++)
                #pragma unroll
                for (int nf = 0; nf < 4; nf++) {
                    MMA16816(acc[mt][nf], ah[mt], bh[nf]);
                    MMA16816(acc[mt][nf], ah[mt], bl[nf]);
                    MMA16816(acc[mt][nf], al[mt], bh[nf]);
                }
        }
    }

    const float alpha = a.alpha[g];
    const float* bias = a.bias[g];
    __nv_bfloat16 *Ch = a.Ch[g], *Cl = a.Cl[g];
    const int qrow = lane >> 2, qcol = (lane & 3) * 2;
    #pragma unroll
    for (int mt = 0; mt < 2; mt++) {
        int r0 = bm + wm*32 + mt*16 + qrow;
        #pragma unroll
        for (int nf = 0; nf < 4; nf++) {
            int col = bn + wn*32 + nf*8 + qcol;
            float2 vb = *(const float2*)&bias[col];
            float2 o0, o1;
            o0.x = alpha * (acc[mt][nf][0] + vb.x);
            o0.y = alpha * (acc[mt][nf][1] + vb.y);
            o1.x = alpha * (acc[mt][nf][2] + vb.x);
            o1.y = alpha * (acc[mt][nf][3] + vb.y);
            size_t off0 = (size_t)r0 * Dq + col;
            size_t off1 = (size_t)(r0 + 8) * Dq + col;
            float h0 = __bfloat162float(__float2bfloat16_rn(o0.x));
            float h1 = __bfloat162float(__float2bfloat16_rn(o0.y));
            float h2 = __bfloat162float(__float2bfloat16_rn(o1.x));
            float h3 = __bfloat162float(__float2bfloat16_rn(o1.y));
            *(uint32_t*)&Ch[off0] = bf2x(h0, h1);
            *(uint32_t*)&Cl[off0] = bf2x(o0.x - h0, o0.y - h1);
            *(uint32_t*)&Ch[off1] = bf2x(h2, h3);
            *(uint32_t*)&Cl[off1] = bf2x(o1.x - h2, o1.y - h3);
        }
    }
}

// ---------------------------------------------------------------------------
// fp16 single-term GEMM: C = A@B^T + bias. A:[M,K] half, B:[N,K] half.
// Output fp32 (Cf) or fp16 (Ch16).
// ---------------------------------------------------------------------------
__global__ __launch_bounds__(512, 1)
void gemm16_kernel(const __half* __restrict__ A, const __half* __restrict__ B,
                   const float* __restrict__ bias, float alpha,
                   float* __restrict__ Cf, __half* __restrict__ Ch16)
{
    extern __shared__ __nv_bfloat16 gsm[];
    const uint32_t sb = smem_u32(gsm);

    const int tid  = threadIdx.x;
    const int wid  = tid >> 5, lane = tid & 31;
    const int wm   = wid & 3,  wn   = wid >> 2;
    const int bm = blockIdx.y * 128, bn = blockIdx.x * 128;
    const int g_row = (lane & 7) + ((lane >> 3) & 1) * 8;
    const int g_col = ((lane >> 4) & 1) * 8;
    const int lrow0 = tid >> 3, lc16 = tid & 7;

    float acc[2][4][4];
    #pragma unroll
    for (int mt = 0; mt < 2; mt++)
        #pragma unroll
        for (int nf = 0; nf < 4; nf++)
            #pragma unroll
            for (int r = 0; r < 4; r++) acc[mt][nf][r] = 0.f;

    auto load_chunk = [&](int buf, int k0) {
        uint32_t base = sb + buf * 2 * TILEB;
        #pragma unroll
        for (int i = 0; i < 2; i++) {
            int row = lrow0 + i * 64;
            uint32_t so = (uint32_t)((row * GROW + lc16 * 8) * 2);
            cpa16(base + 0*TILEB + so, A + (size_t)(bm + row) * Dq + k0 + lc16 * 8);
            cpa16(base + 1*TILEB + so, B + (size_t)(bn + row) * Dq + k0 + lc16 * 8);
        }
        CPA_COMMIT();
    };

    load_chunk(0, 0);
    for (int kc = 0; kc < 16; kc++) {
        CPA_WAIT(0);
        __syncthreads();
        if (kc + 1 < 16) load_chunk((kc + 1) & 1, (kc + 1) * 64);

        uint32_t base = sb + (kc & 1) * 2 * TILEB;
        uint32_t uA = base, uB = base + TILEB;

        #pragma unroll
        for (int ks = 0; ks < 4; ks++) {
            const int kcol = ks * 16 + g_col;
            uint32_t av[2][4];
            #pragma unroll
            for (int mt = 0; mt < 2; mt++) {
                uint32_t off = ((wm*32 + mt*16 + g_row) * GROW + kcol) * 2;
                LDSM_X4(av[mt][0], av[mt][1], av[mt][2], av[mt][3], uA + off);
            }
            uint32_t bv[4][2];
            #pragma unroll
            for (int np = 0; np < 2; np++) {
                uint32_t off = ((wn*32 + np*16 + g_row) * GROW + kcol) * 2;
                uint32_t r0, r1, r2, r3;
                LDSM_X4(r0, r1, r2, r3, uB + off);
                bv[2*np][0] = r0;   bv[2*np][1] = r2;
                bv[2*np+1][0] = r1; bv[2*np+1][1] = r3;
            }
            #pragma unroll
            for (int mt = 0; mt < 2; mt++)
                #pragma unroll
                for (int nf = 0; nf < 4; nf++)
                    MMA16816F16(acc[mt][nf], av[mt], bv[nf]);
        }
    }

    const int qrow = lane >> 2, qcol = (lane & 3) * 2;
    #pragma unroll
    for (int mt = 0; mt < 2; mt++) {
        int r0 = bm + wm*32 + mt*16 + qrow;
        #pragma unroll
        for (int nf = 0; nf < 4; nf++) {
            int col = bn + wn*32 + nf*8 + qcol;
            float2 vb = *(const float2*)&bias[col];
            float2 o0, o1;
            o0.x = alpha * (acc[mt][nf][0] + vb.x);
            o0.y = alpha * (acc[mt][nf][1] + vb.y);
            o1.x = alpha * (acc[mt][nf][2] + vb.x);
            o1.y = alpha * (acc[mt][nf][3] + vb.y);
            size_t off0 = (size_t)r0 * Dq + col;
            size_t off1 = (size_t)(r0 + 8) * Dq + col;
            if (Cf) {
                *(float2*)&Cf[off0] = o0;
                *(float2*)&Cf[off1] = o1;
            } else {
                *(uint32_t*)&Ch16[off0] = h2x(o0.x, o0.y);
                *(uint32_t*)&Ch16[off1] = h2x(o1.x, o1.y);
            }
        }
    }
}

// ---------------------------------------------------------------------------
// Attention v7: single-pass flash, online max, fp16 PV, raw S to probs,
// final in-place exp(S-M)*iL pass; ctx written fp16.
// smem tiles: 0 qh, 1 ql, 2-3 k0(h,l), 4 v0(f16), 5-6 k1(h,l), 7 v1(f16)
// ---------------------------------------------------------------------------
#define ATS 72
#define ATILEB (128*ATS*2)
#define ATTN_SMEM (8*ATILEB + Tq*4)   // 151552

__device__ __forceinline__ void s_mma(uint32_t uqh, uint32_t uql,
        uint32_t ukh, uint32_t ukl, int wid, int g_row, int g_col,
        float acc[16][4])
{
    #pragma unroll
    for (int nf = 0; nf < 16; nf++) {
        acc[nf][0] = 0.f; acc[nf][1] = 0.f; acc[nf][2] = 0.f; acc[nf][3] = 0.f;
    }
    #pragma unroll
    for (int ks = 0; ks < 4; ks++) {
        uint32_t ah[4], al[4];
        uint32_t aoff = (uint32_t)(((wid*16 + g_row) * ATS + ks*16 + g_col) * 2);
        LDSM_X4(ah[0], ah[1], ah[2], ah[3], uqh + aoff);
        LDSM_X4(al[0], al[1], al[2], al[3], uql + aoff);
        #pragma unroll
        for (int np = 0; np < 8; np++) {
            uint32_t boff = (uint32_t)(((np*16 + g_row) * ATS + ks*16 + g_col) * 2);
            uint32_t r0, r1, r2, r3, s0, s1, s2, s3;
            LDSM_X4(r0, r1, r2, r3, ukh + boff);
            LDSM_X4(s0, s1, s2, s3, ukl + boff);
            uint32_t b0[2] = {r0, r2}, b1[2] = {r1, r3};
            uint32_t c0[2] = {s0, s2}, c1[2] = {s1, s3};
            MMA16816(acc[2*np],   ah, b0);
            MMA16816(acc[2*np],   al, b0);
            MMA16816(acc[2*np],   ah, c0);
            MMA16816(acc[2*np+1], ah, b1);
            MMA16816(acc[2*np+1], al, b1);
            MMA16816(acc[2*np+1], ah, c1);
        }
    }
}

__global__ __launch_bounds__(256, 1)
void attn7_kernel(const __nv_bfloat16* __restrict__ qh_g, const __nv_bfloat16* __restrict__ ql_g,
                  const __nv_bfloat16* __restrict__ kh_g, const __nv_bfloat16* __restrict__ kl_g,
                  const __half* __restrict__ v16_g,
                  const int* __restrict__ mask, float* __restrict__ probs,
                  __half* __restrict__ ctx16)
{
    extern __shared__ __nv_bfloat16 sm_[];
    const uint32_t sb = smem_u32(sm_);
    int* msk = (int*)(sm_ + 8*128*ATS);

    const int t0 = blockIdx.x * 128, h = blockIdx.y, b = blockIdx.z;
    const int tid = threadIdx.x, wid = tid >> 5, lane = tid & 31;
    const int qrow = lane >> 2, qc2 = (lane & 3) * 2;
    const int g_row = (lane & 7) + ((lane >> 3) & 1) * 8;
    const int g_col = ((lane >> 4) & 1) * 8;
    const int lrow0 = tid >> 3, lc16 = tid & 7;

    const size_t gq  = ((size_t)(b*Tq + t0)) * Dq + h*DHq;
    const size_t gkv = ((size_t)(b*Tq)) * Dq + h*DHq;

    auto load_pair = [&](int th, int tl, const __nv_bfloat16* gh,
                         const __nv_bfloat16* gl, size_t gbase) {
        #pragma unroll
        for (int i = 0; i < 4; i++) {
            int row = lrow0 + i*32;
            uint32_t so = (uint32_t)((row*ATS + lc16*8) * 2);
            size_t g = gbase + (size_t)row * Dq + lc16*8;
            cpa16(sb + th*ATILEB + so, gh + g);
            cpa16(sb + tl*ATILEB + so, gl + g);
        }
    };
    auto load_v = [&](int tv, size_t gbase) {
        #pragma unroll
        for (int i = 0; i < 4; i++) {
            int row = lrow0 + i*32;
            uint32_t so = (uint32_t)((row*ATS + lc16*8) * 2);
            size_t g = gbase + (size_t)row * Dq + lc16*8;
            cpa16(sb + tv*ATILEB + so, v16_g + g);
        }
    };

    load_pair(0, 1, qh_g, ql_g, gq);
    load_pair(2, 3, kh_g, kl_g, gkv);
    CPA_COMMIT();
    load_v(4, gkv);
    CPA_COMMIT();
    for (int s = tid; s < Tq; s += 256) msk[s] = mask[b*Tq + s];

    float m0 = -1e30f, m1 = -1e30f, l0 = 0.f, l1 = 0.f;
    float cacc[8][4];
    #pragma unroll
    for (int nf = 0; nf < 8; nf++) {
        cacc[nf][0] = 0.f; cacc[nf][1] = 0.f; cacc[nf][2] = 0.f; cacc[nf][3] = 0.f;
    }

    const size_t prow0 = ((size_t)((b*Hq + h)*Tq) + t0 + wid*16 + qrow) * Tq;
    const uint32_t uqh = sb, uql = sb + ATILEB;

    for (int st = 0; st < 8; st++) {
        const int kb_ = 2 + (st & 1) * 3;
        const int vb_ = 4 + (st & 1) * 3;

        CPA_WAIT(1);
        __syncthreads();

        if (st < 7) {
            const int nk = 2 + ((st+1) & 1) * 3;
            const int nv = 4 + ((st+1) & 1) * 3;
            load_pair(nk, nk+1, kh_g, kl_g, gkv + (size_t)((st+1)*128) * Dq);
            CPA_COMMIT();
            load_v(nv, gkv + (size_t)((st+1)*128) * Dq);
            CPA_COMMIT();
        }

        float acc[16][4];
        s_mma(uqh, uql, sb + kb_*ATILEB, sb + (kb_+1)*ATILEB, wid, g_row, g_col, acc);

        int s0 = st * 128;
        float cm0 = -1e30f, cm1 = -1e30f;
        #pragma unroll
        for (int nf = 0; nf < 16; nf++) {
            int col = s0 + nf*8 + qc2;
            int k0 = msk[col], k1 = msk[col + 1];
            acc[nf][0] = k0 ? acc[nf][0] : -1e9f;
            acc[nf][1] = k1 ? acc[nf][1] : -1e9f;
            acc[nf][2] = k0 ? acc[nf][2] : -1e9f;
            acc[nf][3] = k1 ? acc[nf][3] : -1e9f;
            *(float2*)&probs[prow0 + col]        = make_float2(acc[nf][0], acc[nf][1]);
            *(float2*)&probs[prow0 + 8*Tq + col] = make_float2(acc[nf][2], acc[nf][3]);
            cm0 = fmaxf(cm0, fmaxf(acc[nf][0], acc[nf][1]));
            cm1 = fmaxf(cm1, fmaxf(acc[nf][2], acc[nf][3]));
        }
        cm0 = fmaxf(cm0, __shfl_xor_sync(0xffffffffu, cm0, 1));
        cm0 = fmaxf(cm0, __shfl_xor_sync(0xffffffffu, cm0, 2));
        cm1 = fmaxf(cm1, __shfl_xor_sync(0xffffffffu, cm1, 1));
        cm1 = fmaxf(cm1, __shfl_xor_sync(0xffffffffu, cm1, 2));
        float nm0 = fmaxf(m0, cm0), nm1 = fmaxf(m1, cm1);
        float r0 = __expf(m0 - nm0), r1 = __expf(m1 - nm1);
        #pragma unroll
        for (int nf = 0; nf < 8; nf++) {
            cacc[nf][0] *= r0; cacc[nf][1] *= r0;
            cacc[nf][2] *= r1; cacc[nf][3] *= r1;
        }

        float sa0 = 0.f, sa1 = 0.f;
        uint32_t aP[8][4];
        #pragma unroll
        for (int j = 0; j < 8; j++) {
            float p[8];
            #pragma unroll
            for (int u = 0; u < 2; u++) {
                int nf = 2*j + u;
                float p0 = __expf(acc[nf][0] - nm0);
                float p1 = __expf(acc[nf][1] - nm0);
                float p2 = __expf(acc[nf][2] - nm1);
                float p3 = __expf(acc[nf][3] - nm1);
                sa0 += p0 + p1;  sa1 += p2 + p3;
                p[u*4+0] = p0; p[u*4+1] = p1; p[u*4+2] = p2; p[u*4+3] = p3;
            }
            aP[j][0] = h2x(p[0], p[1]);
            aP[j][1] = h2x(p[2], p[3]);
            aP[j][2] = h2x(p[4], p[5]);
            aP[j][3] = h2x(p[6], p[7]);
        }
        sa0 += __shfl_xor_sync(0xffffffffu, sa0, 1);
        sa0 += __shfl_xor_sync(0xffffffffu, sa0, 2);
        sa1 += __shfl_xor_sync(0xffffffffu, sa1, 1);
        sa1 += __shfl_xor_sync(0xffffffffu, sa1, 2);
        l0 = l0 * r0 + sa0;  m0 = nm0;
        l1 = l1 * r1 + sa1;  m1 = nm1;

        if (st < 7) { CPA_WAIT(2); } else { CPA_WAIT(0); }
        __syncthreads();

        uint32_t uv = sb + vb_*ATILEB;
        #pragma unroll
        for (int ks = 0; ks < 8; ks++) {
            uint32_t bv[8][2];
            #pragma unroll
            for (int npv = 0; npv < 4; npv++) {
                uint32_t off = (uint32_t)(((ks*16 + g_row) * ATS + npv*16 + g_col) * 2);
                uint32_t r0v, r1v, r2v, r3v;
                LDSM_T_X4(r0v, r1v, r2v, r3v, uv + off);
                bv[2*npv][0] = r0v;   bv[2*npv][1] = r1v;
                bv[2*npv+1][0] = r2v; bv[2*npv+1][1] = r3v;
            }
            #pragma unroll
            for (int nf = 0; nf < 8; nf++)
                MMA16816F16(cacc[nf], aP[ks], bv[nf]);
        }
    }

    const float iL0 = 1.0f / l0, iL1 = 1.0f / l1;

    for (int st = 0; st < 8; st++) {
        int s0 = st * 128;
        #pragma unroll
        for (int nf = 0; nf < 16; nf++) {
            int col = s0 + nf*8 + qc2;
            float2 v0 = *(float2*)&probs[prow0 + col];
            float2 v1 = *(float2*)&probs[prow0 + 8*Tq + col];
            v0.x = __expf(v0.x - m0) * iL0;
            v0.y = __expf(v0.y - m0) * iL0;
            v1.x = __expf(v1.x - m1) * iL1;
            v1.y = __expf(v1.y - m1) * iL1;
            *(float2*)&probs[prow0 + col]        = v0;
            *(float2*)&probs[prow0 + 8*Tq + col] = v1;
        }
    }

    // write ctx fp16 (feeds gemm16 out)
    {
        int r = t0 + wid*16 + qrow;
        size_t base0 = ((size_t)(b*Tq + r)) * Dq + h*DHq;
        size_t base1 = ((size_t)(b*Tq + r + 8)) * Dq + h*DHq;
        #pragma unroll
        for (int nf = 0; nf < 8; nf++) {
            int col = nf*8 + qc2;
            *(uint32_t*)&ctx16[base0 + col] = h2x(cacc[nf][0] * iL0, cacc[nf][1] * iL0);
            *(uint32_t*)&ctx16[base1 + col] = h2x(cacc[nf][2] * iL1, cacc[nf][3] * iL1);
        }
    }
}

// ---------------------------------------------------------------------------
extern "C" void kernel_launch(void* const* d_in, const int* in_sizes, int n_in,
                              void* d_out, int out_size)
{
    const float* query   = (const float*)d_in[0];
    const float* key     = (const float*)d_in[1];
    const float* value   = (const float*)d_in[2];
    const float* rel_pos = (const float*)d_in[3];
    const int*   kpm     = (const int*)  d_in[4];
    const float* qn_g = (const float*)d_in[5];
    const float* qn_b = (const float*)d_in[6];
    const float* kn_g = (const float*)d_in[7];
    const float* kn_b = (const float*)d_in[8];
    const float* vn_g = (const float*)d_in[9];
    const float* vn_b = (const float*)d_in[10];
    const float* Wq = (const float*)d_in[11];
    const float* bq = (const float*)d_in[12];
    const float* Wk = (const float*)d_in[13];
    const float* bk = (const float*)d_in[14];
    const float* Wv = (const float*)d_in[15];
    const float* bv = (const float*)d_in[16];
    const float* Wr = (const float*)d_in[17];
    const float* Wo = (const float*)d_in[18];
    const float* bo = (const float*)d_in[19];

    float* out   = (float*)d_out;
    float* probs = out + OUT_ELEMS;

    __nv_bfloat16 *lnq_h,*lnq_l,*lnk_h,*lnk_l,*rp_h,*rp_l;
    __nv_bfloat16 *qs_h,*qs_l,*kr_h,*kr_l;
    __half *lnv16, *v16, *ctx16, *wv16, *wo16;
    __nv_bfloat16 *wq_h,*wq_l,*wk_h,*wk_l,*wr_h,*wr_l;
    cudaGetSymbolAddress((void**)&lnq_h, g_lnq_h); cudaGetSymbolAddress((void**)&lnq_l, g_lnq_l);
    cudaGetSymbolAddress((void**)&lnk_h, g_lnk_h); cudaGetSymbolAddress((void**)&lnk_l, g_lnk_l);
    cudaGetSymbolAddress((void**)&lnv16, g_lnv16);
    cudaGetSymbolAddress((void**)&rp_h,  g_rp_h);  cudaGetSymbolAddress((void**)&rp_l,  g_rp_l);
    cudaGetSymbolAddress((void**)&qs_h,  g_qs_h);  cudaGetSymbolAddress((void**)&qs_l,  g_qs_l);
    cudaGetSymbolAddress((void**)&kr_h,  g_kr_h);  cudaGetSymbolAddress((void**)&kr_l,  g_kr_l);
    cudaGetSymbolAddress((void**)&v16,   g_v16);
    cudaGetSymbolAddress((void**)&ctx16, g_ctx16);
    cudaGetSymbolAddress((void**)&wq_h, g_wq_h);   cudaGetSymbolAddress((void**)&wq_l, g_wq_l);
    cudaGetSymbolAddress((void**)&wk_h, g_wk_h);   cudaGetSymbolAddress((void**)&wk_l, g_wk_l);
    cudaGetSymbolAddress((void**)&wv16, g_wv16);
    cudaGetSymbolAddress((void**)&wr_h, g_wr_h);   cudaGetSymbolAddress((void**)&wr_l, g_wr_l);
    cudaGetSymbolAddress((void**)&wo16, g_wo16);

    cudaFuncSetAttribute(proj_gemm_kernel, cudaFuncAttributeMaxDynamicSharedMemorySize, GSM_BYTES);
    cudaFuncSetAttribute(gemm16_kernel, cudaFuncAttributeMaxDynamicSharedMemorySize, G16_BYTES);
    cudaFuncSetAttribute(attn7_kernel, cudaFuncAttributeMaxDynamicSharedMemorySize, ATTN_SMEM);

    // 1) weight transpose + split
    WSplitArgs wa;
    wa.W[0]=Wq; wa.H[0]=wq_h; wa.L[0]=wq_l; wa.scale[0]=1.f;  wa.f16[0]=0;
    wa.W[1]=Wk; wa.H[1]=wk_h; wa.L[1]=wk_l; wa.scale[1]=1.f;  wa.f16[1]=0;
    wa.W[2]=Wv; wa.H[2]=(__nv_bfloat16*)wv16; wa.L[2]=nullptr; wa.scale[2]=1.f; wa.f16[2]=1;
    wa.W[3]=Wr; wa.H[3]=wr_h; wa.L[3]=wr_l; wa.scale[3]=0.1f; wa.f16[3]=0;
    wa.W[4]=Wo; wa.H[4]=(__nv_bfloat16*)wo16; wa.L[4]=nullptr; wa.scale[4]=1.f; wa.f16[4]=1;
    dim3 wgrid(Dq/32, Dq/32, 5);
    wsplit5_kernel<<<wgrid, 256>>>(wa);

    // 2) LayerNorms + rel_pos split
    LnArgs la;
    la.x[0]=query; la.g[0]=qn_g; la.b[0]=qn_b; la.h[0]=lnq_h; la.l[0]=lnq_l; la.f16[0]=0;
    la.x[1]=key;   la.g[1]=kn_g; la.b[1]=kn_b; la.h[1]=lnk_h; la.l[1]=lnk_l; la.f16[1]=0;
    la.x[2]=value; la.g[2]=vn_g; la.b[2]=vn_b; la.h[2]=(__nv_bfloat16*)lnv16; la.l[2]=nullptr; la.f16[2]=1;
    ln3_split_kernel<<<dim3(Mrows, 3), 256>>>(la);
    fsplit_kernel<<<(Mrows*Dq)/1024, 256>>>(rel_pos, rp_h, rp_l);

    // 3) 3-term projections (q, kr) + fp16 v projection
    ProjArgs pa;
    pa.Ah[0]=lnq_h; pa.Al[0]=lnq_l; pa.Bh[0]=wq_h; pa.Bl[0]=wq_l;
    pa.bias[0]=bq;  pa.alpha[0]=0.125f; pa.Ch[0]=qs_h; pa.Cl[0]=qs_l; pa.nch[0]=16;
    pa.Ah[1]=lnk_h; pa.Al[1]=lnk_l; pa.Bh[1]=wk_h; pa.Bl[1]=wk_l;
    pa.A2h=rp_h; pa.A2l=rp_l; pa.B2h=wr_h; pa.B2l=wr_l;
    pa.bias[1]=bk;  pa.alpha[1]=1.f;    pa.Ch[1]=kr_h; pa.Cl[1]=kr_l; pa.nch[1]=32;
    proj_gemm_kernel<<<dim3(Dq/128, 64), 512, GSM_BYTES>>>(pa);
    gemm16_kernel<<<dim3(Dq/128, Mrows/128), 512, G16_BYTES>>>(
        lnv16, wv16, bv, 1.0f, nullptr, v16);

    // 4) single-pass flash attention -> normalized probs + fp16 ctx
    dim3 agrid(Tq/128, Hq, Bq);
    attn7_kernel<<<agrid, 256, ATTN_SMEM>>>(qs_h, qs_l, kr_h, kr_l, v16,
                                            kpm, probs, ctx16);

    // 5) out = ctx@Wo + bo (fp16 single-term)
    gemm16_kernel<<<dim3(Dq/128, Mrows/128), 512, G16_BYTES>>>(
        ctx16, wo16, bo, 1.0f, out, nullptr);
}

// round 13
// speedup vs baseline: 1.8131x; 1.3870x over previous
#include <cuda_runtime.h>
#include <cuda_fp16.h>
#include <math.h>
#include <cstdint>

// Problem constants
#define Bq   4
#define Tq   1024
#define Dq   1024
#define Hq   16
#define DHq  64
#define Mrows (Bq*Tq)
#define OUT_ELEMS ((size_t)Mrows*Dq)

// ---------------- device scratch (no runtime allocation) -------------------
__device__ __half g_lnq16[Mrows*Dq], g_lnk16[Mrows*Dq], g_lnv16[Mrows*Dq];
__device__ __half g_rp16 [Mrows*Dq];
__device__ __half g_q16  [Mrows*Dq], g_kr16 [Mrows*Dq], g_v16 [Mrows*Dq];
__device__ __half g_ctx16[Mrows*Dq];
__device__ __half g_wq16[Dq*Dq], g_wk16[Dq*Dq], g_wv16[Dq*Dq];
__device__ __half g_wr16[Dq*Dq], g_wo16[Dq*Dq];

// ------------------------- asm helpers -------------------------------------
__device__ __forceinline__ uint32_t smem_u32(const void* p) {
    uint32_t a;
    asm("{ .reg .u64 t; cvta.to.shared.u64 t, %1; cvt.u32.u64 %0, t; }"
        : "=r"(a) : "l"(p));
    return a;
}
__device__ __forceinline__ void cpa16(uint32_t s, const void* g) {
    asm volatile("cp.async.cg.shared.global [%0], [%1], 16;" :: "r"(s), "l"(g));
}
#define CPA_COMMIT() asm volatile("cp.async.commit_group;" ::: "memory")
#define CPA_WAIT(n)  asm volatile("cp.async.wait_group %0;" :: "n"(n) : "memory")

#define LDSM_X4(r0, r1, r2, r3, addr)                                        \
    asm volatile("ldmatrix.sync.aligned.m8n8.x4.shared.b16 {%0,%1,%2,%3}, [%4];" \
        : "=r"(r0), "=r"(r1), "=r"(r2), "=r"(r3) : "r"(addr))
#define LDSM_T_X4(r0, r1, r2, r3, addr)                                      \
    asm volatile("ldmatrix.sync.aligned.m8n8.x4.trans.shared.b16 {%0,%1,%2,%3}, [%4];" \
        : "=r"(r0), "=r"(r1), "=r"(r2), "=r"(r3) : "r"(addr))
#define MMA16816F16(c, a, b)                                                 \
    asm volatile("mma.sync.aligned.m16n8k16.row.col.f32.f16.f16.f32 "        \
        "{%0,%1,%2,%3}, {%4,%5,%6,%7}, {%8,%9}, {%0,%1,%2,%3};"              \
        : "+f"((c)[0]), "+f"((c)[1]), "+f"((c)[2]), "+f"((c)[3])             \
        : "r"((a)[0]), "r"((a)[1]), "r"((a)[2]), "r"((a)[3]),                \
          "r"((b)[0]), "r"((b)[1]))

__device__ __forceinline__ uint32_t h2x(float lo, float hi) {
    __half2 h = __floats2half2_rn(lo, hi);
    return *(uint32_t*)&h;
}

// ---------------------------------------------------------------------------
// 3x LayerNorm in one launch; fp16 output.
// ---------------------------------------------------------------------------
struct LnArgs {
    const float *x[3], *g[3], *b[3];
    __half* o[3];
};
__global__ __launch_bounds__(256)
void ln3_kernel(LnArgs a)
{
    int which = blockIdx.y;
    int row = blockIdx.x;
    int tid = threadIdx.x;
    const float4* xr = reinterpret_cast<const float4*>(a.x[which] + (size_t)row * Dq);
    float4 v = xr[tid];
    float s  = v.x + v.y + v.z + v.w;
    float s2 = v.x*v.x + v.y*v.y + v.z*v.z + v.w*v.w;
    #pragma unroll
    for (int o = 16; o; o >>= 1) {
        s  += __shfl_xor_sync(0xffffffffu, s,  o);
        s2 += __shfl_xor_sync(0xffffffffu, s2, o);
    }
    __shared__ float ws[8], ws2[8], stats[2];
    int w = tid >> 5, lane = tid & 31;
    if (lane == 0) { ws[w] = s; ws2[w] = s2; }
    __syncthreads();
    if (tid == 0) {
        float ts = 0.f, ts2 = 0.f;
        #pragma unroll
        for (int i = 0; i < 8; i++) { ts += ws[i]; ts2 += ws2[i]; }
        float mu  = ts * (1.0f / Dq);
        float var = ts2 * (1.0f / Dq) - mu * mu;
        stats[0] = mu;
        stats[1] = rsqrtf(var + 1e-5f);
    }
    __syncthreads();
    float mu = stats[0], rstd = stats[1];
    float4 g4 = reinterpret_cast<const float4*>(a.g[which])[tid];
    float4 b4 = reinterpret_cast<const float4*>(a.b[which])[tid];
    float o0 = (v.x - mu) * rstd * g4.x + b4.x;
    float o1 = (v.y - mu) * rstd * g4.y + b4.y;
    float o2 = (v.z - mu) * rstd * g4.z + b4.z;
    float o3 = (v.w - mu) * rstd * g4.w + b4.w;
    *(uint2*)&a.o[which][(size_t)row * Dq + tid*4] =
        make_uint2(h2x(o0, o1), h2x(o2, o3));
}

// fp32 -> fp16 (rel_pos)
__global__ __launch_bounds__(256)
void f16cvt_kernel(const float* __restrict__ x, __half* __restrict__ o)
{
    size_t i = ((size_t)blockIdx.x * 256 + threadIdx.x) * 4;
    float4 v = *(const float4*)&x[i];
    *(uint2*)&o[i] = make_uint2(h2x(v.x, v.y), h2x(v.z, v.w));
}

// 5 weights: W [K,N] -> WT [N,K] fp16 (per-weight scale)
struct WSplitArgs {
    const float* W[5];
    __half* H[5];
    float scale[5];
};
__global__ __launch_bounds__(256)
void wsplit5_kernel(WSplitArgs a)
{
    __shared__ float t[32][33];
    int z = blockIdx.z;
    const float* W = a.W[z];
    int tx = threadIdx.x & 31, ty = threadIdx.x >> 5;
    int nb = blockIdx.x * 32, kb = blockIdx.y * 32;
    #pragma unroll
    for (int i = 0; i < 32; i += 8)
        t[ty+i][tx] = W[(size_t)(kb + ty + i) * Dq + nb + tx];
    __syncthreads();
    float sc = a.scale[z];
    #pragma unroll
    for (int i = 0; i < 32; i += 8) {
        size_t off = (size_t)(nb + ty + i) * Dq + kb + tx;
        a.H[z][off] = __float2half_rn(t[tx][ty+i] * sc);
    }
}

// ---------------------------------------------------------------------------
// Shared GEMM tile constants
// ---------------------------------------------------------------------------
#define GROW 72
#define GT   (128*GROW)
#define TILEB (GT*2)                  // 18432 B per tile
#define G16_BYTES (4*TILEB)           // 2 buf x 2 tiles

// ---------------------------------------------------------------------------
// Merged fp16 projection GEMM: q (16 chunks), v (16), kr=[lnk|rp]@[Wk;.1Wr](32)
// blockIdx.y: 0-31 -> q, 32-63 -> v, 64-95 -> kr. fp16 output.
// ---------------------------------------------------------------------------
struct Proj16Args {
    const __half *A[3], *B[3];
    const __half *A2, *B2;
    const float* bias[3];
    float alpha[3];
    __half* C[3];
    int nch[3];
};

__global__ __launch_bounds__(512, 1)
void proj16_kernel(Proj16Args a)
{
    extern __shared__ __half gsm[];
    const uint32_t sb = smem_u32(gsm);

    const int g  = blockIdx.y >> 5;
    const int bm = (blockIdx.y & 31) * 128, bn = blockIdx.x * 128;

    const int tid  = threadIdx.x;
    const int wid  = tid >> 5, lane = tid & 31;
    const int wm   = wid & 3,  wn   = wid >> 2;
    const int g_row = (lane & 7) + ((lane >> 3) & 1) * 8;
    const int g_col = ((lane >> 4) & 1) * 8;
    const int lrow0 = tid >> 3, lc16 = tid & 7;

    const __half *A1 = a.A[g], *B1 = a.B[g];
    const int nchunks = a.nch[g];

    float acc[2][4][4];
    #pragma unroll
    for (int mt = 0; mt < 2; mt++)
        #pragma unroll
        for (int nf = 0; nf < 4; nf++)
            #pragma unroll
            for (int r = 0; r < 4; r++) acc[mt][nf][r] = 0.f;

    auto load_chunk = [&](int buf, int kc) {
        const __half *pA, *pB;
        int k0;
        if (kc < 16) { pA = A1;   pB = B1;   k0 = kc * 64; }
        else         { pA = a.A2; pB = a.B2; k0 = (kc - 16) * 64; }
        uint32_t base = sb + buf * 2 * TILEB;
        #pragma unroll
        for (int i = 0; i < 2; i++) {
            int row = lrow0 + i * 64;
            uint32_t so = (uint32_t)((row * GROW + lc16 * 8) * 2);
            cpa16(base + 0*TILEB + so, pA + (size_t)(bm + row) * Dq + k0 + lc16 * 8);
            cpa16(base + 1*TILEB + so, pB + (size_t)(bn + row) * Dq + k0 + lc16 * 8);
        }
        CPA_COMMIT();
    };

    load_chunk(0, 0);

    for (int kc = 0; kc < nchunks; kc++) {
        CPA_WAIT(0);
        __syncthreads();
        if (kc + 1 < nchunks) load_chunk((kc + 1) & 1, kc + 1);

        uint32_t base = sb + (kc & 1) * 2 * TILEB;
        uint32_t uA = base, uB = base + TILEB;

        #pragma unroll
        for (int ks = 0; ks < 4; ks++) {
            const int kcol = ks * 16 + g_col;
            uint32_t av[2][4];
            #pragma unroll
            for (int mt = 0; mt < 2; mt++) {
                uint32_t off = ((wm*32 + mt*16 + g_row) * GROW + kcol) * 2;
                LDSM_X4(av[mt][0], av[mt][1], av[mt][2], av[mt][3], uA + off);
            }
            uint32_t bv[4][2];
            #pragma unroll
            for (int np = 0; np < 2; np++) {
                uint32_t off = ((wn*32 + np*16 + g_row) * GROW + kcol) * 2;
                uint32_t r0, r1, r2, r3;
                LDSM_X4(r0, r1, r2, r3, uB + off);
                bv[2*np][0] = r0;   bv[2*np][1] = r2;
                bv[2*np+1][0] = r1; bv[2*np+1][1] = r3;
            }
            #pragma unroll
            for (int mt = 0; mt < 2; mt++)
                #pragma unroll
                for (int nf = 0; nf < 4; nf++)
                    MMA16816F16(acc[mt][nf], av[mt], bv[nf]);
        }
    }

    const float alpha = a.alpha[g];
    const float* bias = a.bias[g];
    __half* C = a.C[g];
    const int qrow = lane >> 2, qcol = (lane & 3) * 2;
    #pragma unroll
    for (int mt = 0; mt < 2; mt++) {
        int r0 = bm + wm*32 + mt*16 + qrow;
        #pragma unroll
        for (int nf = 0; nf < 4; nf++) {
            int col = bn + wn*32 + nf*8 + qcol;
            float2 vb = *(const float2*)&bias[col];
            size_t off0 = (size_t)r0 * Dq + col;
            size_t off1 = (size_t)(r0 + 8) * Dq + col;
            *(uint32_t*)&C[off0] = h2x(alpha * (acc[mt][nf][0] + vb.x),
                                       alpha * (acc[mt][nf][1] + vb.y));
            *(uint32_t*)&C[off1] = h2x(alpha * (acc[mt][nf][2] + vb.x),
                                       alpha * (acc[mt][nf][3] + vb.y));
        }
    }
}

// ---------------------------------------------------------------------------
// fp16 GEMM, fp32 output: out = ctx@Wo^T + bias.
// ---------------------------------------------------------------------------
__global__ __launch_bounds__(512, 1)
void gemm16_out_kernel(const __half* __restrict__ A, const __half* __restrict__ B,
                       const float* __restrict__ bias, float* __restrict__ C)
{
    extern __shared__ __half gsm[];
    const uint32_t sb = smem_u32(gsm);

    const int tid  = threadIdx.x;
    const int wid  = tid >> 5, lane = tid & 31;
    const int wm   = wid & 3,  wn   = wid >> 2;
    const int bm = blockIdx.y * 128, bn = blockIdx.x * 128;
    const int g_row = (lane & 7) + ((lane >> 3) & 1) * 8;
    const int g_col = ((lane >> 4) & 1) * 8;
    const int lrow0 = tid >> 3, lc16 = tid & 7;

    float acc[2][4][4];
    #pragma unroll
    for (int mt = 0; mt < 2; mt++)
        #pragma unroll
        for (int nf = 0; nf < 4; nf++)
            #pragma unroll
            for (int r = 0; r < 4; r++) acc[mt][nf][r] = 0.f;

    auto load_chunk = [&](int buf, int k0) {
        uint32_t base = sb + buf * 2 * TILEB;
        #pragma unroll
        for (int i = 0; i < 2; i++) {
            int row = lrow0 + i * 64;
            uint32_t so = (uint32_t)((row * GROW + lc16 * 8) * 2);
            cpa16(base + 0*TILEB + so, A + (size_t)(bm + row) * Dq + k0 + lc16 * 8);
            cpa16(base + 1*TILEB + so, B + (size_t)(bn + row) * Dq + k0 + lc16 * 8);
        }
        CPA_COMMIT();
    };

    load_chunk(0, 0);
    for (int kc = 0; kc < 16; kc++) {
        CPA_WAIT(0);
        __syncthreads();
        if (kc + 1 < 16) load_chunk((kc + 1) & 1, (kc + 1) * 64);

        uint32_t base = sb + (kc & 1) * 2 * TILEB;
        uint32_t uA = base, uB = base + TILEB;

        #pragma unroll
        for (int ks = 0; ks < 4; ks++) {
            const int kcol = ks * 16 + g_col;
            uint32_t av[2][4];
            #pragma unroll
            for (int mt = 0; mt < 2; mt++) {
                uint32_t off = ((wm*32 + mt*16 + g_row) * GROW + kcol) * 2;
                LDSM_X4(av[mt][0], av[mt][1], av[mt][2], av[mt][3], uA + off);
            }
            uint32_t bv[4][2];
            #pragma unroll
            for (int np = 0; np < 2; np++) {
                uint32_t off = ((wn*32 + np*16 + g_row) * GROW + kcol) * 2;
                uint32_t r0, r1, r2, r3;
                LDSM_X4(r0, r1, r2, r3, uB + off);
                bv[2*np][0] = r0;   bv[2*np][1] = r2;
                bv[2*np+1][0] = r1; bv[2*np+1][1] = r3;
            }
            #pragma unroll
            for (int mt = 0; mt < 2; mt++)
                #pragma unroll
                for (int nf = 0; nf < 4; nf++)
                    MMA16816F16(acc[mt][nf], av[mt], bv[nf]);
        }
    }

    const int qrow = lane >> 2, qcol = (lane & 3) * 2;
    #pragma unroll
    for (int mt = 0; mt < 2; mt++) {
        int r0 = bm + wm*32 + mt*16 + qrow;
        #pragma unroll
        for (int nf = 0; nf < 4; nf++) {
            int col = bn + wn*32 + nf*8 + qcol;
            float2 vb = *(const float2*)&bias[col];
            size_t off0 = (size_t)r0 * Dq + col;
            size_t off1 = (size_t)(r0 + 8) * Dq + col;
            *(float2*)&C[off0] = make_float2(acc[mt][nf][0] + vb.x, acc[mt][nf][1] + vb.y);
            *(float2*)&C[off1] = make_float2(acc[mt][nf][2] + vb.x, acc[mt][nf][3] + vb.y);
        }
    }
}

// ---------------------------------------------------------------------------
// Attention v8: single-pass flash, all-fp16 operands (q, kr, v), fp32 accum.
// Raw S to probs during loop; final in-place exp(S-M)*iL; ctx fp16.
// smem tiles: 0 q, 1 k0, 2 v0, 3 k1, 4 v1 (+ mask)
// ---------------------------------------------------------------------------
#define ATS 72
#define ATILEB (128*ATS*2)
#define ATTN_SMEM (5*ATILEB + Tq*4)   // 96256

__global__ __launch_bounds__(256, 1)
void attn8_kernel(const __half* __restrict__ q_g, const __half* __restrict__ k_g,
                  const __half* __restrict__ v_g,
                  const int* __restrict__ mask, float* __restrict__ probs,
                  __half* __restrict__ ctx16)
{
    extern __shared__ __half sm_[];
    const uint32_t sb = smem_u32(sm_);
    int* msk = (int*)(sm_ + 5*128*ATS);

    const int t0 = blockIdx.x * 128, h = blockIdx.y, b = blockIdx.z;
    const int tid = threadIdx.x, wid = tid >> 5, lane = tid & 31;
    const int qrow = lane >> 2, qc2 = (lane & 3) * 2;
    const int g_row = (lane & 7) + ((lane >> 3) & 1) * 8;
    const int g_col = ((lane >> 4) & 1) * 8;
    const int lrow0 = tid >> 3, lc16 = tid & 7;

    const size_t gq  = ((size_t)(b*Tq + t0)) * Dq + h*DHq;
    const size_t gkv = ((size_t)(b*Tq)) * Dq + h*DHq;

    auto load_t = [&](int tile, const __half* src, size_t gbase) {
        #pragma unroll
        for (int i = 0; i < 4; i++) {
            int row = lrow0 + i*32;
            uint32_t so = (uint32_t)((row*ATS + lc16*8) * 2);
            cpa16(sb + tile*ATILEB + so, src + gbase + (size_t)row * Dq + lc16*8);
        }
    };

    // prologue: group1 = q + k0, group2 = v0
    load_t(0, q_g, gq);
    load_t(1, k_g, gkv);
    CPA_COMMIT();
    load_t(2, v_g, gkv);
    CPA_COMMIT();
    for (int s = tid; s < Tq; s += 256) msk[s] = mask[b*Tq + s];

    float m0 = -1e30f, m1 = -1e30f, l0 = 0.f, l1 = 0.f;
    float cacc[8][4];
    #pragma unroll
    for (int nf = 0; nf < 8; nf++) {
        cacc[nf][0] = 0.f; cacc[nf][1] = 0.f; cacc[nf][2] = 0.f; cacc[nf][3] = 0.f;
    }

    const size_t prow0 = ((size_t)((b*Hq + h)*Tq) + t0 + wid*16 + qrow) * Tq;
    const uint32_t uq = sb;

    for (int st = 0; st < 8; st++) {
        const int kb_ = 1 + (st & 1) * 2;   // 1 or 3
        const int vb_ = 2 + (st & 1) * 2;   // 2 or 4

        CPA_WAIT(1);
        __syncthreads();

        if (st < 7) {
            const int nk = 1 + ((st+1) & 1) * 2;
            const int nv = 2 + ((st+1) & 1) * 2;
            load_t(nk, k_g, gkv + (size_t)((st+1)*128) * Dq);
            CPA_COMMIT();
            load_t(nv, v_g, gkv + (size_t)((st+1)*128) * Dq);
            CPA_COMMIT();
        }

        // ---- S = q @ k^T : single-term fp16 ----
        float acc[16][4];
        #pragma unroll
        for (int nf = 0; nf < 16; nf++) {
            acc[nf][0] = 0.f; acc[nf][1] = 0.f; acc[nf][2] = 0.f; acc[nf][3] = 0.f;
        }
        {
            uint32_t uk = sb + kb_*ATILEB;
            #pragma unroll
            for (int ks = 0; ks < 4; ks++) {
                uint32_t aq[4];
                uint32_t aoff = (uint32_t)(((wid*16 + g_row) * ATS + ks*16 + g_col) * 2);
                LDSM_X4(aq[0], aq[1], aq[2], aq[3], uq + aoff);
                #pragma unroll
                for (int np = 0; np < 8; np++) {
                    uint32_t boff = (uint32_t)(((np*16 + g_row) * ATS + ks*16 + g_col) * 2);
                    uint32_t r0, r1, r2, r3;
                    LDSM_X4(r0, r1, r2, r3, uk + boff);
                    uint32_t b0[2] = {r0, r2}, b1[2] = {r1, r3};
                    MMA16816F16(acc[2*np],   aq, b0);
                    MMA16816F16(acc[2*np+1], aq, b1);
                }
            }
        }

        // ---- mask + raw-S store + online max + fp16 P fragments ----
        int s0 = st * 128;
        float cm0 = -1e30f, cm1 = -1e30f;
        #pragma unroll
        for (int nf = 0; nf < 16; nf++) {
            int col = s0 + nf*8 + qc2;
            int k0 = msk[col], k1 = msk[col + 1];
            acc[nf][0] = k0 ? acc[nf][0] : -1e9f;
            acc[nf][1] = k1 ? acc[nf][1] : -1e9f;
            acc[nf][2] = k0 ? acc[nf][2] : -1e9f;
            acc[nf][3] = k1 ? acc[nf][3] : -1e9f;
            *(float2*)&probs[prow0 + col]        = make_float2(acc[nf][0], acc[nf][1]);
            *(float2*)&probs[prow0 + 8*Tq + col] = make_float2(acc[nf][2], acc[nf][3]);
            cm0 = fmaxf(cm0, fmaxf(acc[nf][0], acc[nf][1]));
            cm1 = fmaxf(cm1, fmaxf(acc[nf][2], acc[nf][3]));
        }
        cm0 = fmaxf(cm0, __shfl_xor_sync(0xffffffffu, cm0, 1));
        cm0 = fmaxf(cm0, __shfl_xor_sync(0xffffffffu, cm0, 2));
        cm1 = fmaxf(cm1, __shfl_xor_sync(0xffffffffu, cm1, 1));
        cm1 = fmaxf(cm1, __shfl_xor_sync(0xffffffffu, cm1, 2));
        float nm0 = fmaxf(m0, cm0), nm1 = fmaxf(m1, cm1);
        float r0 = __expf(m0 - nm0), r1 = __expf(m1 - nm1);
        #pragma unroll
        for (int nf = 0; nf < 8; nf++) {
            cacc[nf][0] *= r0; cacc[nf][1] *= r0;
            cacc[nf][2] *= r1; cacc[nf][3] *= r1;
        }

        float sa0 = 0.f, sa1 = 0.f;
        uint32_t aP[8][4];
        #pragma unroll
        for (int j = 0; j < 8; j++) {
            float p[8];
            #pragma unroll
            for (int u = 0; u < 2; u++) {
                int nf = 2*j + u;
                float p0 = __expf(acc[nf][0] - nm0);
                float p1 = __expf(acc[nf][1] - nm0);
                float p2 = __expf(acc[nf][2] - nm1);
                float p3 = __expf(acc[nf][3] - nm1);
                sa0 += p0 + p1;  sa1 += p2 + p3;
                p[u*4+0] = p0; p[u*4+1] = p1; p[u*4+2] = p2; p[u*4+3] = p3;
            }
            aP[j][0] = h2x(p[0], p[1]);
            aP[j][1] = h2x(p[2], p[3]);
            aP[j][2] = h2x(p[4], p[5]);
            aP[j][3] = h2x(p[6], p[7]);
        }
        sa0 += __shfl_xor_sync(0xffffffffu, sa0, 1);
        sa0 += __shfl_xor_sync(0xffffffffu, sa0, 2);
        sa1 += __shfl_xor_sync(0xffffffffu, sa1, 1);
        sa1 += __shfl_xor_sync(0xffffffffu, sa1, 2);
        l0 = l0 * r0 + sa0;  m0 = nm0;
        l1 = l1 * r1 + sa1;  m1 = nm1;

        if (st < 7) { CPA_WAIT(2); } else { CPA_WAIT(0); }
        __syncthreads();

        // ---- ctx += P @ V (fp16) ----
        uint32_t uv = sb + vb_*ATILEB;
        #pragma unroll
        for (int ks = 0; ks < 8; ks++) {
            uint32_t bv[8][2];
            #pragma unroll
            for (int npv = 0; npv < 4; npv++) {
                uint32_t off = (uint32_t)(((ks*16 + g_row) * ATS + npv*16 + g_col) * 2);
                uint32_t r0v, r1v, r2v, r3v;
                LDSM_T_X4(r0v, r1v, r2v, r3v, uv + off);
                bv[2*npv][0] = r0v;   bv[2*npv][1] = r1v;
                bv[2*npv+1][0] = r2v; bv[2*npv+1][1] = r3v;
            }
            #pragma unroll
            for (int nf = 0; nf < 8; nf++)
                MMA16816F16(cacc[nf], aP[ks], bv[nf]);
        }
    }

    const float iL0 = 1.0f / l0, iL1 = 1.0f / l1;

    // in-place probs: p = exp(S - M) * iL
    for (int st = 0; st < 8; st++) {
        int s0 = st * 128;
        #pragma unroll
        for (int nf = 0; nf < 16; nf++) {
            int col = s0 + nf*8 + qc2;
            float2 v0 = *(float2*)&probs[prow0 + col];
            float2 v1 = *(float2*)&probs[prow0 + 8*Tq + col];
            v0.x = __expf(v0.x - m0) * iL0;
            v0.y = __expf(v0.y - m0) * iL0;
            v1.x = __expf(v1.x - m1) * iL1;
            v1.y = __expf(v1.y - m1) * iL1;
            *(float2*)&probs[prow0 + col]        = v0;
            *(float2*)&probs[prow0 + 8*Tq + col] = v1;
        }
    }

    // write ctx fp16
    {
        int r = t0 + wid*16 + qrow;
        size_t base0 = ((size_t)(b*Tq + r)) * Dq + h*DHq;
        size_t base1 = ((size_t)(b*Tq + r + 8)) * Dq + h*DHq;
        #pragma unroll
        for (int nf = 0; nf < 8; nf++) {
            int col = nf*8 + qc2;
            *(uint32_t*)&ctx16[base0 + col] = h2x(cacc[nf][0] * iL0, cacc[nf][1] * iL0);
            *(uint32_t*)&ctx16[base1 + col] = h2x(cacc[nf][2] * iL1, cacc[nf][3] * iL1);
        }
    }
}

// ---------------------------------------------------------------------------
extern "C" void kernel_launch(void* const* d_in, const int* in_sizes, int n_in,
                              void* d_out, int out_size)
{
    const float* query   = (const float*)d_in[0];
    const float* key     = (const float*)d_in[1];
    const float* value   = (const float*)d_in[2];
    const float* rel_pos = (const float*)d_in[3];
    const int*   kpm     = (const int*)  d_in[4];
    const float* qn_g = (const float*)d_in[5];
    const float* qn_b = (const float*)d_in[6];
    const float* kn_g = (const float*)d_in[7];
    const float* kn_b = (const float*)d_in[8];
    const float* vn_g = (const float*)d_in[9];
    const float* vn_b = (const float*)d_in[10];
    const float* Wq = (const float*)d_in[11];
    const float* bq = (const float*)d_in[12];
    const float* Wk = (const float*)d_in[13];
    const float* bk = (const float*)d_in[14];
    const float* Wv = (const float*)d_in[15];
    const float* bv = (const float*)d_in[16];
    const float* Wr = (const float*)d_in[17];
    const float* Wo = (const float*)d_in[18];
    const float* bo = (const float*)d_in[19];

    float* out   = (float*)d_out;
    float* probs = out + OUT_ELEMS;

    __half *lnq16,*lnk16,*lnv16,*rp16,*q16,*kr16,*v16,*ctx16;
    __half *wq16,*wk16,*wv16,*wr16,*wo16;
    cudaGetSymbolAddress((void**)&lnq16, g_lnq16);
    cudaGetSymbolAddress((void**)&lnk16, g_lnk16);
    cudaGetSymbolAddress((void**)&lnv16, g_lnv16);
    cudaGetSymbolAddress((void**)&rp16,  g_rp16);
    cudaGetSymbolAddress((void**)&q16,   g_q16);
    cudaGetSymbolAddress((void**)&kr16,  g_kr16);
    cudaGetSymbolAddress((void**)&v16,   g_v16);
    cudaGetSymbolAddress((void**)&ctx16, g_ctx16);
    cudaGetSymbolAddress((void**)&wq16, g_wq16);
    cudaGetSymbolAddress((void**)&wk16, g_wk16);
    cudaGetSymbolAddress((void**)&wv16, g_wv16);
    cudaGetSymbolAddress((void**)&wr16, g_wr16);
    cudaGetSymbolAddress((void**)&wo16, g_wo16);

    cudaFuncSetAttribute(proj16_kernel, cudaFuncAttributeMaxDynamicSharedMemorySize, G16_BYTES);
    cudaFuncSetAttribute(gemm16_out_kernel, cudaFuncAttributeMaxDynamicSharedMemorySize, G16_BYTES);
    cudaFuncSetAttribute(attn8_kernel, cudaFuncAttributeMaxDynamicSharedMemorySize, ATTN_SMEM);

    // 1) weight transpose -> fp16 (0.1 folded into Wr)
    WSplitArgs wa;
    wa.W[0]=Wq; wa.H[0]=wq16; wa.scale[0]=1.f;
    wa.W[1]=Wk; wa.H[1]=wk16; wa.scale[1]=1.f;
    wa.W[2]=Wv; wa.H[2]=wv16; wa.scale[2]=1.f;
    wa.W[3]=Wr; wa.H[3]=wr16; wa.scale[3]=0.1f;
    wa.W[4]=Wo; wa.H[4]=wo16; wa.scale[4]=1.f;
    dim3 wgrid(Dq/32, Dq/32, 5);
    wsplit5_kernel<<<wgrid, 256>>>(wa);

    // 2) LayerNorms -> fp16, rel_pos -> fp16
    LnArgs la;
    la.x[0]=query; la.g[0]=qn_g; la.b[0]=qn_b; la.o[0]=lnq16;
    la.x[1]=key;   la.g[1]=kn_g; la.b[1]=kn_b; la.o[1]=lnk16;
    la.x[2]=value; la.g[2]=vn_g; la.b[2]=vn_b; la.o[2]=lnv16;
    ln3_kernel<<<dim3(Mrows, 3), 256>>>(la);
    f16cvt_kernel<<<(Mrows*Dq)/1024, 256>>>(rel_pos, rp16);

    // 3) merged fp16 projections: q, v, kr=[lnk|rp]@[Wk;0.1Wr]
    Proj16Args pa;
    pa.A[0]=lnq16; pa.B[0]=wq16; pa.bias[0]=bq; pa.alpha[0]=0.125f;
    pa.C[0]=q16;  pa.nch[0]=16;
    pa.A[1]=lnv16; pa.B[1]=wv16; pa.bias[1]=bv; pa.alpha[1]=1.f;
    pa.C[1]=v16;  pa.nch[1]=16;
    pa.A[2]=lnk16; pa.B[2]=wk16; pa.bias[2]=bk; pa.alpha[2]=1.f;
    pa.A2=rp16; pa.B2=wr16;
    pa.C[2]=kr16; pa.nch[2]=32;
    proj16_kernel<<<dim3(Dq/128, 96), 512, G16_BYTES>>>(pa);

    // 4) single-pass flash attention (all fp16) -> normalized probs + fp16 ctx
    dim3 agrid(Tq/128, Hq, Bq);
    attn8_kernel<<<agrid, 256, ATTN_SMEM>>>(q16, kr16, v16, kpm, probs, ctx16);

    // 5) out = ctx@Wo + bo
    gemm16_out_kernel<<<dim3(Dq/128, Mrows/128), 512, G16_BYTES>>>(
        ctx16, wo16, bo, out);
}